// round 2
// baseline (speedup 1.0000x reference)
#include <cuda_runtime.h>
#include <math.h>

#define N_NODES 20000
#define T_STEPS 8
#define E_EDGES 320000
#define ETOT    (E_EDGES + N_NODES)
#define NFEAT   512
#define HC      512        // H * C
#define H_HEADS 4
#define C_CH    128
#define SLOPEV  0.2f

// ---------------- scratch (device globals; allocation-free) ----------------
__device__ float g_h[(size_t)N_NODES * HC];              // 41 MB
__device__ float g_asrc[N_NODES * H_HEADS];
__device__ float g_adst[N_NODES * H_HEADS];
__device__ int   g_deg[N_NODES];
__device__ int   g_rowptr[N_NODES + 1];
__device__ int   g_fill[N_NODES];
__device__ int   g_col[ETOT];
__device__ float g_z[(size_t)N_NODES * C_CH];
// LP stored in FLAT [T, N, C] layout (matches reference's raw reshape)
__device__ float g_LP[(size_t)T_STEPS * N_NODES * C_CH]; // 82 MB

__device__ __forceinline__ float leaky(float x) { return x >= 0.f ? x : SLOPEV * x; }

// ---------------- 1) SGEMM: g_h = A[20000,512] @ B[512,512] ----------------
// classic 128x128 tile, BK=8, 256 threads, 8x8 per thread
__global__ __launch_bounds__(256) void sgemm512(const float* __restrict__ A,
                                                const float* __restrict__ B) {
    const int M = N_NODES, K = 512, Nn = 512;
    __shared__ float As[8][128];
    __shared__ float Bs[8][128];

    int tid = threadIdx.x;
    int tx = tid & 15;          // 0..15
    int ty = tid >> 4;          // 0..15
    int bm = blockIdx.y;
    int bn = blockIdx.x;        // 0..3

    int row0 = bm * 128 + ty * 8;
    int col0 = bn * 128 + tx * 8;

    // A-tile load mapping: 128 rows x 8 k, one float4 per thread
    int arow  = tid >> 1;            // 0..127
    int acol4 = (tid & 1) * 4;       // 0 or 4
    int gArow = bm * 128 + arow;
    bool aValid = gArow < M;
    const float* Aptr = A + (size_t)gArow * K + acol4;

    // B-tile load mapping: 8 rows x 128 cols, one float4 per thread
    int brow = tid >> 5;             // 0..7
    int bcol = (tid & 31) * 4;       // 0..124
    const float* Bptr = B + (size_t)brow * Nn + bn * 128 + bcol;

    float acc[8][8];
#pragma unroll
    for (int i = 0; i < 8; i++)
#pragma unroll
        for (int j = 0; j < 8; j++) acc[i][j] = 0.f;

    for (int k0 = 0; k0 < K; k0 += 8) {
        float4 av = aValid ? *(const float4*)(Aptr + k0) : make_float4(0.f, 0.f, 0.f, 0.f);
        float4 bv = *(const float4*)(Bptr + (size_t)k0 * Nn);
        __syncthreads();
        As[acol4 + 0][arow] = av.x;
        As[acol4 + 1][arow] = av.y;
        As[acol4 + 2][arow] = av.z;
        As[acol4 + 3][arow] = av.w;
        *(float4*)&Bs[brow][bcol] = bv;
        __syncthreads();
#pragma unroll
        for (int kk = 0; kk < 8; kk++) {
            float ar[8], br[8];
#pragma unroll
            for (int i = 0; i < 8; i++) ar[i] = As[kk][ty * 8 + i];
#pragma unroll
            for (int i = 0; i < 8; i++) br[i] = Bs[kk][tx * 8 + i];
#pragma unroll
            for (int i = 0; i < 8; i++)
#pragma unroll
                for (int j = 0; j < 8; j++) acc[i][j] = fmaf(ar[i], br[j], acc[i][j]);
        }
    }

#pragma unroll
    for (int i = 0; i < 8; i++) {
        int r = row0 + i;
        if (r < M) {
            float4* o = (float4*)(g_h + (size_t)r * 512 + col0);
            o[0] = make_float4(acc[i][0], acc[i][1], acc[i][2], acc[i][3]);
            o[1] = make_float4(acc[i][4], acc[i][5], acc[i][6], acc[i][7]);
        }
    }
}

// ---------------- 2) attention coefficients ----------------
// grid = N blocks, 128 threads (4 warps = 4 heads)
__global__ __launch_bounds__(128) void att_kernel(const float* __restrict__ att_src,
                                                  const float* __restrict__ att_dst) {
    int n = blockIdx.x;
    int warp = threadIdx.x >> 5;
    int lane = threadIdx.x & 31;
    const float4 v  = ((const float4*)(g_h + (size_t)n * HC + warp * C_CH))[lane];
    const float4 as = ((const float4*)(att_src + warp * C_CH))[lane];
    const float4 ad = ((const float4*)(att_dst + warp * C_CH))[lane];
    float s = v.x * as.x + v.y * as.y + v.z * as.z + v.w * as.w;
    float d = v.x * ad.x + v.y * ad.y + v.z * ad.z + v.w * ad.w;
#pragma unroll
    for (int o = 16; o; o >>= 1) {
        s += __shfl_xor_sync(0xffffffffu, s, o);
        d += __shfl_xor_sync(0xffffffffu, d, o);
    }
    if (lane == 0) {
        g_asrc[n * H_HEADS + warp] = s;
        g_adst[n * H_HEADS + warp] = d;
    }
}

// ---------------- 3) CSR build ----------------
__global__ void zero_deg() {
    int i = blockIdx.x * blockDim.x + threadIdx.x;
    if (i < N_NODES) g_deg[i] = 0;
}

__global__ void deg_kernel(const int* __restrict__ graph_t) {
    int i = blockIdx.x * blockDim.x + threadIdx.x;
    if (i >= ETOT) return;
    int d = (i < E_EDGES) ? graph_t[E_EDGES + i] : (i - E_EDGES); // dst row
    atomicAdd(&g_deg[d], 1);
}

__global__ __launch_bounds__(1024) void scan_kernel() {
    __shared__ int s[1024];
    int tid = threadIdx.x;
    const int PER = 20; // 1024*20 >= 20000
    int base = tid * PER;
    int vals[PER];
    int run = 0;
#pragma unroll
    for (int i = 0; i < PER; i++) {
        int idx = base + i;
        int v = (idx < N_NODES) ? g_deg[idx] : 0;
        vals[i] = run;
        run += v;
    }
    s[tid] = run;
    __syncthreads();
    for (int off = 1; off < 1024; off <<= 1) {
        int v = (tid >= off) ? s[tid - off] : 0;
        __syncthreads();
        s[tid] += v;
        __syncthreads();
    }
    int prev = (tid == 0) ? 0 : s[tid - 1];
#pragma unroll
    for (int i = 0; i < PER; i++) {
        int idx = base + i;
        if (idx < N_NODES) {
            int r = prev + vals[i];
            g_rowptr[idx] = r;
            g_fill[idx] = r;
        }
    }
    if (tid == 1023) g_rowptr[N_NODES] = s[1023];
}

__global__ void scatter_kernel(const int* __restrict__ graph_t) {
    int i = blockIdx.x * blockDim.x + threadIdx.x;
    if (i >= ETOT) return;
    int sidx, d;
    if (i < E_EDGES) {
        sidx = graph_t[i];
        d    = graph_t[E_EDGES + i];
    } else {
        sidx = d = i - E_EDGES;
    }
    int pos = atomicAdd(&g_fill[d], 1);
    g_col[pos] = sidx;
}

// ---------------- 4) GAT aggregation (gather, warp per node-head) ----------------
// block = 256 threads = 8 warps = 2 nodes x 4 heads
__global__ __launch_bounds__(256) void aggregate_kernel(const float* __restrict__ b_gat) {
    __shared__ __align__(16) float acc_sm[2][H_HEADS][C_CH];
    int warp = threadIdx.x >> 5;
    int lane = threadIdx.x & 31;
    int nodeLocal = warp >> 2;
    int head = warp & 3;
    int n = blockIdx.x * 2 + nodeLocal;

    int beg = g_rowptr[n];
    int end = g_rowptr[n + 1];
    float ad = g_adst[n * H_HEADS + head];

    // pass 1: max
    float mx = -INFINITY;
    for (int k = beg + lane; k < end; k += 32) {
        int s = g_col[k];
        float e = leaky(g_asrc[s * H_HEADS + head] + ad);
        mx = fmaxf(mx, e);
    }
#pragma unroll
    for (int o = 16; o; o >>= 1) mx = fmaxf(mx, __shfl_xor_sync(0xffffffffu, mx, o));

    // pass 2: denom
    float sum = 0.f;
    for (int k = beg + lane; k < end; k += 32) {
        int s = g_col[k];
        float e = leaky(g_asrc[s * H_HEADS + head] + ad);
        sum += __expf(e - mx);
    }
#pragma unroll
    for (int o = 16; o; o >>= 1) sum += __shfl_xor_sync(0xffffffffu, sum, o);
    float inv = 1.f / (sum + 1e-16f);

    // pass 3: weighted gather of h[src]
    float4 acc = make_float4(0.f, 0.f, 0.f, 0.f);
    for (int k = beg; k < end; k++) {
        int s = g_col[k];                 // broadcast load
        float e = leaky(g_asrc[s * H_HEADS + head] + ad);
        float alpha = __expf(e - mx) * inv;
        const float4 v = ((const float4*)(g_h + (size_t)s * HC + head * C_CH))[lane];
        acc.x = fmaf(alpha, v.x, acc.x);
        acc.y = fmaf(alpha, v.y, acc.y);
        acc.z = fmaf(alpha, v.z, acc.z);
        acc.w = fmaf(alpha, v.w, acc.w);
    }
    ((float4*)&acc_sm[nodeLocal][head][lane * 4])[0] = acc;
    __syncthreads();

    // head mean + bias + leaky -> z
    int idx = threadIdx.x;
    int nl = idx >> 7;
    int c  = idx & 127;
    int n2 = blockIdx.x * 2 + nl;
    float v = 0.25f * (acc_sm[nl][0][c] + acc_sm[nl][1][c] + acc_sm[nl][2][c] + acc_sm[nl][3][c])
              + b_gat[c];
    g_z[(size_t)n2 * C_CH + c] = leaky(v);
}

// ---------------- 5) LP[t, n, j] = leaky(z @ W1 + b1)  (flat [T,N,C] layout) ----------------
// block = 128 threads (one per output col j), 32 nodes per block
__global__ __launch_bounds__(128) void lin_kernel(const float* __restrict__ W1,
                                                  const float* __restrict__ b1, int t) {
    __shared__ float zs[32 * 128];
    int j = threadIdx.x;
    int n0 = blockIdx.x * 32;
#pragma unroll
    for (int r = 0; r < 32; r++) {
        int n = n0 + r;
        zs[r * 128 + j] = (n < N_NODES) ? g_z[(size_t)n * C_CH + j] : 0.f;
    }
    __syncthreads();
    float acc[32];
    float b = b1[j];
#pragma unroll
    for (int r = 0; r < 32; r++) acc[r] = b;
    for (int k = 0; k < 128; k++) {
        float w = __ldg(&W1[k * 128 + j]);
#pragma unroll
        for (int r = 0; r < 32; r++) acc[r] = fmaf(zs[r * 128 + k], w, acc[r]);
    }
#pragma unroll
    for (int r = 0; r < 32; r++) {
        int n = n0 + r;
        if (n < N_NODES)
            g_LP[(size_t)t * N_NODES * C_CH + (size_t)n * C_CH + j] = leaky(acc[r]);
    }
}

// ---------------- 6) final: reshape-slab @ W2 + b2 -> log_softmax ----------------
// Reference reshape is a raw flatten of [T,N,C] into [N, T*C]:
// row n = contiguous flat elements [n*1024, (n+1)*1024) of g_LP.
__global__ __launch_bounds__(256) void final_kernel(const float* __restrict__ W2,
                                                    const float* __restrict__ b2,
                                                    float* __restrict__ out) {
    int gw = (blockIdx.x * blockDim.x + threadIdx.x) >> 5;
    int lane = threadIdx.x & 31;
    if (gw >= N_NODES) return;
    const float* row = g_LP + (size_t)gw * (T_STEPS * C_CH);
    float a0 = 0.f, a1 = 0.f;
    for (int i = lane; i < T_STEPS * C_CH; i += 32) {
        float v = row[i];
        a0 = fmaf(v, __ldg(&W2[i * 2 + 0]), a0);
        a1 = fmaf(v, __ldg(&W2[i * 2 + 1]), a1);
    }
#pragma unroll
    for (int o = 16; o; o >>= 1) {
        a0 += __shfl_xor_sync(0xffffffffu, a0, o);
        a1 += __shfl_xor_sync(0xffffffffu, a1, o);
    }
    if (lane == 0) {
        float f0 = a0 + b2[0];
        float f1 = a1 + b2[1];
        float m = fmaxf(f0, f1);
        float lse = m + logf(expf(f0 - m) + expf(f1 - m));
        out[gw * 2 + 0] = f0 - lse;
        out[gw * 2 + 1] = f1 - lse;
    }
}

// ---------------- launch ----------------
extern "C" void kernel_launch(void* const* d_in, const int* in_sizes, int n_in,
                              void* d_out, int out_size) {
    // metadata order: fts, graph, [time_steps scalar], W_gat, att_src, att_dst,
    //                 b_gat, W1, b1, W2, b2
    int base = 2;
    if (n_in >= 11 && in_sizes[2] <= 1) base = 3;  // time_steps present as scalar

    const float* fts     = (const float*)d_in[0];
    const int*   graph   = (const int*)d_in[1];
    const float* W_gat   = (const float*)d_in[base + 0];
    const float* att_src = (const float*)d_in[base + 1];
    const float* att_dst = (const float*)d_in[base + 2];
    const float* b_gat   = (const float*)d_in[base + 3];
    const float* W1      = (const float*)d_in[base + 4];
    const float* b1      = (const float*)d_in[base + 5];
    const float* W2      = (const float*)d_in[base + 6];
    const float* b2      = (const float*)d_in[base + 7];
    float* out = (float*)d_out;

    for (int t = 0; t < T_STEPS; t++) {
        const float* A = fts + (size_t)t * N_NODES * NFEAT;
        const int* gt  = graph + (size_t)t * 2 * E_EDGES;

        sgemm512<<<dim3(4, (N_NODES + 127) / 128), 256>>>(A, W_gat);
        att_kernel<<<N_NODES, 128>>>(att_src, att_dst);
        zero_deg<<<(N_NODES + 255) / 256, 256>>>();
        deg_kernel<<<(ETOT + 255) / 256, 256>>>(gt);
        scan_kernel<<<1, 1024>>>();
        scatter_kernel<<<(ETOT + 255) / 256, 256>>>(gt);
        aggregate_kernel<<<N_NODES / 2, 256>>>(b_gat);
        lin_kernel<<<(N_NODES + 31) / 32, 128>>>(W1, b1, t);
    }
    final_kernel<<<(N_NODES * 32 + 255) / 256, 256>>>(W2, b2, out);
}

// round 4
// speedup vs baseline: 1.5120x; 1.5120x over previous
#include <cuda_runtime.h>
#include <cuda_bf16.h>
#include <math.h>
#include <stdint.h>

#define N_NODES 20000
#define T_STEPS 8
#define E_EDGES 320000
#define ETOT    (E_EDGES + N_NODES)
#define NFEAT   512
#define HC      512        // H * C
#define H_HEADS 4
#define C_CH    128
#define SLOPEV  0.2f

#define MT_TILES 157       // ceil(20000/128)
#define NT_TILES 4         // 512/128

// ---------------- scratch (device globals; allocation-free) ----------------
__device__ float g_h[(size_t)N_NODES * HC];              // 41 MB
__device__ float g_asrc[N_NODES * H_HEADS];
__device__ float g_adst[N_NODES * H_HEADS];
__device__ int   g_deg[N_NODES];
__device__ int   g_rowptr[N_NODES + 1];
__device__ int   g_fill[N_NODES];
__device__ int   g_col[ETOT];
__device__ float g_z[(size_t)N_NODES * C_CH];
__device__ float g_LP[(size_t)T_STEPS * N_NODES * C_CH]; // 82 MB

__device__ __forceinline__ float leaky(float x) { return x >= 0.f ? x : SLOPEV * x; }

__device__ __forceinline__ uint32_t smem_u32(const void* p) {
    uint32_t a;
    asm("{ .reg .u64 t; cvta.to.shared.u64 t, %1; cvt.u32.u64 %0, t; }" : "=r"(a) : "l"(p));
    return a;
}
__device__ __forceinline__ void ldsm_x4(uint32_t& r0, uint32_t& r1, uint32_t& r2, uint32_t& r3,
                                        uint32_t addr) {
    asm volatile("ldmatrix.sync.aligned.m8n8.x4.shared.b16 {%0,%1,%2,%3}, [%4];"
                 : "=r"(r0), "=r"(r1), "=r"(r2), "=r"(r3) : "r"(addr));
}
__device__ __forceinline__ void ldsm_x2(uint32_t& r0, uint32_t& r1, uint32_t addr) {
    asm volatile("ldmatrix.sync.aligned.m8n8.x2.shared.b16 {%0,%1}, [%2];"
                 : "=r"(r0), "=r"(r1) : "r"(addr));
}
__device__ __forceinline__ void mma16816(float* c, const uint32_t* a, const uint32_t* b) {
    asm volatile(
        "mma.sync.aligned.m16n8k16.row.col.f32.bf16.bf16.f32 "
        "{%0,%1,%2,%3}, {%4,%5,%6,%7}, {%8,%9}, {%0,%1,%2,%3};"
        : "+f"(c[0]), "+f"(c[1]), "+f"(c[2]), "+f"(c[3])
        : "r"(a[0]), "r"(a[1]), "r"(a[2]), "r"(a[3]), "r"(b[0]), "r"(b[1]));
}
__device__ __forceinline__ uint32_t pack_hi2(float v0, float v1) {
    __nv_bfloat162 p = __floats2bfloat162_rn(v0, v1);
    return *reinterpret_cast<uint32_t*>(&p);
}

// ---------------- 1) GEMM: g_h = A[20000,512] @ W[512,512], bf16 mma.sync, 3-term split ----
// CTA: 128x128 tile, 8 warps (warpM 0..3 -> 32 rows, warpN 0..1 -> 64 cols), BK=32
#define ROWP 40   // padded row length (bf16 elems): 80 B, 16B-aligned, conflict-free
__global__ __launch_bounds__(256) void gemm_mma(const float* __restrict__ A,
                                                const float* __restrict__ W) {
    __shared__ __align__(16) uint16_t Ah[128][ROWP], Al[128][ROWP];
    __shared__ __align__(16) uint16_t Bh[128][ROWP], Bl[128][ROWP];

    const int tid = threadIdx.x, warp = tid >> 5, lane = tid & 31;
    const int mt = blockIdx.y, nt = blockIdx.x;
    const int warpM = warp & 3, warpN = warp >> 2;

    float acc[2][8][4];
#pragma unroll
    for (int i = 0; i < 2; i++)
#pragma unroll
        for (int j = 0; j < 8; j++)
#pragma unroll
            for (int q = 0; q < 4; q++) acc[i][j][q] = 0.f;

    // A tile loader mapping: row = tid>>1 (0..127), 16 cols starting at (tid&1)*16
    const int aRow = tid >> 1;
    const int aCol = (tid & 1) * 16;
    const int node = mt * 128 + aRow;
    const bool aValid = node < N_NODES;
    const float* aSrc = A + (size_t)node * 512 + aCol;

    // B tile loader mapping: n = tid&127 (col of W), khalf = (tid>>7)*16
    const int bN = tid & 127;
    const int bK = (tid >> 7) * 16;
    const float* bSrc = W + (size_t)bK * 512 + nt * 128 + bN;

    // ldmatrix per-lane addresses
    const uint32_t ahBase = smem_u32(&Ah[0][0]);
    const uint32_t alBase = smem_u32(&Al[0][0]);
    const uint32_t bhBase = smem_u32(&Bh[0][0]);
    const uint32_t blBase = smem_u32(&Bl[0][0]);
    const int aLdRow = warpM * 32 + (lane & 7) + ((lane >> 3) & 1) * 8; // + mf*16
    const int aLdK   = (lane >> 4) * 8;                                 // within k16
    const int bLdRow = warpN * 64 + (lane & 7);                         // + nf*8
    const int bLdK   = ((lane >> 3) & 1) * 8;

    for (int k0 = 0; k0 < 512; k0 += 32) {
        // ---- stage A (128x32) ----
        float4 v0 = make_float4(0.f, 0.f, 0.f, 0.f), v1 = v0, v2 = v0, v3 = v0;
        if (aValid) {
            const float4* p = (const float4*)(aSrc + k0);
            v0 = p[0]; v1 = p[1]; v2 = p[2]; v3 = p[3];
        }
        // ---- stage B (32x128, transposed into [n][k]) ----
        float bv[16];
#pragma unroll
        for (int e = 0; e < 16; e++) bv[e] = bSrc[(size_t)(k0 + e) * 512];

        __syncthreads();
        {
            uint32_t* ahp = (uint32_t*)&Ah[aRow][aCol];
            uint32_t* alp = (uint32_t*)&Al[aRow][aCol];
            float vv[16] = {v0.x, v0.y, v0.z, v0.w, v1.x, v1.y, v1.z, v1.w,
                            v2.x, v2.y, v2.z, v2.w, v3.x, v3.y, v3.z, v3.w};
#pragma unroll
            for (int e = 0; e < 8; e++) {
                float f0 = vv[e * 2], f1 = vv[e * 2 + 1];
                float h0 = __bfloat162float(__float2bfloat16(f0));
                float h1 = __bfloat162float(__float2bfloat16(f1));
                ahp[e] = pack_hi2(f0, f1);
                alp[e] = pack_hi2(f0 - h0, f1 - h1);
            }
            uint32_t* bhp = (uint32_t*)&Bh[bN][bK];
            uint32_t* blp = (uint32_t*)&Bl[bN][bK];
#pragma unroll
            for (int e = 0; e < 8; e++) {
                float f0 = bv[e * 2], f1 = bv[e * 2 + 1];
                float h0 = __bfloat162float(__float2bfloat16(f0));
                float h1 = __bfloat162float(__float2bfloat16(f1));
                bhp[e] = pack_hi2(f0, f1);
                blp[e] = pack_hi2(f0 - h0, f1 - h1);
            }
        }
        __syncthreads();

        // ---- compute 2 k-steps of 16 ----
#pragma unroll
        for (int kk = 0; kk < 32; kk += 16) {
            uint32_t bhf[8][2], blf[8][2];
#pragma unroll
            for (int nf = 0; nf < 8; nf++) {
                uint32_t off = (uint32_t)((bLdRow + nf * 8) * (ROWP * 2) + (kk + bLdK) * 2);
                ldsm_x2(bhf[nf][0], bhf[nf][1], bhBase + off);
                ldsm_x2(blf[nf][0], blf[nf][1], blBase + off);
            }
            uint32_t ahf[2][4], alf[2][4];
#pragma unroll
            for (int mf = 0; mf < 2; mf++) {
                uint32_t off = (uint32_t)((aLdRow + mf * 16) * (ROWP * 2) + (kk + aLdK) * 2);
                ldsm_x4(ahf[mf][0], ahf[mf][1], ahf[mf][2], ahf[mf][3], ahBase + off);
                ldsm_x4(alf[mf][0], alf[mf][1], alf[mf][2], alf[mf][3], alBase + off);
            }
#pragma unroll
            for (int mf = 0; mf < 2; mf++)
#pragma unroll
                for (int nf = 0; nf < 8; nf++) {
                    mma16816(acc[mf][nf], ahf[mf], bhf[nf]);
                    mma16816(acc[mf][nf], alf[mf], bhf[nf]);
                    mma16816(acc[mf][nf], ahf[mf], blf[nf]);
                }
        }
    }

    // ---- epilogue ----
    const int r0 = lane >> 2, c0 = (lane & 3) * 2;
#pragma unroll
    for (int mf = 0; mf < 2; mf++) {
#pragma unroll
        for (int nf = 0; nf < 8; nf++) {
            int row = mt * 128 + warpM * 32 + mf * 16 + r0;
            int col = nt * 128 + warpN * 64 + nf * 8 + c0;
            if (row < N_NODES)
                *(float2*)(g_h + (size_t)row * 512 + col) = make_float2(acc[mf][nf][0], acc[mf][nf][1]);
            if (row + 8 < N_NODES)
                *(float2*)(g_h + (size_t)(row + 8) * 512 + col) = make_float2(acc[mf][nf][2], acc[mf][nf][3]);
        }
    }
}

// ---------------- 2) attention coefficients ----------------
__global__ __launch_bounds__(128) void att_kernel(const float* __restrict__ att_src,
                                                  const float* __restrict__ att_dst) {
    int n = blockIdx.x;
    int warp = threadIdx.x >> 5;
    int lane = threadIdx.x & 31;
    const float4 v  = ((const float4*)(g_h + (size_t)n * HC + warp * C_CH))[lane];
    const float4 as = ((const float4*)(att_src + warp * C_CH))[lane];
    const float4 ad = ((const float4*)(att_dst + warp * C_CH))[lane];
    float s = v.x * as.x + v.y * as.y + v.z * as.z + v.w * as.w;
    float d = v.x * ad.x + v.y * ad.y + v.z * ad.z + v.w * ad.w;
#pragma unroll
    for (int o = 16; o; o >>= 1) {
        s += __shfl_xor_sync(0xffffffffu, s, o);
        d += __shfl_xor_sync(0xffffffffu, d, o);
    }
    if (lane == 0) {
        g_asrc[n * H_HEADS + warp] = s;
        g_adst[n * H_HEADS + warp] = d;
    }
}

// ---------------- 3) CSR build ----------------
__global__ void zero_deg() {
    int i = blockIdx.x * blockDim.x + threadIdx.x;
    if (i < N_NODES) g_deg[i] = 0;
}

__global__ void deg_kernel(const int* __restrict__ graph_t) {
    int i = blockIdx.x * blockDim.x + threadIdx.x;
    if (i >= ETOT) return;
    int d = (i < E_EDGES) ? graph_t[E_EDGES + i] : (i - E_EDGES);
    atomicAdd(&g_deg[d], 1);
}

__global__ __launch_bounds__(1024) void scan_kernel() {
    __shared__ int s[1024];
    int tid = threadIdx.x;
    const int PER = 20;
    int base = tid * PER;
    int vals[PER];
    int run = 0;
#pragma unroll
    for (int i = 0; i < PER; i++) {
        int idx = base + i;
        int v = (idx < N_NODES) ? g_deg[idx] : 0;
        vals[i] = run;
        run += v;
    }
    s[tid] = run;
    __syncthreads();
    for (int off = 1; off < 1024; off <<= 1) {
        int v = (tid >= off) ? s[tid - off] : 0;
        __syncthreads();
        s[tid] += v;
        __syncthreads();
    }
    int prev = (tid == 0) ? 0 : s[tid - 1];
#pragma unroll
    for (int i = 0; i < PER; i++) {
        int idx = base + i;
        if (idx < N_NODES) {
            int r = prev + vals[i];
            g_rowptr[idx] = r;
            g_fill[idx] = r;
        }
    }
    if (tid == 1023) g_rowptr[N_NODES] = s[1023];
}

__global__ void scatter_kernel(const int* __restrict__ graph_t) {
    int i = blockIdx.x * blockDim.x + threadIdx.x;
    if (i >= ETOT) return;
    int sidx, d;
    if (i < E_EDGES) {
        sidx = graph_t[i];
        d    = graph_t[E_EDGES + i];
    } else {
        sidx = d = i - E_EDGES;
    }
    int pos = atomicAdd(&g_fill[d], 1);
    g_col[pos] = sidx;
}

// ---------------- 4) GAT aggregation ----------------
__global__ __launch_bounds__(256) void aggregate_kernel(const float* __restrict__ b_gat) {
    __shared__ __align__(16) float acc_sm[2][H_HEADS][C_CH];
    int warp = threadIdx.x >> 5;
    int lane = threadIdx.x & 31;
    int nodeLocal = warp >> 2;
    int head = warp & 3;
    int n = blockIdx.x * 2 + nodeLocal;

    int beg = g_rowptr[n];
    int end = g_rowptr[n + 1];
    float ad = g_adst[n * H_HEADS + head];

    float mx = -INFINITY;
    for (int k = beg + lane; k < end; k += 32) {
        int s = g_col[k];
        float e = leaky(g_asrc[s * H_HEADS + head] + ad);
        mx = fmaxf(mx, e);
    }
#pragma unroll
    for (int o = 16; o; o >>= 1) mx = fmaxf(mx, __shfl_xor_sync(0xffffffffu, mx, o));

    float sum = 0.f;
    for (int k = beg + lane; k < end; k += 32) {
        int s = g_col[k];
        float e = leaky(g_asrc[s * H_HEADS + head] + ad);
        sum += __expf(e - mx);
    }
#pragma unroll
    for (int o = 16; o; o >>= 1) sum += __shfl_xor_sync(0xffffffffu, sum, o);
    float inv = 1.f / (sum + 1e-16f);

    float4 acc = make_float4(0.f, 0.f, 0.f, 0.f);
    for (int k = beg; k < end; k++) {
        int s = g_col[k];
        float e = leaky(g_asrc[s * H_HEADS + head] + ad);
        float alpha = __expf(e - mx) * inv;
        const float4 v = ((const float4*)(g_h + (size_t)s * HC + head * C_CH))[lane];
        acc.x = fmaf(alpha, v.x, acc.x);
        acc.y = fmaf(alpha, v.y, acc.y);
        acc.z = fmaf(alpha, v.z, acc.z);
        acc.w = fmaf(alpha, v.w, acc.w);
    }
    ((float4*)&acc_sm[nodeLocal][head][lane * 4])[0] = acc;
    __syncthreads();

    int idx = threadIdx.x;
    int nl = idx >> 7;
    int c  = idx & 127;
    int n2 = blockIdx.x * 2 + nl;
    float v = 0.25f * (acc_sm[nl][0][c] + acc_sm[nl][1][c] + acc_sm[nl][2][c] + acc_sm[nl][3][c])
              + b_gat[c];
    g_z[(size_t)n2 * C_CH + c] = leaky(v);
}

// ---------------- 5) LP[t, n, j] = leaky(z @ W1 + b1) ----------------
__global__ __launch_bounds__(128) void lin_kernel(const float* __restrict__ W1,
                                                  const float* __restrict__ b1, int t) {
    __shared__ float zs[32 * 128];
    int j = threadIdx.x;
    int n0 = blockIdx.x * 32;
#pragma unroll
    for (int r = 0; r < 32; r++) {
        int n = n0 + r;
        zs[r * 128 + j] = (n < N_NODES) ? g_z[(size_t)n * C_CH + j] : 0.f;
    }
    __syncthreads();
    float acc[32];
    float b = b1[j];
#pragma unroll
    for (int r = 0; r < 32; r++) acc[r] = b;
    for (int k = 0; k < 128; k++) {
        float w = __ldg(&W1[k * 128 + j]);
#pragma unroll
        for (int r = 0; r < 32; r++) acc[r] = fmaf(zs[r * 128 + k], w, acc[r]);
    }
#pragma unroll
    for (int r = 0; r < 32; r++) {
        int n = n0 + r;
        if (n < N_NODES)
            g_LP[(size_t)t * N_NODES * C_CH + (size_t)n * C_CH + j] = leaky(acc[r]);
    }
}

// ---------------- 6) final: reshape-slab @ W2 + b2 -> log_softmax ----------------
__global__ __launch_bounds__(256) void final_kernel(const float* __restrict__ W2,
                                                    const float* __restrict__ b2,
                                                    float* __restrict__ out) {
    int gw = (blockIdx.x * blockDim.x + threadIdx.x) >> 5;
    int lane = threadIdx.x & 31;
    if (gw >= N_NODES) return;
    const float* row = g_LP + (size_t)gw * (T_STEPS * C_CH);
    float a0 = 0.f, a1 = 0.f;
    for (int i = lane; i < T_STEPS * C_CH; i += 32) {
        float v = row[i];
        a0 = fmaf(v, __ldg(&W2[i * 2 + 0]), a0);
        a1 = fmaf(v, __ldg(&W2[i * 2 + 1]), a1);
    }
#pragma unroll
    for (int o = 16; o; o >>= 1) {
        a0 += __shfl_xor_sync(0xffffffffu, a0, o);
        a1 += __shfl_xor_sync(0xffffffffu, a1, o);
    }
    if (lane == 0) {
        float f0 = a0 + b2[0];
        float f1 = a1 + b2[1];
        float m = fmaxf(f0, f1);
        float lse = m + logf(expf(f0 - m) + expf(f1 - m));
        out[gw * 2 + 0] = f0 - lse;
        out[gw * 2 + 1] = f1 - lse;
    }
}

// ---------------- launch ----------------
extern "C" void kernel_launch(void* const* d_in, const int* in_sizes, int n_in,
                              void* d_out, int out_size) {
    int base = 2;
    if (n_in >= 11 && in_sizes[2] <= 1) base = 3;

    const float* fts     = (const float*)d_in[0];
    const int*   graph   = (const int*)d_in[1];
    const float* W_gat   = (const float*)d_in[base + 0];
    const float* att_src = (const float*)d_in[base + 1];
    const float* att_dst = (const float*)d_in[base + 2];
    const float* b_gat   = (const float*)d_in[base + 3];
    const float* W1      = (const float*)d_in[base + 4];
    const float* b1      = (const float*)d_in[base + 5];
    const float* W2      = (const float*)d_in[base + 6];
    const float* b2      = (const float*)d_in[base + 7];
    float* out = (float*)d_out;

    for (int t = 0; t < T_STEPS; t++) {
        const float* A = fts + (size_t)t * N_NODES * NFEAT;
        const int* gt  = graph + (size_t)t * 2 * E_EDGES;

        gemm_mma<<<dim3(NT_TILES, MT_TILES), 256>>>(A, W_gat);
        att_kernel<<<N_NODES, 128>>>(att_src, att_dst);
        zero_deg<<<(N_NODES + 255) / 256, 256>>>();
        deg_kernel<<<(ETOT + 255) / 256, 256>>>(gt);
        scan_kernel<<<1, 1024>>>();
        scatter_kernel<<<(ETOT + 255) / 256, 256>>>(gt);
        aggregate_kernel<<<N_NODES / 2, 256>>>(b_gat);
        lin_kernel<<<(N_NODES + 31) / 32, 128>>>(W1, b1, t);
    }
    final_kernel<<<(N_NODES * 32 + 255) / 256, 256>>>(W2, b2, out);
}

// round 5
// speedup vs baseline: 1.5763x; 1.0425x over previous
#include <cuda_runtime.h>
#include <cuda_bf16.h>
#include <math.h>
#include <stdint.h>

#define N_NODES 20000
#define T_STEPS 8
#define E_EDGES 320000
#define ETOT    (E_EDGES + N_NODES)
#define NFEAT   512
#define HC      512
#define H_HEADS 4
#define C_CH    128
#define SLOPEV  0.2f

#define MT_TILES 157
#define NT_TILES 4
#define BK 32

// ---------------- scratch ----------------
__device__ float g_h[(size_t)N_NODES * HC];
__device__ float g_asrc[N_NODES * H_HEADS];
__device__ float g_adst[N_NODES * H_HEADS];
__device__ float g_z[(size_t)N_NODES * C_CH];
__device__ float g_LP[(size_t)T_STEPS * N_NODES * C_CH];
__device__ uint16_t g_B16h[512 * 512];   // [n][k]
__device__ uint16_t g_B16l[512 * 512];
// batched CSR
__device__ int g_degT[T_STEPS * N_NODES];
__device__ int g_rowptrT[T_STEPS * (N_NODES + 1)];
__device__ int g_fillT[T_STEPS * N_NODES];
__device__ int g_colT[(size_t)T_STEPS * ETOT];

__device__ __forceinline__ float leaky(float x) { return x >= 0.f ? x : SLOPEV * x; }

__device__ __forceinline__ uint32_t smem_u32(const void* p) {
    uint32_t a;
    asm("{ .reg .u64 t; cvta.to.shared.u64 t, %1; cvt.u32.u64 %0, t; }" : "=r"(a) : "l"(p));
    return a;
}
__device__ __forceinline__ void ldsm_x4(uint32_t& r0, uint32_t& r1, uint32_t& r2, uint32_t& r3,
                                        uint32_t addr) {
    asm volatile("ldmatrix.sync.aligned.m8n8.x4.shared.b16 {%0,%1,%2,%3}, [%4];"
                 : "=r"(r0), "=r"(r1), "=r"(r2), "=r"(r3) : "r"(addr));
}
__device__ __forceinline__ void ldsm_x2(uint32_t& r0, uint32_t& r1, uint32_t addr) {
    asm volatile("ldmatrix.sync.aligned.m8n8.x2.shared.b16 {%0,%1}, [%2];"
                 : "=r"(r0), "=r"(r1) : "r"(addr));
}
__device__ __forceinline__ void mma16816(float* c, const uint32_t* a, const uint32_t* b) {
    asm volatile(
        "mma.sync.aligned.m16n8k16.row.col.f32.bf16.bf16.f32 "
        "{%0,%1,%2,%3}, {%4,%5,%6,%7}, {%8,%9}, {%0,%1,%2,%3};"
        : "+f"(c[0]), "+f"(c[1]), "+f"(c[2]), "+f"(c[3])
        : "r"(a[0]), "r"(a[1]), "r"(a[2]), "r"(a[3]), "r"(b[0]), "r"(b[1]));
}
__device__ __forceinline__ uint32_t pack_hi2(float v0, float v1) {
    __nv_bfloat162 p = __floats2bfloat162_rn(v0, v1);
    return *reinterpret_cast<uint32_t*>(&p);
}
__device__ __forceinline__ void cp16(uint32_t dst, const void* src) {
    asm volatile("cp.async.cg.shared.global [%0], [%1], 16;" :: "r"(dst), "l"(src));
}
#define CP_COMMIT() asm volatile("cp.async.commit_group;" ::: "memory")
#define CP_WAIT0()  asm volatile("cp.async.wait_group 0;" ::: "memory")

// ---------------- 0) convert W -> bf16 hi/lo, [n][k] layout ----------------
__global__ void conv_B(const float* __restrict__ W) {
    int i = blockIdx.x * blockDim.x + threadIdx.x;
    if (i >= 512 * 512) return;
    int k = i >> 9, n = i & 511;
    float v = W[(size_t)k * 512 + n];
    __nv_bfloat16 h = __float2bfloat16(v);
    __nv_bfloat16 l = __float2bfloat16(v - __bfloat162float(h));
    g_B16h[(size_t)n * 512 + k] = *reinterpret_cast<uint16_t*>(&h);
    g_B16l[(size_t)n * 512 + k] = *reinterpret_cast<uint16_t*>(&l);
}

// ---------------- 1) GEMM: pipelined cp.async + mma.sync, 3-term bf16 ----------------
#define A32_PITCH 36                           // floats (144 B rows)
#define BF_PITCH  40                           // bf16 (80 B rows)
#define A32_STAGE (128 * A32_PITCH * 4)        // 18432 B
#define BF_STAGE  (128 * BF_PITCH * 2)         // 10240 B
#define OFF_AS32  0
#define OFF_AH    (2 * A32_STAGE)              // 36864
#define OFF_AL    (OFF_AH + 2 * BF_STAGE)      // 57344
#define OFF_BH    (OFF_AL + 2 * BF_STAGE)      // 77824
#define OFF_BL    (OFF_BH + 2 * BF_STAGE)      // 98304
#define GEMM_SMEM_TOT (OFF_BL + 2 * BF_STAGE)  // 118784

__device__ __forceinline__ void load_stage(uint32_t sb, int tid, int mt, int nt,
                                           const float* __restrict__ A, int buf, int k0) {
#pragma unroll
    for (int c = 0; c < 4; c++) {
        int idx = tid + c * 256;
        int row = idx >> 3, ch = idx & 7;
        int node = mt * 128 + row;
        if (node > N_NODES - 1) node = N_NODES - 1;
        const float* src = A + (size_t)node * 512 + k0 + ch * 4;
        cp16(sb + OFF_AS32 + buf * A32_STAGE + row * (A32_PITCH * 4) + ch * 16, src);
    }
#pragma unroll
    for (int c = 0; c < 2; c++) {
        int idx = tid + c * 256;
        int row = idx >> 2, ch = idx & 3;
        const uint16_t* srh = g_B16h + (size_t)(nt * 128 + row) * 512 + k0 + ch * 8;
        const uint16_t* srl = g_B16l + (size_t)(nt * 128 + row) * 512 + k0 + ch * 8;
        cp16(sb + OFF_BH + buf * BF_STAGE + row * (BF_PITCH * 2) + ch * 16, srh);
        cp16(sb + OFF_BL + buf * BF_STAGE + row * (BF_PITCH * 2) + ch * 16, srl);
    }
}

__global__ __launch_bounds__(256) void gemm_mma(const float* __restrict__ A) {
    extern __shared__ __align__(16) unsigned char sm[];
    uint32_t sb = smem_u32(sm);
    const int tid = threadIdx.x, warp = tid >> 5, lane = tid & 31;
    const int mt = blockIdx.y, nt = blockIdx.x;
    const int warpM = warp & 3, warpN = warp >> 2;

    float acc[2][8][4];
#pragma unroll
    for (int i = 0; i < 2; i++)
#pragma unroll
        for (int j = 0; j < 8; j++)
#pragma unroll
            for (int q = 0; q < 4; q++) acc[i][j][q] = 0.f;

    const int cRow = tid >> 1, cHalf = tid & 1;
    const bool cValid = (mt * 128 + cRow) < N_NODES;

    const uint32_t ahB = sb + OFF_AH, alB = sb + OFF_AL;
    const uint32_t bhB = sb + OFF_BH, blB = sb + OFF_BL;
    const int aLdRow = warpM * 32 + (lane & 7) + ((lane >> 3) & 1) * 8;
    const int aLdK   = (lane >> 4) * 8;
    const int bLdRow = warpN * 64 + (lane & 7);
    const int bLdK   = ((lane >> 3) & 1) * 8;

    load_stage(sb, tid, mt, nt, A, 0, 0);
    CP_COMMIT();

    for (int it = 0; it < 16; it++) {
        const int cur = it & 1;
        CP_WAIT0();
        __syncthreads();
        if (it + 1 < 16) {
            load_stage(sb, tid, mt, nt, A, cur ^ 1, (it + 1) * BK);
            CP_COMMIT();
        }
        // convert A fp32 -> bf16 hi/lo
        {
            const float* s32 = (const float*)(sm + OFF_AS32 + cur * A32_STAGE)
                               + cRow * A32_PITCH + cHalf * 16;
            uint32_t* hdst = (uint32_t*)(sm + OFF_AH + cur * BF_STAGE
                               + cRow * (BF_PITCH * 2) + cHalf * 32);
            uint32_t* ldst = (uint32_t*)(sm + OFF_AL + cur * BF_STAGE
                               + cRow * (BF_PITCH * 2) + cHalf * 32);
#pragma unroll
            for (int e = 0; e < 8; e++) {
                float f0 = cValid ? s32[e * 2] : 0.f;
                float f1 = cValid ? s32[e * 2 + 1] : 0.f;
                float h0 = __bfloat162float(__float2bfloat16(f0));
                float h1 = __bfloat162float(__float2bfloat16(f1));
                hdst[e] = pack_hi2(f0, f1);
                ldst[e] = pack_hi2(f0 - h0, f1 - h1);
            }
        }
        __syncthreads();

#pragma unroll
        for (int kk = 0; kk < 32; kk += 16) {
            uint32_t bhf[8][2], blf[8][2];
#pragma unroll
            for (int nf = 0; nf < 8; nf++) {
                uint32_t off = (uint32_t)(cur * BF_STAGE + (bLdRow + nf * 8) * (BF_PITCH * 2)
                                          + (kk + bLdK) * 2);
                ldsm_x2(bhf[nf][0], bhf[nf][1], bhB + off);
                ldsm_x2(blf[nf][0], blf[nf][1], blB + off);
            }
            uint32_t ahf[2][4], alf[2][4];
#pragma unroll
            for (int mf = 0; mf < 2; mf++) {
                uint32_t off = (uint32_t)(cur * BF_STAGE + (aLdRow + mf * 16) * (BF_PITCH * 2)
                                          + (kk + aLdK) * 2);
                ldsm_x4(ahf[mf][0], ahf[mf][1], ahf[mf][2], ahf[mf][3], ahB + off);
                ldsm_x4(alf[mf][0], alf[mf][1], alf[mf][2], alf[mf][3], alB + off);
            }
#pragma unroll
            for (int mf = 0; mf < 2; mf++)
#pragma unroll
                for (int nf = 0; nf < 8; nf++) {
                    mma16816(acc[mf][nf], ahf[mf], bhf[nf]);
                    mma16816(acc[mf][nf], alf[mf], bhf[nf]);
                    mma16816(acc[mf][nf], ahf[mf], blf[nf]);
                }
        }
    }

    const int r0 = lane >> 2, c0 = (lane & 3) * 2;
#pragma unroll
    for (int mf = 0; mf < 2; mf++) {
#pragma unroll
        for (int nf = 0; nf < 8; nf++) {
            int row = mt * 128 + warpM * 32 + mf * 16 + r0;
            int col = nt * 128 + warpN * 64 + nf * 8 + c0;
            if (row < N_NODES)
                *(float2*)(g_h + (size_t)row * 512 + col) = make_float2(acc[mf][nf][0], acc[mf][nf][1]);
            if (row + 8 < N_NODES)
                *(float2*)(g_h + (size_t)(row + 8) * 512 + col) = make_float2(acc[mf][nf][2], acc[mf][nf][3]);
        }
    }
}

// ---------------- 2) attention coefficients ----------------
__global__ __launch_bounds__(128) void att_kernel(const float* __restrict__ att_src,
                                                  const float* __restrict__ att_dst) {
    int n = blockIdx.x;
    int warp = threadIdx.x >> 5;
    int lane = threadIdx.x & 31;
    const float4 v  = ((const float4*)(g_h + (size_t)n * HC + warp * C_CH))[lane];
    const float4 as = ((const float4*)(att_src + warp * C_CH))[lane];
    const float4 ad = ((const float4*)(att_dst + warp * C_CH))[lane];
    float s = v.x * as.x + v.y * as.y + v.z * as.z + v.w * as.w;
    float d = v.x * ad.x + v.y * ad.y + v.z * ad.z + v.w * ad.w;
#pragma unroll
    for (int o = 16; o; o >>= 1) {
        s += __shfl_xor_sync(0xffffffffu, s, o);
        d += __shfl_xor_sync(0xffffffffu, d, o);
    }
    if (lane == 0) {
        g_asrc[n * H_HEADS + warp] = s;
        g_adst[n * H_HEADS + warp] = d;
    }
}

// ---------------- 3) batched CSR build (all T at once) ----------------
__global__ void zero_degT() {
    int i = blockIdx.x * blockDim.x + threadIdx.x;
    if (i < T_STEPS * N_NODES) g_degT[i] = 0;
}

__global__ void degT_kernel(const int* __restrict__ graph) {
    int i = blockIdx.x * blockDim.x + threadIdx.x;
    if (i >= T_STEPS * ETOT) return;
    int t = i / ETOT, e = i - t * ETOT;
    int d = (e < E_EDGES) ? graph[(size_t)t * 2 * E_EDGES + E_EDGES + e] : (e - E_EDGES);
    atomicAdd(&g_degT[t * N_NODES + d], 1);
}

__global__ __launch_bounds__(1024) void scanT_kernel() {
    __shared__ int s[1024];
    int t = blockIdx.x;
    const int* deg = g_degT + t * N_NODES;
    int* rowptr = g_rowptrT + t * (N_NODES + 1);
    int* fill = g_fillT + t * N_NODES;
    int tid = threadIdx.x;
    const int PER = 20;
    int base = tid * PER;
    int vals[PER];
    int run = 0;
#pragma unroll
    for (int i = 0; i < PER; i++) {
        int idx = base + i;
        int v = (idx < N_NODES) ? deg[idx] : 0;
        vals[i] = run;
        run += v;
    }
    s[tid] = run;
    __syncthreads();
    for (int off = 1; off < 1024; off <<= 1) {
        int v = (tid >= off) ? s[tid - off] : 0;
        __syncthreads();
        s[tid] += v;
        __syncthreads();
    }
    int prev = (tid == 0) ? 0 : s[tid - 1];
#pragma unroll
    for (int i = 0; i < PER; i++) {
        int idx = base + i;
        if (idx < N_NODES) {
            int r = prev + vals[i];
            rowptr[idx] = r;
            fill[idx] = r;
        }
    }
    if (tid == 1023) rowptr[N_NODES] = s[1023];
}

__global__ void scatterT_kernel(const int* __restrict__ graph) {
    int i = blockIdx.x * blockDim.x + threadIdx.x;
    if (i >= T_STEPS * ETOT) return;
    int t = i / ETOT, e = i - t * ETOT;
    int sidx, d;
    if (e < E_EDGES) {
        sidx = graph[(size_t)t * 2 * E_EDGES + e];
        d    = graph[(size_t)t * 2 * E_EDGES + E_EDGES + e];
    } else {
        sidx = d = e - E_EDGES;
    }
    int pos = atomicAdd(&g_fillT[t * N_NODES + d], 1);
    g_colT[(size_t)t * ETOT + pos] = sidx;
}

// ---------------- 4) GAT aggregation ----------------
__global__ __launch_bounds__(256) void aggregate_kernel(const float* __restrict__ b_gat, int t) {
    __shared__ __align__(16) float acc_sm[2][H_HEADS][C_CH];
    int warp = threadIdx.x >> 5;
    int lane = threadIdx.x & 31;
    int nodeLocal = warp >> 2;
    int head = warp & 3;
    int n = blockIdx.x * 2 + nodeLocal;

    const int* rowptr = g_rowptrT + t * (N_NODES + 1);
    const int* col = g_colT + (size_t)t * ETOT;

    int beg = rowptr[n];
    int end = rowptr[n + 1];
    float ad = g_adst[n * H_HEADS + head];

    float mx = -INFINITY;
    for (int k = beg + lane; k < end; k += 32) {
        int s = col[k];
        float e = leaky(g_asrc[s * H_HEADS + head] + ad);
        mx = fmaxf(mx, e);
    }
#pragma unroll
    for (int o = 16; o; o >>= 1) mx = fmaxf(mx, __shfl_xor_sync(0xffffffffu, mx, o));

    float sum = 0.f;
    for (int k = beg + lane; k < end; k += 32) {
        int s = col[k];
        float e = leaky(g_asrc[s * H_HEADS + head] + ad);
        sum += __expf(e - mx);
    }
#pragma unroll
    for (int o = 16; o; o >>= 1) sum += __shfl_xor_sync(0xffffffffu, sum, o);
    float inv = 1.f / (sum + 1e-16f);

    float4 acc = make_float4(0.f, 0.f, 0.f, 0.f);
    for (int k = beg; k < end; k++) {
        int s = col[k];
        float e = leaky(g_asrc[s * H_HEADS + head] + ad);
        float alpha = __expf(e - mx) * inv;
        const float4 v = ((const float4*)(g_h + (size_t)s * HC + head * C_CH))[lane];
        acc.x = fmaf(alpha, v.x, acc.x);
        acc.y = fmaf(alpha, v.y, acc.y);
        acc.z = fmaf(alpha, v.z, acc.z);
        acc.w = fmaf(alpha, v.w, acc.w);
    }
    ((float4*)&acc_sm[nodeLocal][head][lane * 4])[0] = acc;
    __syncthreads();

    int idx = threadIdx.x;
    int nl = idx >> 7;
    int c  = idx & 127;
    int n2 = blockIdx.x * 2 + nl;
    float v = 0.25f * (acc_sm[nl][0][c] + acc_sm[nl][1][c] + acc_sm[nl][2][c] + acc_sm[nl][3][c])
              + b_gat[c];
    g_z[(size_t)n2 * C_CH + c] = leaky(v);
}

// ---------------- 5) LP[t, n, j] = leaky(z @ W1 + b1) ----------------
__global__ __launch_bounds__(128) void lin_kernel(const float* __restrict__ W1,
                                                  const float* __restrict__ b1, int t) {
    __shared__ float zs[32 * 128];
    int j = threadIdx.x;
    int n0 = blockIdx.x * 32;
#pragma unroll
    for (int r = 0; r < 32; r++) {
        int n = n0 + r;
        zs[r * 128 + j] = (n < N_NODES) ? g_z[(size_t)n * C_CH + j] : 0.f;
    }
    __syncthreads();
    float acc[32];
    float b = b1[j];
#pragma unroll
    for (int r = 0; r < 32; r++) acc[r] = b;
    for (int k = 0; k < 128; k++) {
        float w = __ldg(&W1[k * 128 + j]);
#pragma unroll
        for (int r = 0; r < 32; r++) acc[r] = fmaf(zs[r * 128 + k], w, acc[r]);
    }
#pragma unroll
    for (int r = 0; r < 32; r++) {
        int n = n0 + r;
        if (n < N_NODES)
            g_LP[(size_t)t * N_NODES * C_CH + (size_t)n * C_CH + j] = leaky(acc[r]);
    }
}

// ---------------- 6) final ----------------
__global__ __launch_bounds__(256) void final_kernel(const float* __restrict__ W2,
                                                    const float* __restrict__ b2,
                                                    float* __restrict__ out) {
    int gw = (blockIdx.x * blockDim.x + threadIdx.x) >> 5;
    int lane = threadIdx.x & 31;
    if (gw >= N_NODES) return;
    const float* row = g_LP + (size_t)gw * (T_STEPS * C_CH);
    float a0 = 0.f, a1 = 0.f;
    for (int i = lane; i < T_STEPS * C_CH; i += 32) {
        float v = row[i];
        a0 = fmaf(v, __ldg(&W2[i * 2 + 0]), a0);
        a1 = fmaf(v, __ldg(&W2[i * 2 + 1]), a1);
    }
#pragma unroll
    for (int o = 16; o; o >>= 1) {
        a0 += __shfl_xor_sync(0xffffffffu, a0, o);
        a1 += __shfl_xor_sync(0xffffffffu, a1, o);
    }
    if (lane == 0) {
        float f0 = a0 + b2[0];
        float f1 = a1 + b2[1];
        float m = fmaxf(f0, f1);
        float lse = m + logf(expf(f0 - m) + expf(f1 - m));
        out[gw * 2 + 0] = f0 - lse;
        out[gw * 2 + 1] = f1 - lse;
    }
}

// ---------------- launch ----------------
extern "C" void kernel_launch(void* const* d_in, const int* in_sizes, int n_in,
                              void* d_out, int out_size) {
    int base = 2;
    if (n_in >= 11 && in_sizes[2] <= 1) base = 3;

    const float* fts     = (const float*)d_in[0];
    const int*   graph   = (const int*)d_in[1];
    const float* W_gat   = (const float*)d_in[base + 0];
    const float* att_src = (const float*)d_in[base + 1];
    const float* att_dst = (const float*)d_in[base + 2];
    const float* b_gat   = (const float*)d_in[base + 3];
    const float* W1      = (const float*)d_in[base + 4];
    const float* b1      = (const float*)d_in[base + 5];
    const float* W2      = (const float*)d_in[base + 6];
    const float* b2      = (const float*)d_in[base + 7];
    float* out = (float*)d_out;

    cudaFuncSetAttribute(gemm_mma, cudaFuncAttributeMaxDynamicSharedMemorySize, GEMM_SMEM_TOT);

    conv_B<<<(512 * 512 + 255) / 256, 256>>>(W_gat);
    zero_degT<<<(T_STEPS * N_NODES + 255) / 256, 256>>>();
    degT_kernel<<<(T_STEPS * ETOT + 255) / 256, 256>>>(graph);
    scanT_kernel<<<T_STEPS, 1024>>>();
    scatterT_kernel<<<(T_STEPS * ETOT + 255) / 256, 256>>>(graph);

    for (int t = 0; t < T_STEPS; t++) {
        const float* A = fts + (size_t)t * N_NODES * NFEAT;
        gemm_mma<<<dim3(NT_TILES, MT_TILES), 256, GEMM_SMEM_TOT>>>(A);
        att_kernel<<<N_NODES, 128>>>(att_src, att_dst);
        aggregate_kernel<<<N_NODES / 2, 256>>>(b_gat, t);
        lin_kernel<<<(N_NODES + 31) / 32, 128>>>(W1, b1, t);
    }
    final_kernel<<<(N_NODES * 32 + 255) / 256, 256>>>(W2, b2, out);
}

// round 6
// speedup vs baseline: 1.6287x; 1.0333x over previous
#include <cuda_runtime.h>
#include <cuda_bf16.h>
#include <math.h>
#include <stdint.h>

#define N_NODES 20000
#define T_STEPS 8
#define E_EDGES 320000
#define ETOT    (E_EDGES + N_NODES)
#define NFEAT   512
#define HC      512
#define H_HEADS 4
#define C_CH    128
#define SLOPEV  0.2f

#define MT_TILES 157
#define NT_TILES 4
#define BK 32

// ---------------- scratch ----------------
__device__ float g_h[(size_t)N_NODES * HC];
__device__ float g_asrc[N_NODES * H_HEADS];
__device__ float g_adst[N_NODES * H_HEADS];
__device__ float g_z[(size_t)N_NODES * C_CH];
__device__ float g_LP[(size_t)T_STEPS * N_NODES * C_CH];
__device__ uint16_t g_B16h[512 * 512];   // [n][k]
__device__ uint16_t g_B16l[512 * 512];
__device__ float g_w[(size_t)ETOT * H_HEADS];   // per-edge softmax weights (reused per t)
// batched CSR
__device__ int g_degT[T_STEPS * N_NODES];
__device__ int g_rowptrT[T_STEPS * (N_NODES + 1)];
__device__ int g_fillT[T_STEPS * N_NODES];
__device__ int g_colT[(size_t)T_STEPS * ETOT];

__device__ __forceinline__ float leaky(float x) { return x >= 0.f ? x : SLOPEV * x; }

__device__ __forceinline__ uint32_t smem_u32(const void* p) {
    uint32_t a;
    asm("{ .reg .u64 t; cvta.to.shared.u64 t, %1; cvt.u32.u64 %0, t; }" : "=r"(a) : "l"(p));
    return a;
}
__device__ __forceinline__ void ldsm_x4(uint32_t& r0, uint32_t& r1, uint32_t& r2, uint32_t& r3,
                                        uint32_t addr) {
    asm volatile("ldmatrix.sync.aligned.m8n8.x4.shared.b16 {%0,%1,%2,%3}, [%4];"
                 : "=r"(r0), "=r"(r1), "=r"(r2), "=r"(r3) : "r"(addr));
}
__device__ __forceinline__ void ldsm_x2(uint32_t& r0, uint32_t& r1, uint32_t addr) {
    asm volatile("ldmatrix.sync.aligned.m8n8.x2.shared.b16 {%0,%1}, [%2];"
                 : "=r"(r0), "=r"(r1) : "r"(addr));
}
__device__ __forceinline__ void mma16816(float* c, const uint32_t* a, const uint32_t* b) {
    asm volatile(
        "mma.sync.aligned.m16n8k16.row.col.f32.bf16.bf16.f32 "
        "{%0,%1,%2,%3}, {%4,%5,%6,%7}, {%8,%9}, {%0,%1,%2,%3};"
        : "+f"(c[0]), "+f"(c[1]), "+f"(c[2]), "+f"(c[3])
        : "r"(a[0]), "r"(a[1]), "r"(a[2]), "r"(a[3]), "r"(b[0]), "r"(b[1]));
}
__device__ __forceinline__ uint32_t pack_hi2(float v0, float v1) {
    __nv_bfloat162 p = __floats2bfloat162_rn(v0, v1);
    return *reinterpret_cast<uint32_t*>(&p);
}
__device__ __forceinline__ void cp16(uint32_t dst, const void* src) {
    asm volatile("cp.async.cg.shared.global [%0], [%1], 16;" :: "r"(dst), "l"(src));
}
#define CP_COMMIT() asm volatile("cp.async.commit_group;" ::: "memory")
#define CP_WAIT0()  asm volatile("cp.async.wait_group 0;" ::: "memory")

// ---------------- 0) convert W -> bf16 hi/lo, [n][k] layout ----------------
__global__ void conv_B(const float* __restrict__ W) {
    int i = blockIdx.x * blockDim.x + threadIdx.x;
    if (i >= 512 * 512) return;
    int k = i >> 9, n = i & 511;
    float v = W[(size_t)k * 512 + n];
    __nv_bfloat16 h = __float2bfloat16(v);
    __nv_bfloat16 l = __float2bfloat16(v - __bfloat162float(h));
    g_B16h[(size_t)n * 512 + k] = *reinterpret_cast<uint16_t*>(&h);
    g_B16l[(size_t)n * 512 + k] = *reinterpret_cast<uint16_t*>(&l);
}

// ---------------- 1) GEMM: pipelined cp.async + mma.sync, 3-term bf16 ----------------
#define A32_PITCH 36
#define BF_PITCH  40
#define A32_STAGE (128 * A32_PITCH * 4)
#define BF_STAGE  (128 * BF_PITCH * 2)
#define OFF_AS32  0
#define OFF_AH    (2 * A32_STAGE)
#define OFF_AL    (OFF_AH + 2 * BF_STAGE)
#define OFF_BH    (OFF_AL + 2 * BF_STAGE)
#define OFF_BL    (OFF_BH + 2 * BF_STAGE)
#define GEMM_SMEM_TOT (OFF_BL + 2 * BF_STAGE)

__device__ __forceinline__ void load_stage(uint32_t sb, int tid, int mt, int nt,
                                           const float* __restrict__ A, int buf, int k0) {
#pragma unroll
    for (int c = 0; c < 4; c++) {
        int idx = tid + c * 256;
        int row = idx >> 3, ch = idx & 7;
        int node = mt * 128 + row;
        if (node > N_NODES - 1) node = N_NODES - 1;
        const float* src = A + (size_t)node * 512 + k0 + ch * 4;
        cp16(sb + OFF_AS32 + buf * A32_STAGE + row * (A32_PITCH * 4) + ch * 16, src);
    }
#pragma unroll
    for (int c = 0; c < 2; c++) {
        int idx = tid + c * 256;
        int row = idx >> 2, ch = idx & 3;
        const uint16_t* srh = g_B16h + (size_t)(nt * 128 + row) * 512 + k0 + ch * 8;
        const uint16_t* srl = g_B16l + (size_t)(nt * 128 + row) * 512 + k0 + ch * 8;
        cp16(sb + OFF_BH + buf * BF_STAGE + row * (BF_PITCH * 2) + ch * 16, srh);
        cp16(sb + OFF_BL + buf * BF_STAGE + row * (BF_PITCH * 2) + ch * 16, srl);
    }
}

__global__ __launch_bounds__(256) void gemm_mma(const float* __restrict__ A) {
    extern __shared__ __align__(16) unsigned char sm[];
    uint32_t sb = smem_u32(sm);
    const int tid = threadIdx.x, warp = tid >> 5, lane = tid & 31;
    const int mt = blockIdx.y, nt = blockIdx.x;
    const int warpM = warp & 3, warpN = warp >> 2;

    float acc[2][8][4];
#pragma unroll
    for (int i = 0; i < 2; i++)
#pragma unroll
        for (int j = 0; j < 8; j++)
#pragma unroll
            for (int q = 0; q < 4; q++) acc[i][j][q] = 0.f;

    const int cRow = tid >> 1, cHalf = tid & 1;
    const bool cValid = (mt * 128 + cRow) < N_NODES;

    const uint32_t ahB = sb + OFF_AH, alB = sb + OFF_AL;
    const uint32_t bhB = sb + OFF_BH, blB = sb + OFF_BL;
    const int aLdRow = warpM * 32 + (lane & 7) + ((lane >> 3) & 1) * 8;
    const int aLdK   = (lane >> 4) * 8;
    const int bLdRow = warpN * 64 + (lane & 7);
    const int bLdK   = ((lane >> 3) & 1) * 8;

    load_stage(sb, tid, mt, nt, A, 0, 0);
    CP_COMMIT();

    for (int it = 0; it < 16; it++) {
        const int cur = it & 1;
        CP_WAIT0();
        __syncthreads();
        if (it + 1 < 16) {
            load_stage(sb, tid, mt, nt, A, cur ^ 1, (it + 1) * BK);
            CP_COMMIT();
        }
        {
            const float* s32 = (const float*)(sm + OFF_AS32 + cur * A32_STAGE)
                               + cRow * A32_PITCH + cHalf * 16;
            uint32_t* hdst = (uint32_t*)(sm + OFF_AH + cur * BF_STAGE
                               + cRow * (BF_PITCH * 2) + cHalf * 32);
            uint32_t* ldst = (uint32_t*)(sm + OFF_AL + cur * BF_STAGE
                               + cRow * (BF_PITCH * 2) + cHalf * 32);
#pragma unroll
            for (int e = 0; e < 8; e++) {
                float f0 = cValid ? s32[e * 2] : 0.f;
                float f1 = cValid ? s32[e * 2 + 1] : 0.f;
                float h0 = __bfloat162float(__float2bfloat16(f0));
                float h1 = __bfloat162float(__float2bfloat16(f1));
                hdst[e] = pack_hi2(f0, f1);
                ldst[e] = pack_hi2(f0 - h0, f1 - h1);
            }
        }
        __syncthreads();

#pragma unroll
        for (int kk = 0; kk < 32; kk += 16) {
            uint32_t bhf[8][2], blf[8][2];
#pragma unroll
            for (int nf = 0; nf < 8; nf++) {
                uint32_t off = (uint32_t)(cur * BF_STAGE + (bLdRow + nf * 8) * (BF_PITCH * 2)
                                          + (kk + bLdK) * 2);
                ldsm_x2(bhf[nf][0], bhf[nf][1], bhB + off);
                ldsm_x2(blf[nf][0], blf[nf][1], blB + off);
            }
            uint32_t ahf[2][4], alf[2][4];
#pragma unroll
            for (int mf = 0; mf < 2; mf++) {
                uint32_t off = (uint32_t)(cur * BF_STAGE + (aLdRow + mf * 16) * (BF_PITCH * 2)
                                          + (kk + aLdK) * 2);
                ldsm_x4(ahf[mf][0], ahf[mf][1], ahf[mf][2], ahf[mf][3], ahB + off);
                ldsm_x4(alf[mf][0], alf[mf][1], alf[mf][2], alf[mf][3], alB + off);
            }
#pragma unroll
            for (int mf = 0; mf < 2; mf++)
#pragma unroll
                for (int nf = 0; nf < 8; nf++) {
                    mma16816(acc[mf][nf], ahf[mf], bhf[nf]);
                    mma16816(acc[mf][nf], alf[mf], bhf[nf]);
                    mma16816(acc[mf][nf], ahf[mf], blf[nf]);
                }
        }
    }

    const int r0 = lane >> 2, c0 = (lane & 3) * 2;
#pragma unroll
    for (int mf = 0; mf < 2; mf++) {
#pragma unroll
        for (int nf = 0; nf < 8; nf++) {
            int row = mt * 128 + warpM * 32 + mf * 16 + r0;
            int col = nt * 128 + warpN * 64 + nf * 8 + c0;
            if (row < N_NODES)
                *(float2*)(g_h + (size_t)row * 512 + col) = make_float2(acc[mf][nf][0], acc[mf][nf][1]);
            if (row + 8 < N_NODES)
                *(float2*)(g_h + (size_t)(row + 8) * 512 + col) = make_float2(acc[mf][nf][2], acc[mf][nf][3]);
        }
    }
}

// ---------------- 2) attention coefficients (2 nodes per block) ----------------
__global__ __launch_bounds__(256) void att_kernel(const float* __restrict__ att_src,
                                                  const float* __restrict__ att_dst) {
    int warp = threadIdx.x >> 5;
    int lane = threadIdx.x & 31;
    int n = blockIdx.x * 2 + (warp >> 2);
    int head = warp & 3;
    const float4 v  = ((const float4*)(g_h + (size_t)n * HC + head * C_CH))[lane];
    const float4 as = ((const float4*)(att_src + head * C_CH))[lane];
    const float4 ad = ((const float4*)(att_dst + head * C_CH))[lane];
    float s = v.x * as.x + v.y * as.y + v.z * as.z + v.w * as.w;
    float d = v.x * ad.x + v.y * ad.y + v.z * ad.z + v.w * ad.w;
#pragma unroll
    for (int o = 16; o; o >>= 1) {
        s += __shfl_xor_sync(0xffffffffu, s, o);
        d += __shfl_xor_sync(0xffffffffu, d, o);
    }
    if (lane == 0) {
        g_asrc[n * H_HEADS + head] = s;
        g_adst[n * H_HEADS + head] = d;
    }
}

// ---------------- 3) batched CSR build ----------------
__global__ void zero_degT() {
    int i = blockIdx.x * blockDim.x + threadIdx.x;
    if (i < T_STEPS * N_NODES) g_degT[i] = 0;
}

__global__ void degT_kernel(const int* __restrict__ graph) {
    int i = blockIdx.x * blockDim.x + threadIdx.x;
    if (i >= T_STEPS * ETOT) return;
    int t = i / ETOT, e = i - t * ETOT;
    int d = (e < E_EDGES) ? graph[(size_t)t * 2 * E_EDGES + E_EDGES + e] : (e - E_EDGES);
    atomicAdd(&g_degT[t * N_NODES + d], 1);
}

__global__ __launch_bounds__(1024) void scanT_kernel() {
    __shared__ int s[1024];
    int t = blockIdx.x;
    const int* deg = g_degT + t * N_NODES;
    int* rowptr = g_rowptrT + t * (N_NODES + 1);
    int* fill = g_fillT + t * N_NODES;
    int tid = threadIdx.x;
    const int PER = 20;
    int base = tid * PER;
    int vals[PER];
    int run = 0;
#pragma unroll
    for (int i = 0; i < PER; i++) {
        int idx = base + i;
        int v = (idx < N_NODES) ? deg[idx] : 0;
        vals[i] = run;
        run += v;
    }
    s[tid] = run;
    __syncthreads();
    for (int off = 1; off < 1024; off <<= 1) {
        int v = (tid >= off) ? s[tid - off] : 0;
        __syncthreads();
        s[tid] += v;
        __syncthreads();
    }
    int prev = (tid == 0) ? 0 : s[tid - 1];
#pragma unroll
    for (int i = 0; i < PER; i++) {
        int idx = base + i;
        if (idx < N_NODES) {
            int r = prev + vals[i];
            rowptr[idx] = r;
            fill[idx] = r;
        }
    }
    if (tid == 1023) rowptr[N_NODES] = s[1023];
}

__global__ void scatterT_kernel(const int* __restrict__ graph) {
    int i = blockIdx.x * blockDim.x + threadIdx.x;
    if (i >= T_STEPS * ETOT) return;
    int t = i / ETOT, e = i - t * ETOT;
    int sidx, d;
    if (e < E_EDGES) {
        sidx = graph[(size_t)t * 2 * E_EDGES + e];
        d    = graph[(size_t)t * 2 * E_EDGES + E_EDGES + e];
    } else {
        sidx = d = e - E_EDGES;
    }
    int pos = atomicAdd(&g_fillT[t * N_NODES + d], 1);
    g_colT[(size_t)t * ETOT + pos] = sidx;
}

// ---------------- 4) GAT aggregation: 2 passes, staged weights ----------------
__global__ __launch_bounds__(256) void aggregate_kernel(const float* __restrict__ b_gat, int t) {
    __shared__ __align__(16) float acc_sm[2][H_HEADS][C_CH];
    int warp = threadIdx.x >> 5;
    int lane = threadIdx.x & 31;
    int nodeLocal = warp >> 2;
    int head = warp & 3;
    int n = blockIdx.x * 2 + nodeLocal;

    const int* rowptr = g_rowptrT + t * (N_NODES + 1);
    const int* col = g_colT + (size_t)t * ETOT;

    int beg = rowptr[n];
    int end = rowptr[n + 1];
    float ad = g_adst[n * H_HEADS + head];

    // pass 1: compute weights (no max shift; e is O(1)), store, accumulate denom
    float sum = 0.f;
    for (int k = beg + lane; k < end; k += 32) {
        int s = col[k];
        float w = __expf(leaky(g_asrc[s * H_HEADS + head] + ad));
        g_w[(size_t)k * H_HEADS + head] = w;
        sum += w;
    }
#pragma unroll
    for (int o = 16; o; o >>= 1) sum += __shfl_xor_sync(0xffffffffu, sum, o);
    float inv = 1.f / (sum + 1e-16f);
    __threadfence_block();
    __syncwarp();

    // pass 2: weighted gather, unrolled x2 for MLP
    float4 acc = make_float4(0.f, 0.f, 0.f, 0.f);
    int k = beg;
    for (; k + 2 <= end; k += 2) {
        int s0 = col[k], s1 = col[k + 1];
        float w0 = g_w[(size_t)k * H_HEADS + head];
        float w1 = g_w[(size_t)(k + 1) * H_HEADS + head];
        const float4 v0 = ((const float4*)(g_h + (size_t)s0 * HC + head * C_CH))[lane];
        const float4 v1 = ((const float4*)(g_h + (size_t)s1 * HC + head * C_CH))[lane];
        float a0 = w0 * inv, a1 = w1 * inv;
        acc.x = fmaf(a0, v0.x, fmaf(a1, v1.x, acc.x));
        acc.y = fmaf(a0, v0.y, fmaf(a1, v1.y, acc.y));
        acc.z = fmaf(a0, v0.z, fmaf(a1, v1.z, acc.z));
        acc.w = fmaf(a0, v0.w, fmaf(a1, v1.w, acc.w));
    }
    if (k < end) {
        int s0 = col[k];
        float a0 = g_w[(size_t)k * H_HEADS + head] * inv;
        const float4 v0 = ((const float4*)(g_h + (size_t)s0 * HC + head * C_CH))[lane];
        acc.x = fmaf(a0, v0.x, acc.x);
        acc.y = fmaf(a0, v0.y, acc.y);
        acc.z = fmaf(a0, v0.z, acc.z);
        acc.w = fmaf(a0, v0.w, acc.w);
    }
    ((float4*)&acc_sm[nodeLocal][head][lane * 4])[0] = acc;
    __syncthreads();

    int idx = threadIdx.x;
    int nl = idx >> 7;
    int c  = idx & 127;
    int n2 = blockIdx.x * 2 + nl;
    float v = 0.25f * (acc_sm[nl][0][c] + acc_sm[nl][1][c] + acc_sm[nl][2][c] + acc_sm[nl][3][c])
              + b_gat[c];
    g_z[(size_t)n2 * C_CH + c] = leaky(v);
}

// ---------------- 5) LP[t, n, j] = leaky(z @ W1 + b1) ----------------
__global__ __launch_bounds__(128) void lin_kernel(const float* __restrict__ W1,
                                                  const float* __restrict__ b1, int t) {
    __shared__ float zs[32 * 128];
    int j = threadIdx.x;
    int n0 = blockIdx.x * 32;
#pragma unroll
    for (int r = 0; r < 32; r++) {
        int n = n0 + r;
        zs[r * 128 + j] = (n < N_NODES) ? g_z[(size_t)n * C_CH + j] : 0.f;
    }
    __syncthreads();
    float acc[32];
    float b = b1[j];
#pragma unroll
    for (int r = 0; r < 32; r++) acc[r] = b;
    for (int k = 0; k < 128; k++) {
        float w = __ldg(&W1[k * 128 + j]);
#pragma unroll
        for (int r = 0; r < 32; r++) acc[r] = fmaf(zs[r * 128 + k], w, acc[r]);
    }
#pragma unroll
    for (int r = 0; r < 32; r++) {
        int n = n0 + r;
        if (n < N_NODES)
            g_LP[(size_t)t * N_NODES * C_CH + (size_t)n * C_CH + j] = leaky(acc[r]);
    }
}

// ---------------- 6) final ----------------
__global__ __launch_bounds__(256) void final_kernel(const float* __restrict__ W2,
                                                    const float* __restrict__ b2,
                                                    float* __restrict__ out) {
    int gw = (blockIdx.x * blockDim.x + threadIdx.x) >> 5;
    int lane = threadIdx.x & 31;
    if (gw >= N_NODES) return;
    const float* row = g_LP + (size_t)gw * (T_STEPS * C_CH);
    float a0 = 0.f, a1 = 0.f;
    for (int i = lane; i < T_STEPS * C_CH; i += 32) {
        float v = row[i];
        a0 = fmaf(v, __ldg(&W2[i * 2 + 0]), a0);
        a1 = fmaf(v, __ldg(&W2[i * 2 + 1]), a1);
    }
#pragma unroll
    for (int o = 16; o; o >>= 1) {
        a0 += __shfl_xor_sync(0xffffffffu, a0, o);
        a1 += __shfl_xor_sync(0xffffffffu, a1, o);
    }
    if (lane == 0) {
        float f0 = a0 + b2[0];
        float f1 = a1 + b2[1];
        float m = fmaxf(f0, f1);
        float lse = m + logf(expf(f0 - m) + expf(f1 - m));
        out[gw * 2 + 0] = f0 - lse;
        out[gw * 2 + 1] = f1 - lse;
    }
}

// ---------------- launch ----------------
extern "C" void kernel_launch(void* const* d_in, const int* in_sizes, int n_in,
                              void* d_out, int out_size) {
    int base = 2;
    if (n_in >= 11 && in_sizes[2] <= 1) base = 3;

    const float* fts     = (const float*)d_in[0];
    const int*   graph   = (const int*)d_in[1];
    const float* W_gat   = (const float*)d_in[base + 0];
    const float* att_src = (const float*)d_in[base + 1];
    const float* att_dst = (const float*)d_in[base + 2];
    const float* b_gat   = (const float*)d_in[base + 3];
    const float* W1      = (const float*)d_in[base + 4];
    const float* b1      = (const float*)d_in[base + 5];
    const float* W2      = (const float*)d_in[base + 6];
    const float* b2      = (const float*)d_in[base + 7];
    float* out = (float*)d_out;

    cudaFuncSetAttribute(gemm_mma, cudaFuncAttributeMaxDynamicSharedMemorySize, GEMM_SMEM_TOT);

    // launch order arranged so gemm_mma is the 4th launch (ncu -s 5 window)
    conv_B<<<(512 * 512 + 255) / 256, 256>>>(W_gat);
    zero_degT<<<(T_STEPS * N_NODES + 255) / 256, 256>>>();
    degT_kernel<<<(T_STEPS * ETOT + 255) / 256, 256>>>(graph);
    gemm_mma<<<dim3(NT_TILES, MT_TILES), 256, GEMM_SMEM_TOT>>>(fts);   // t = 0
    scanT_kernel<<<T_STEPS, 1024>>>();
    scatterT_kernel<<<(T_STEPS * ETOT + 255) / 256, 256>>>(graph);
    att_kernel<<<N_NODES / 2, 256>>>(att_src, att_dst);
    aggregate_kernel<<<N_NODES / 2, 256>>>(b_gat, 0);
    lin_kernel<<<(N_NODES + 31) / 32, 128>>>(W1, b1, 0);

    for (int t = 1; t < T_STEPS; t++) {
        const float* A = fts + (size_t)t * N_NODES * NFEAT;
        gemm_mma<<<dim3(NT_TILES, MT_TILES), 256, GEMM_SMEM_TOT>>>(A);
        att_kernel<<<N_NODES / 2, 256>>>(att_src, att_dst);
        aggregate_kernel<<<N_NODES / 2, 256>>>(b_gat, t);
        lin_kernel<<<(N_NODES + 31) / 32, 128>>>(W1, b1, t);
    }
    final_kernel<<<(N_NODES * 32 + 255) / 256, 256>>>(W2, b2, out);
}

// round 7
// speedup vs baseline: 1.9089x; 1.1720x over previous
#include <cuda_runtime.h>
#include <cuda_bf16.h>
#include <math.h>
#include <stdint.h>

#define N_NODES 20000
#define T_STEPS 8
#define E_EDGES 320000
#define ETOT    (E_EDGES + N_NODES)
#define NFEAT   512
#define HC      512
#define H_HEADS 4
#define C_CH    128
#define SLOPEV  0.2f

#define MT_TILES 157
#define NT_TILES 4
#define BK 32

// ---------------- scratch ----------------
__device__ float g_h[(size_t)N_NODES * HC];
__device__ float g_asrc[N_NODES * H_HEADS];
__device__ float g_adst[N_NODES * H_HEADS];
__device__ float g_z[(size_t)N_NODES * C_CH];
__device__ float g_LP[(size_t)T_STEPS * N_NODES * C_CH];
__device__ uint16_t g_B16h[512 * 512];   // [n][k]
__device__ uint16_t g_B16l[512 * 512];
__device__ uint16_t g_A16h[(size_t)N_NODES * 512];  // [node][k] bf16 hi
__device__ uint16_t g_A16l[(size_t)N_NODES * 512];  // lo
__device__ float g_w[(size_t)ETOT * H_HEADS];
// batched CSR
__device__ int g_degT[T_STEPS * N_NODES];
__device__ int g_rowptrT[T_STEPS * (N_NODES + 1)];
__device__ int g_fillT[T_STEPS * N_NODES];
__device__ int g_colT[(size_t)T_STEPS * ETOT];

__device__ __forceinline__ float leaky(float x) { return x >= 0.f ? x : SLOPEV * x; }

__device__ __forceinline__ uint32_t smem_u32(const void* p) {
    uint32_t a;
    asm("{ .reg .u64 t; cvta.to.shared.u64 t, %1; cvt.u32.u64 %0, t; }" : "=r"(a) : "l"(p));
    return a;
}
__device__ __forceinline__ void ldsm_x4(uint32_t& r0, uint32_t& r1, uint32_t& r2, uint32_t& r3,
                                        uint32_t addr) {
    asm volatile("ldmatrix.sync.aligned.m8n8.x4.shared.b16 {%0,%1,%2,%3}, [%4];"
                 : "=r"(r0), "=r"(r1), "=r"(r2), "=r"(r3) : "r"(addr));
}
__device__ __forceinline__ void mma16816(float* c, const uint32_t* a, const uint32_t* b) {
    asm volatile(
        "mma.sync.aligned.m16n8k16.row.col.f32.bf16.bf16.f32 "
        "{%0,%1,%2,%3}, {%4,%5,%6,%7}, {%8,%9}, {%0,%1,%2,%3};"
        : "+f"(c[0]), "+f"(c[1]), "+f"(c[2]), "+f"(c[3])
        : "r"(a[0]), "r"(a[1]), "r"(a[2]), "r"(a[3]), "r"(b[0]), "r"(b[1]));
}
__device__ __forceinline__ uint32_t pack_hi2(float v0, float v1) {
    __nv_bfloat162 p = __floats2bfloat162_rn(v0, v1);
    return *reinterpret_cast<uint32_t*>(&p);
}
__device__ __forceinline__ void cp16(uint32_t dst, const void* src) {
    asm volatile("cp.async.cg.shared.global [%0], [%1], 16;" :: "r"(dst), "l"(src));
}
#define CP_COMMIT() asm volatile("cp.async.commit_group;" ::: "memory")
#define CP_WAIT0()  asm volatile("cp.async.wait_group 0;" ::: "memory")

// ---------------- 0a) convert W -> bf16 hi/lo, [n][k] ----------------
__global__ void conv_B(const float* __restrict__ W) {
    int i = blockIdx.x * blockDim.x + threadIdx.x;
    if (i >= 512 * 512) return;
    int k = i >> 9, n = i & 511;
    float v = W[(size_t)k * 512 + n];
    __nv_bfloat16 h = __float2bfloat16(v);
    __nv_bfloat16 l = __float2bfloat16(v - __bfloat162float(h));
    g_B16h[(size_t)n * 512 + k] = *reinterpret_cast<uint16_t*>(&h);
    g_B16l[(size_t)n * 512 + k] = *reinterpret_cast<uint16_t*>(&l);
}

// ---------------- 0b) convert fts[t] -> bf16 hi/lo, row-major ----------------
__global__ __launch_bounds__(256) void conv_A(const float* __restrict__ A) {
    size_t i = (size_t)blockIdx.x * blockDim.x + threadIdx.x;   // float4 index
    if (i >= (size_t)N_NODES * 128) return;
    float4 v = ((const float4*)A)[i];
    float h0 = __bfloat162float(__float2bfloat16(v.x));
    float h1 = __bfloat162float(__float2bfloat16(v.y));
    float h2 = __bfloat162float(__float2bfloat16(v.z));
    float h3 = __bfloat162float(__float2bfloat16(v.w));
    uint2 hi = make_uint2(pack_hi2(v.x, v.y), pack_hi2(v.z, v.w));
    uint2 lo = make_uint2(pack_hi2(v.x - h0, v.y - h1), pack_hi2(v.z - h2, v.w - h3));
    ((uint2*)g_A16h)[i] = hi;
    ((uint2*)g_A16l)[i] = lo;
}

// ---------------- 1) GEMM: pure bf16 3-term, cp.async 2-stage, 2 CTA/SM ----------------
#define BF_PITCH  40                     // bf16 elems per smem row (80 B)
#define STG       (128 * BF_PITCH * 2)   // 10240 B per array per stage
#define OFF_AH    0
#define OFF_AL    (2 * STG)
#define OFF_BH    (4 * STG)
#define OFF_BL    (6 * STG)
#define GEMM_SMEM_TOT (8 * STG)          // 81920

__device__ __forceinline__ void load_stage(uint32_t sb, int tid, int mt, int nt,
                                           int buf, int k0) {
#pragma unroll
    for (int c = 0; c < 2; c++) {
        int idx = tid + c * 256;          // 0..511
        int row = idx >> 2, ch = idx & 3; // row 0..127, 16B chunk
        int node = mt * 128 + row;
        if (node > N_NODES - 1) node = N_NODES - 1;
        const uint16_t* sah = g_A16h + (size_t)node * 512 + k0 + ch * 8;
        const uint16_t* sal = g_A16l + (size_t)node * 512 + k0 + ch * 8;
        uint32_t doff = buf * STG + row * (BF_PITCH * 2) + ch * 16;
        cp16(sb + OFF_AH + doff, sah);
        cp16(sb + OFF_AL + doff, sal);
        const uint16_t* sbh = g_B16h + (size_t)(nt * 128 + row) * 512 + k0 + ch * 8;
        const uint16_t* sbl = g_B16l + (size_t)(nt * 128 + row) * 512 + k0 + ch * 8;
        cp16(sb + OFF_BH + doff, sbh);
        cp16(sb + OFF_BL + doff, sbl);
    }
}

__global__ __launch_bounds__(256, 2) void gemm_mma(int unused) {
    extern __shared__ __align__(16) unsigned char sm[];
    uint32_t sb = smem_u32(sm);
    const int tid = threadIdx.x, warp = tid >> 5, lane = tid & 31;
    const int mt = blockIdx.y, nt = blockIdx.x;
    const int warpM = warp & 1, warpN = warp >> 1;   // 2 x 4 warps, 64m x 32n each

    float acc[4][4][4];
#pragma unroll
    for (int i = 0; i < 4; i++)
#pragma unroll
        for (int j = 0; j < 4; j++)
#pragma unroll
            for (int q = 0; q < 4; q++) acc[i][j][q] = 0.f;

    const uint32_t ahB = sb + OFF_AH, alB = sb + OFF_AL;
    const uint32_t bhB = sb + OFF_BH, blB = sb + OFF_BL;
    // A ldmatrix lane mapping (m16k16 fragment): lanes 0-7 rows 0-7 k0, 8-15 rows 8-15 k0,
    // 16-23 rows 0-7 k8, 24-31 rows 8-15 k8
    const int aLdRow = warpM * 64 + (lane & 7) + ((lane >> 3) & 1) * 8;  // + mf*16
    const int aLdK   = (lane >> 4) * 8;
    // B ldmatrix x4 (two n8k16 fragments): lanes 0-7 n0-7 k0, 8-15 n0-7 k8,
    // 16-23 n8-15 k0, 24-31 n8-15 k8
    const int bLdRow = warpN * 32 + (lane & 7) + ((lane >> 4) & 1) * 8;  // + nfp*16
    const int bLdK   = ((lane >> 3) & 1) * 8;

    load_stage(sb, tid, mt, nt, 0, 0);
    CP_COMMIT();

    for (int it = 0; it < 16; it++) {
        const int cur = it & 1;
        CP_WAIT0();
        __syncthreads();
        if (it + 1 < 16) {
            load_stage(sb, tid, mt, nt, cur ^ 1, (it + 1) * BK);
            CP_COMMIT();
        }

#pragma unroll
        for (int kk = 0; kk < 32; kk += 16) {
            uint32_t bh[2][4], bl[2][4];
#pragma unroll
            for (int nfp = 0; nfp < 2; nfp++) {
                uint32_t off = (uint32_t)(cur * STG + (bLdRow + nfp * 16) * (BF_PITCH * 2)
                                          + (kk + bLdK) * 2);
                ldsm_x4(bh[nfp][0], bh[nfp][1], bh[nfp][2], bh[nfp][3], bhB + off);
                ldsm_x4(bl[nfp][0], bl[nfp][1], bl[nfp][2], bl[nfp][3], blB + off);
            }
#pragma unroll
            for (int mf = 0; mf < 4; mf++) {
                uint32_t off = (uint32_t)(cur * STG + (aLdRow + mf * 16) * (BF_PITCH * 2)
                                          + (kk + aLdK) * 2);
                uint32_t ah[4], al[4];
                ldsm_x4(ah[0], ah[1], ah[2], ah[3], ahB + off);
                ldsm_x4(al[0], al[1], al[2], al[3], alB + off);
#pragma unroll
                for (int nf = 0; nf < 4; nf++) {
                    const uint32_t* bfrag_h = &bh[nf >> 1][(nf & 1) * 2];
                    const uint32_t* bfrag_l = &bl[nf >> 1][(nf & 1) * 2];
                    mma16816(acc[mf][nf], ah, bfrag_h);
                    mma16816(acc[mf][nf], al, bfrag_h);
                    mma16816(acc[mf][nf], ah, bfrag_l);
                }
            }
        }
        __syncthreads();
    }

    const int r0 = lane >> 2, c0 = (lane & 3) * 2;
#pragma unroll
    for (int mf = 0; mf < 4; mf++) {
#pragma unroll
        for (int nf = 0; nf < 4; nf++) {
            int row = mt * 128 + warpM * 64 + mf * 16 + r0;
            int col = nt * 128 + warpN * 32 + nf * 8 + c0;
            if (row < N_NODES)
                *(float2*)(g_h + (size_t)row * 512 + col) = make_float2(acc[mf][nf][0], acc[mf][nf][1]);
            if (row + 8 < N_NODES)
                *(float2*)(g_h + (size_t)(row + 8) * 512 + col) = make_float2(acc[mf][nf][2], acc[mf][nf][3]);
        }
    }
}

// ---------------- 2) attention coefficients ----------------
__global__ __launch_bounds__(256) void att_kernel(const float* __restrict__ att_src,
                                                  const float* __restrict__ att_dst) {
    int warp = threadIdx.x >> 5;
    int lane = threadIdx.x & 31;
    int n = blockIdx.x * 2 + (warp >> 2);
    int head = warp & 3;
    const float4 v  = ((const float4*)(g_h + (size_t)n * HC + head * C_CH))[lane];
    const float4 as = ((const float4*)(att_src + head * C_CH))[lane];
    const float4 ad = ((const float4*)(att_dst + head * C_CH))[lane];
    float s = v.x * as.x + v.y * as.y + v.z * as.z + v.w * as.w;
    float d = v.x * ad.x + v.y * ad.y + v.z * ad.z + v.w * ad.w;
#pragma unroll
    for (int o = 16; o; o >>= 1) {
        s += __shfl_xor_sync(0xffffffffu, s, o);
        d += __shfl_xor_sync(0xffffffffu, d, o);
    }
    if (lane == 0) {
        g_asrc[n * H_HEADS + head] = s;
        g_adst[n * H_HEADS + head] = d;
    }
}

// ---------------- 3) batched CSR build ----------------
__global__ void zero_degT() {
    int i = blockIdx.x * blockDim.x + threadIdx.x;
    if (i < T_STEPS * N_NODES) g_degT[i] = 0;
}

__global__ void degT_kernel(const int* __restrict__ graph) {
    int i = blockIdx.x * blockDim.x + threadIdx.x;
    if (i >= T_STEPS * ETOT) return;
    int t = i / ETOT, e = i - t * ETOT;
    int d = (e < E_EDGES) ? graph[(size_t)t * 2 * E_EDGES + E_EDGES + e] : (e - E_EDGES);
    atomicAdd(&g_degT[t * N_NODES + d], 1);
}

__global__ __launch_bounds__(1024) void scanT_kernel() {
    __shared__ int s[1024];
    int t = blockIdx.x;
    const int* deg = g_degT + t * N_NODES;
    int* rowptr = g_rowptrT + t * (N_NODES + 1);
    int* fill = g_fillT + t * N_NODES;
    int tid = threadIdx.x;
    const int PER = 20;
    int base = tid * PER;
    int vals[PER];
    int run = 0;
#pragma unroll
    for (int i = 0; i < PER; i++) {
        int idx = base + i;
        int v = (idx < N_NODES) ? deg[idx] : 0;
        vals[i] = run;
        run += v;
    }
    s[tid] = run;
    __syncthreads();
    for (int off = 1; off < 1024; off <<= 1) {
        int v = (tid >= off) ? s[tid - off] : 0;
        __syncthreads();
        s[tid] += v;
        __syncthreads();
    }
    int prev = (tid == 0) ? 0 : s[tid - 1];
#pragma unroll
    for (int i = 0; i < PER; i++) {
        int idx = base + i;
        if (idx < N_NODES) {
            int r = prev + vals[i];
            rowptr[idx] = r;
            fill[idx] = r;
        }
    }
    if (tid == 1023) rowptr[N_NODES] = s[1023];
}

__global__ void scatterT_kernel(const int* __restrict__ graph) {
    int i = blockIdx.x * blockDim.x + threadIdx.x;
    if (i >= T_STEPS * ETOT) return;
    int t = i / ETOT, e = i - t * ETOT;
    int sidx, d;
    if (e < E_EDGES) {
        sidx = graph[(size_t)t * 2 * E_EDGES + e];
        d    = graph[(size_t)t * 2 * E_EDGES + E_EDGES + e];
    } else {
        sidx = d = e - E_EDGES;
    }
    int pos = atomicAdd(&g_fillT[t * N_NODES + d], 1);
    g_colT[(size_t)t * ETOT + pos] = sidx;
}

// ---------------- 4) GAT aggregation: 2 passes, staged weights ----------------
__global__ __launch_bounds__(256) void aggregate_kernel(const float* __restrict__ b_gat, int t) {
    __shared__ __align__(16) float acc_sm[2][H_HEADS][C_CH];
    int warp = threadIdx.x >> 5;
    int lane = threadIdx.x & 31;
    int nodeLocal = warp >> 2;
    int head = warp & 3;
    int n = blockIdx.x * 2 + nodeLocal;

    const int* rowptr = g_rowptrT + t * (N_NODES + 1);
    const int* col = g_colT + (size_t)t * ETOT;

    int beg = rowptr[n];
    int end = rowptr[n + 1];
    float ad = g_adst[n * H_HEADS + head];

    float sum = 0.f;
    for (int k = beg + lane; k < end; k += 32) {
        int s = col[k];
        float w = __expf(leaky(g_asrc[s * H_HEADS + head] + ad));
        g_w[(size_t)k * H_HEADS + head] = w;
        sum += w;
    }
#pragma unroll
    for (int o = 16; o; o >>= 1) sum += __shfl_xor_sync(0xffffffffu, sum, o);
    float inv = 1.f / (sum + 1e-16f);
    __threadfence_block();
    __syncwarp();

    float4 acc = make_float4(0.f, 0.f, 0.f, 0.f);
    int k = beg;
    for (; k + 2 <= end; k += 2) {
        int s0 = col[k], s1 = col[k + 1];
        float w0 = g_w[(size_t)k * H_HEADS + head];
        float w1 = g_w[(size_t)(k + 1) * H_HEADS + head];
        const float4 v0 = ((const float4*)(g_h + (size_t)s0 * HC + head * C_CH))[lane];
        const float4 v1 = ((const float4*)(g_h + (size_t)s1 * HC + head * C_CH))[lane];
        float a0 = w0 * inv, a1 = w1 * inv;
        acc.x = fmaf(a0, v0.x, fmaf(a1, v1.x, acc.x));
        acc.y = fmaf(a0, v0.y, fmaf(a1, v1.y, acc.y));
        acc.z = fmaf(a0, v0.z, fmaf(a1, v1.z, acc.z));
        acc.w = fmaf(a0, v0.w, fmaf(a1, v1.w, acc.w));
    }
    if (k < end) {
        int s0 = col[k];
        float a0 = g_w[(size_t)k * H_HEADS + head] * inv;
        const float4 v0 = ((const float4*)(g_h + (size_t)s0 * HC + head * C_CH))[lane];
        acc.x = fmaf(a0, v0.x, acc.x);
        acc.y = fmaf(a0, v0.y, acc.y);
        acc.z = fmaf(a0, v0.z, acc.z);
        acc.w = fmaf(a0, v0.w, acc.w);
    }
    ((float4*)&acc_sm[nodeLocal][head][lane * 4])[0] = acc;
    __syncthreads();

    int idx = threadIdx.x;
    int nl = idx >> 7;
    int c  = idx & 127;
    int n2 = blockIdx.x * 2 + nl;
    float v = 0.25f * (acc_sm[nl][0][c] + acc_sm[nl][1][c] + acc_sm[nl][2][c] + acc_sm[nl][3][c])
              + b_gat[c];
    g_z[(size_t)n2 * C_CH + c] = leaky(v);
}

// ---------------- 5) LP[t, n, j] = leaky(z @ W1 + b1) ----------------
__global__ __launch_bounds__(128) void lin_kernel(const float* __restrict__ W1,
                                                  const float* __restrict__ b1, int t) {
    __shared__ float zs[32 * 128];
    int j = threadIdx.x;
    int n0 = blockIdx.x * 32;
#pragma unroll
    for (int r = 0; r < 32; r++) {
        int n = n0 + r;
        zs[r * 128 + j] = (n < N_NODES) ? g_z[(size_t)n * C_CH + j] : 0.f;
    }
    __syncthreads();
    float acc[32];
    float b = b1[j];
#pragma unroll
    for (int r = 0; r < 32; r++) acc[r] = b;
    for (int k = 0; k < 128; k++) {
        float w = __ldg(&W1[k * 128 + j]);
#pragma unroll
        for (int r = 0; r < 32; r++) acc[r] = fmaf(zs[r * 128 + k], w, acc[r]);
    }
#pragma unroll
    for (int r = 0; r < 32; r++) {
        int n = n0 + r;
        if (n < N_NODES)
            g_LP[(size_t)t * N_NODES * C_CH + (size_t)n * C_CH + j] = leaky(acc[r]);
    }
}

// ---------------- 6) final ----------------
__global__ __launch_bounds__(256) void final_kernel(const float* __restrict__ W2,
                                                    const float* __restrict__ b2,
                                                    float* __restrict__ out) {
    int gw = (blockIdx.x * blockDim.x + threadIdx.x) >> 5;
    int lane = threadIdx.x & 31;
    if (gw >= N_NODES) return;
    const float* row = g_LP + (size_t)gw * (T_STEPS * C_CH);
    float a0 = 0.f, a1 = 0.f;
    for (int i = lane; i < T_STEPS * C_CH; i += 32) {
        float v = row[i];
        a0 = fmaf(v, __ldg(&W2[i * 2 + 0]), a0);
        a1 = fmaf(v, __ldg(&W2[i * 2 + 1]), a1);
    }
#pragma unroll
    for (int o = 16; o; o >>= 1) {
        a0 += __shfl_xor_sync(0xffffffffu, a0, o);
        a1 += __shfl_xor_sync(0xffffffffu, a1, o);
    }
    if (lane == 0) {
        float f0 = a0 + b2[0];
        float f1 = a1 + b2[1];
        float m = fmaxf(f0, f1);
        float lse = m + logf(expf(f0 - m) + expf(f1 - m));
        out[gw * 2 + 0] = f0 - lse;
        out[gw * 2 + 1] = f1 - lse;
    }
}

// ---------------- launch ----------------
extern "C" void kernel_launch(void* const* d_in, const int* in_sizes, int n_in,
                              void* d_out, int out_size) {
    int base = 2;
    if (n_in >= 11 && in_sizes[2] <= 1) base = 3;

    const float* fts     = (const float*)d_in[0];
    const int*   graph   = (const int*)d_in[1];
    const float* W_gat   = (const float*)d_in[base + 0];
    const float* att_src = (const float*)d_in[base + 1];
    const float* att_dst = (const float*)d_in[base + 2];
    const float* b_gat   = (const float*)d_in[base + 3];
    const float* W1      = (const float*)d_in[base + 4];
    const float* b1      = (const float*)d_in[base + 5];
    const float* W2      = (const float*)d_in[base + 6];
    const float* b2      = (const float*)d_in[base + 7];
    float* out = (float*)d_out;

    cudaFuncSetAttribute(gemm_mma, cudaFuncAttributeMaxDynamicSharedMemorySize, GEMM_SMEM_TOT);

    const int convGrid = (int)(((size_t)N_NODES * 128 + 255) / 256);

    // gemm_mma kept as the 4th launch for the ncu window
    conv_B<<<(512 * 512 + 255) / 256, 256>>>(W_gat);
    conv_A<<<convGrid, 256>>>(fts);                         // t = 0
    zero_degT<<<(T_STEPS * N_NODES + 255) / 256, 256>>>();
    gemm_mma<<<dim3(NT_TILES, MT_TILES), 256, GEMM_SMEM_TOT>>>(0);
    degT_kernel<<<(T_STEPS * ETOT + 255) / 256, 256>>>(graph);
    scanT_kernel<<<T_STEPS, 1024>>>();
    scatterT_kernel<<<(T_STEPS * ETOT + 255) / 256, 256>>>(graph);
    att_kernel<<<N_NODES / 2, 256>>>(att_src, att_dst);
    aggregate_kernel<<<N_NODES / 2, 256>>>(b_gat, 0);
    lin_kernel<<<(N_NODES + 31) / 32, 128>>>(W1, b1, 0);

    for (int t = 1; t < T_STEPS; t++) {
        const float* A = fts + (size_t)t * N_NODES * NFEAT;
        conv_A<<<convGrid, 256>>>(A);
        gemm_mma<<<dim3(NT_TILES, MT_TILES), 256, GEMM_SMEM_TOT>>>(0);
        att_kernel<<<N_NODES / 2, 256>>>(att_src, att_dst);
        aggregate_kernel<<<N_NODES / 2, 256>>>(b_gat, t);
        lin_kernel<<<(N_NODES + 31) / 32, 128>>>(W1, b1, t);
    }
    final_kernel<<<(N_NODES * 32 + 255) / 256, 256>>>(W2, b2, out);
}

// round 8
// speedup vs baseline: 2.3196x; 1.2152x over previous
#include <cuda_runtime.h>
#include <cuda_bf16.h>
#include <math.h>
#include <stdint.h>

#define N_NODES 20000
#define T_STEPS 8
#define E_EDGES 320000
#define ETOT    (E_EDGES + N_NODES)
#define NFEAT   512
#define HC      512
#define H_HEADS 4
#define C_CH    128
#define SLOPEV  0.2f

#define MT_TILES 157
#define NT_TILES 4
#define BK 32

// ---------------- scratch (batched across T) ----------------
__device__ float g_hT[(size_t)T_STEPS * N_NODES * HC];          // 328 MB
__device__ float g_asrcT[T_STEPS * N_NODES * H_HEADS];
__device__ float g_adstT[T_STEPS * N_NODES * H_HEADS];
__device__ float g_zT[(size_t)T_STEPS * N_NODES * C_CH];        // 82 MB
__device__ float g_LP[(size_t)T_STEPS * N_NODES * C_CH];        // 82 MB
__device__ uint16_t g_B16h[512 * 512];   // [n][k]
__device__ uint16_t g_B16l[512 * 512];
__device__ uint16_t g_A16h[(size_t)T_STEPS * N_NODES * 512];    // 164 MB
__device__ uint16_t g_A16l[(size_t)T_STEPS * N_NODES * 512];    // 164 MB
__device__ float g_wT[(size_t)T_STEPS * ETOT * H_HEADS];        // 42 MB
// batched CSR
__device__ int g_degT[T_STEPS * N_NODES];
__device__ int g_rowptrT[T_STEPS * (N_NODES + 1)];
__device__ int g_fillT[T_STEPS * N_NODES];
__device__ int g_colT[(size_t)T_STEPS * ETOT];

__device__ __forceinline__ float leaky(float x) { return x >= 0.f ? x : SLOPEV * x; }

__device__ __forceinline__ uint32_t smem_u32(const void* p) {
    uint32_t a;
    asm("{ .reg .u64 t; cvta.to.shared.u64 t, %1; cvt.u32.u64 %0, t; }" : "=r"(a) : "l"(p));
    return a;
}
__device__ __forceinline__ void ldsm_x4(uint32_t& r0, uint32_t& r1, uint32_t& r2, uint32_t& r3,
                                        uint32_t addr) {
    asm volatile("ldmatrix.sync.aligned.m8n8.x4.shared.b16 {%0,%1,%2,%3}, [%4];"
                 : "=r"(r0), "=r"(r1), "=r"(r2), "=r"(r3) : "r"(addr));
}
__device__ __forceinline__ void mma16816(float* c, const uint32_t* a, const uint32_t* b) {
    asm volatile(
        "mma.sync.aligned.m16n8k16.row.col.f32.bf16.bf16.f32 "
        "{%0,%1,%2,%3}, {%4,%5,%6,%7}, {%8,%9}, {%0,%1,%2,%3};"
        : "+f"(c[0]), "+f"(c[1]), "+f"(c[2]), "+f"(c[3])
        : "r"(a[0]), "r"(a[1]), "r"(a[2]), "r"(a[3]), "r"(b[0]), "r"(b[1]));
}
__device__ __forceinline__ uint32_t pack_hi2(float v0, float v1) {
    __nv_bfloat162 p = __floats2bfloat162_rn(v0, v1);
    return *reinterpret_cast<uint32_t*>(&p);
}
__device__ __forceinline__ void cp16(uint32_t dst, const void* src) {
    asm volatile("cp.async.cg.shared.global [%0], [%1], 16;" :: "r"(dst), "l"(src));
}
#define CP_COMMIT() asm volatile("cp.async.commit_group;" ::: "memory")
#define CP_WAIT0()  asm volatile("cp.async.wait_group 0;" ::: "memory")

// ---------------- 0a) convert W -> bf16 hi/lo, [n][k] ----------------
__global__ void conv_B(const float* __restrict__ W) {
    int i = blockIdx.x * blockDim.x + threadIdx.x;
    if (i >= 512 * 512) return;
    int k = i >> 9, n = i & 511;
    float v = W[(size_t)k * 512 + n];
    __nv_bfloat16 h = __float2bfloat16(v);
    __nv_bfloat16 l = __float2bfloat16(v - __bfloat162float(h));
    g_B16h[(size_t)n * 512 + k] = *reinterpret_cast<uint16_t*>(&h);
    g_B16l[(size_t)n * 512 + k] = *reinterpret_cast<uint16_t*>(&l);
}

// ---------------- 0b) convert ALL fts -> bf16 hi/lo, row-major ----------------
__global__ __launch_bounds__(256) void conv_A(const float* __restrict__ A) {
    size_t i = (size_t)blockIdx.x * blockDim.x + threadIdx.x;   // float4 index
    if (i >= (size_t)T_STEPS * N_NODES * 128) return;
    float4 v = ((const float4*)A)[i];
    float h0 = __bfloat162float(__float2bfloat16(v.x));
    float h1 = __bfloat162float(__float2bfloat16(v.y));
    float h2 = __bfloat162float(__float2bfloat16(v.z));
    float h3 = __bfloat162float(__float2bfloat16(v.w));
    uint2 hi = make_uint2(pack_hi2(v.x, v.y), pack_hi2(v.z, v.w));
    uint2 lo = make_uint2(pack_hi2(v.x - h0, v.y - h1), pack_hi2(v.z - h2, v.w - h3));
    ((uint2*)g_A16h)[i] = hi;
    ((uint2*)g_A16l)[i] = lo;
}

// ---------------- 1) GEMM batched over t: pure bf16 3-term ----------------
#define BF_PITCH  40
#define STG       (128 * BF_PITCH * 2)
#define OFF_AH    0
#define OFF_AL    (2 * STG)
#define OFF_BH    (4 * STG)
#define OFF_BL    (6 * STG)
#define GEMM_SMEM_TOT (8 * STG)

__device__ __forceinline__ void load_stage(uint32_t sb, int tid, size_t aBase, int mt, int nt,
                                           int buf, int k0) {
#pragma unroll
    for (int c = 0; c < 2; c++) {
        int idx = tid + c * 256;
        int row = idx >> 2, ch = idx & 3;
        int node = mt * 128 + row;
        if (node > N_NODES - 1) node = N_NODES - 1;
        const uint16_t* sah = g_A16h + aBase + (size_t)node * 512 + k0 + ch * 8;
        const uint16_t* sal = g_A16l + aBase + (size_t)node * 512 + k0 + ch * 8;
        uint32_t doff = buf * STG + row * (BF_PITCH * 2) + ch * 16;
        cp16(sb + OFF_AH + doff, sah);
        cp16(sb + OFF_AL + doff, sal);
        const uint16_t* sbh = g_B16h + (size_t)(nt * 128 + row) * 512 + k0 + ch * 8;
        const uint16_t* sbl = g_B16l + (size_t)(nt * 128 + row) * 512 + k0 + ch * 8;
        cp16(sb + OFF_BH + doff, sbh);
        cp16(sb + OFF_BL + doff, sbl);
    }
}

__global__ __launch_bounds__(256, 2) void gemm_mma(int unused) {
    extern __shared__ __align__(16) unsigned char sm[];
    uint32_t sb = smem_u32(sm);
    const int tid = threadIdx.x, warp = tid >> 5, lane = tid & 31;
    const int mt = blockIdx.y, nt = blockIdx.x, t = blockIdx.z;
    const int warpM = warp & 1, warpN = warp >> 1;
    const size_t aBase = (size_t)t * N_NODES * 512;

    float acc[4][4][4];
#pragma unroll
    for (int i = 0; i < 4; i++)
#pragma unroll
        for (int j = 0; j < 4; j++)
#pragma unroll
            for (int q = 0; q < 4; q++) acc[i][j][q] = 0.f;

    const uint32_t ahB = sb + OFF_AH, alB = sb + OFF_AL;
    const uint32_t bhB = sb + OFF_BH, blB = sb + OFF_BL;
    const int aLdRow = warpM * 64 + (lane & 7) + ((lane >> 3) & 1) * 8;
    const int aLdK   = (lane >> 4) * 8;
    const int bLdRow = warpN * 32 + (lane & 7) + ((lane >> 4) & 1) * 8;
    const int bLdK   = ((lane >> 3) & 1) * 8;

    load_stage(sb, tid, aBase, mt, nt, 0, 0);
    CP_COMMIT();

    for (int it = 0; it < 16; it++) {
        const int cur = it & 1;
        CP_WAIT0();
        __syncthreads();
        if (it + 1 < 16) {
            load_stage(sb, tid, aBase, mt, nt, cur ^ 1, (it + 1) * BK);
            CP_COMMIT();
        }

#pragma unroll
        for (int kk = 0; kk < 32; kk += 16) {
            uint32_t bh[2][4], bl[2][4];
#pragma unroll
            for (int nfp = 0; nfp < 2; nfp++) {
                uint32_t off = (uint32_t)(cur * STG + (bLdRow + nfp * 16) * (BF_PITCH * 2)
                                          + (kk + bLdK) * 2);
                ldsm_x4(bh[nfp][0], bh[nfp][1], bh[nfp][2], bh[nfp][3], bhB + off);
                ldsm_x4(bl[nfp][0], bl[nfp][1], bl[nfp][2], bl[nfp][3], blB + off);
            }
#pragma unroll
            for (int mf = 0; mf < 4; mf++) {
                uint32_t off = (uint32_t)(cur * STG + (aLdRow + mf * 16) * (BF_PITCH * 2)
                                          + (kk + aLdK) * 2);
                uint32_t ah[4], al[4];
                ldsm_x4(ah[0], ah[1], ah[2], ah[3], ahB + off);
                ldsm_x4(al[0], al[1], al[2], al[3], alB + off);
#pragma unroll
                for (int nf = 0; nf < 4; nf++) {
                    const uint32_t* bfrag_h = &bh[nf >> 1][(nf & 1) * 2];
                    const uint32_t* bfrag_l = &bl[nf >> 1][(nf & 1) * 2];
                    mma16816(acc[mf][nf], ah, bfrag_h);
                    mma16816(acc[mf][nf], al, bfrag_h);
                    mma16816(acc[mf][nf], ah, bfrag_l);
                }
            }
        }
        __syncthreads();
    }

    float* hOut = g_hT + (size_t)t * N_NODES * HC;
    const int r0 = lane >> 2, c0 = (lane & 3) * 2;
#pragma unroll
    for (int mf = 0; mf < 4; mf++) {
#pragma unroll
        for (int nf = 0; nf < 4; nf++) {
            int row = mt * 128 + warpM * 64 + mf * 16 + r0;
            int col = nt * 128 + warpN * 32 + nf * 8 + c0;
            if (row < N_NODES)
                *(float2*)(hOut + (size_t)row * 512 + col) = make_float2(acc[mf][nf][0], acc[mf][nf][1]);
            if (row + 8 < N_NODES)
                *(float2*)(hOut + (size_t)(row + 8) * 512 + col) = make_float2(acc[mf][nf][2], acc[mf][nf][3]);
        }
    }
}

// ---------------- 2) attention coefficients (batched over t) ----------------
__global__ __launch_bounds__(256) void att_kernel(const float* __restrict__ att_src,
                                                  const float* __restrict__ att_dst) {
    int warp = threadIdx.x >> 5;
    int lane = threadIdx.x & 31;
    int t = blockIdx.y;
    int n = blockIdx.x * 2 + (warp >> 2);
    int head = warp & 3;
    const float* h = g_hT + (size_t)t * N_NODES * HC;
    const float4 v  = ((const float4*)(h + (size_t)n * HC + head * C_CH))[lane];
    const float4 as = ((const float4*)(att_src + head * C_CH))[lane];
    const float4 ad = ((const float4*)(att_dst + head * C_CH))[lane];
    float s = v.x * as.x + v.y * as.y + v.z * as.z + v.w * as.w;
    float d = v.x * ad.x + v.y * ad.y + v.z * ad.z + v.w * ad.w;
#pragma unroll
    for (int o = 16; o; o >>= 1) {
        s += __shfl_xor_sync(0xffffffffu, s, o);
        d += __shfl_xor_sync(0xffffffffu, d, o);
    }
    if (lane == 0) {
        g_asrcT[(t * N_NODES + n) * H_HEADS + head] = s;
        g_adstT[(t * N_NODES + n) * H_HEADS + head] = d;
    }
}

// ---------------- 3) batched CSR build ----------------
__global__ void zero_degT() {
    int i = blockIdx.x * blockDim.x + threadIdx.x;
    if (i < T_STEPS * N_NODES) g_degT[i] = 0;
}

__global__ void degT_kernel(const int* __restrict__ graph) {
    int i = blockIdx.x * blockDim.x + threadIdx.x;
    if (i >= T_STEPS * ETOT) return;
    int t = i / ETOT, e = i - t * ETOT;
    int d = (e < E_EDGES) ? graph[(size_t)t * 2 * E_EDGES + E_EDGES + e] : (e - E_EDGES);
    atomicAdd(&g_degT[t * N_NODES + d], 1);
}

__global__ __launch_bounds__(1024) void scanT_kernel() {
    __shared__ int s[1024];
    int t = blockIdx.x;
    const int* deg = g_degT + t * N_NODES;
    int* rowptr = g_rowptrT + t * (N_NODES + 1);
    int* fill = g_fillT + t * N_NODES;
    int tid = threadIdx.x;
    const int PER = 20;
    int base = tid * PER;
    int vals[PER];
    int run = 0;
#pragma unroll
    for (int i = 0; i < PER; i++) {
        int idx = base + i;
        int v = (idx < N_NODES) ? deg[idx] : 0;
        vals[i] = run;
        run += v;
    }
    s[tid] = run;
    __syncthreads();
    for (int off = 1; off < 1024; off <<= 1) {
        int v = (tid >= off) ? s[tid - off] : 0;
        __syncthreads();
        s[tid] += v;
        __syncthreads();
    }
    int prev = (tid == 0) ? 0 : s[tid - 1];
#pragma unroll
    for (int i = 0; i < PER; i++) {
        int idx = base + i;
        if (idx < N_NODES) {
            int r = prev + vals[i];
            rowptr[idx] = r;
            fill[idx] = r;
        }
    }
    if (tid == 1023) rowptr[N_NODES] = s[1023];
}

__global__ void scatterT_kernel(const int* __restrict__ graph) {
    int i = blockIdx.x * blockDim.x + threadIdx.x;
    if (i >= T_STEPS * ETOT) return;
    int t = i / ETOT, e = i - t * ETOT;
    int sidx, d;
    if (e < E_EDGES) {
        sidx = graph[(size_t)t * 2 * E_EDGES + e];
        d    = graph[(size_t)t * 2 * E_EDGES + E_EDGES + e];
    } else {
        sidx = d = e - E_EDGES;
    }
    int pos = atomicAdd(&g_fillT[t * N_NODES + d], 1);
    g_colT[(size_t)t * ETOT + pos] = sidx;
}

// ---------------- 4) GAT aggregation (batched over t) ----------------
__global__ __launch_bounds__(256) void aggregate_kernel(const float* __restrict__ b_gat) {
    __shared__ __align__(16) float acc_sm[2][H_HEADS][C_CH];
    int warp = threadIdx.x >> 5;
    int lane = threadIdx.x & 31;
    int nodeLocal = warp >> 2;
    int head = warp & 3;
    int t = blockIdx.y;
    int n = blockIdx.x * 2 + nodeLocal;

    const int* rowptr = g_rowptrT + t * (N_NODES + 1);
    const int* col = g_colT + (size_t)t * ETOT;
    const float* asrc = g_asrcT + (size_t)t * N_NODES * H_HEADS;
    const float* h = g_hT + (size_t)t * N_NODES * HC;
    float* w_arr = g_wT + (size_t)t * ETOT * H_HEADS;

    int beg = rowptr[n];
    int end = rowptr[n + 1];
    float ad = g_adstT[(t * N_NODES + n) * H_HEADS + head];

    float sum = 0.f;
    for (int k = beg + lane; k < end; k += 32) {
        int s = col[k];
        float w = __expf(leaky(asrc[s * H_HEADS + head] + ad));
        w_arr[(size_t)k * H_HEADS + head] = w;
        sum += w;
    }
#pragma unroll
    for (int o = 16; o; o >>= 1) sum += __shfl_xor_sync(0xffffffffu, sum, o);
    float inv = 1.f / (sum + 1e-16f);
    __threadfence_block();
    __syncwarp();

    float4 acc = make_float4(0.f, 0.f, 0.f, 0.f);
    int k = beg;
    for (; k + 2 <= end; k += 2) {
        int s0 = col[k], s1 = col[k + 1];
        float w0 = w_arr[(size_t)k * H_HEADS + head];
        float w1 = w_arr[(size_t)(k + 1) * H_HEADS + head];
        const float4 v0 = ((const float4*)(h + (size_t)s0 * HC + head * C_CH))[lane];
        const float4 v1 = ((const float4*)(h + (size_t)s1 * HC + head * C_CH))[lane];
        float a0 = w0 * inv, a1 = w1 * inv;
        acc.x = fmaf(a0, v0.x, fmaf(a1, v1.x, acc.x));
        acc.y = fmaf(a0, v0.y, fmaf(a1, v1.y, acc.y));
        acc.z = fmaf(a0, v0.z, fmaf(a1, v1.z, acc.z));
        acc.w = fmaf(a0, v0.w, fmaf(a1, v1.w, acc.w));
    }
    if (k < end) {
        int s0 = col[k];
        float a0 = w_arr[(size_t)k * H_HEADS + head] * inv;
        const float4 v0 = ((const float4*)(h + (size_t)s0 * HC + head * C_CH))[lane];
        acc.x = fmaf(a0, v0.x, acc.x);
        acc.y = fmaf(a0, v0.y, acc.y);
        acc.z = fmaf(a0, v0.z, acc.z);
        acc.w = fmaf(a0, v0.w, acc.w);
    }
    ((float4*)&acc_sm[nodeLocal][head][lane * 4])[0] = acc;
    __syncthreads();

    int idx = threadIdx.x;
    int nl = idx >> 7;
    int c  = idx & 127;
    int n2 = blockIdx.x * 2 + nl;
    float v = 0.25f * (acc_sm[nl][0][c] + acc_sm[nl][1][c] + acc_sm[nl][2][c] + acc_sm[nl][3][c])
              + b_gat[c];
    g_zT[((size_t)t * N_NODES + n2) * C_CH + c] = leaky(v);
}

// ---------------- 5) LP[t, n, j] = leaky(z @ W1 + b1) (batched over t) ----------------
__global__ __launch_bounds__(128) void lin_kernel(const float* __restrict__ W1,
                                                  const float* __restrict__ b1) {
    __shared__ float zs[32 * 128];
    int j = threadIdx.x;
    int t = blockIdx.y;
    int n0 = blockIdx.x * 32;
    const float* z = g_zT + (size_t)t * N_NODES * C_CH;
#pragma unroll
    for (int r = 0; r < 32; r++) {
        int n = n0 + r;
        zs[r * 128 + j] = (n < N_NODES) ? z[(size_t)n * C_CH + j] : 0.f;
    }
    __syncthreads();
    float acc[32];
    float b = b1[j];
#pragma unroll
    for (int r = 0; r < 32; r++) acc[r] = b;
    for (int k = 0; k < 128; k++) {
        float w = __ldg(&W1[k * 128 + j]);
#pragma unroll
        for (int r = 0; r < 32; r++) acc[r] = fmaf(zs[r * 128 + k], w, acc[r]);
    }
#pragma unroll
    for (int r = 0; r < 32; r++) {
        int n = n0 + r;
        if (n < N_NODES)
            g_LP[(size_t)t * N_NODES * C_CH + (size_t)n * C_CH + j] = leaky(acc[r]);
    }
}

// ---------------- 6) final ----------------
__global__ __launch_bounds__(256) void final_kernel(const float* __restrict__ W2,
                                                    const float* __restrict__ b2,
                                                    float* __restrict__ out) {
    int gw = (blockIdx.x * blockDim.x + threadIdx.x) >> 5;
    int lane = threadIdx.x & 31;
    if (gw >= N_NODES) return;
    const float* row = g_LP + (size_t)gw * (T_STEPS * C_CH);
    float a0 = 0.f, a1 = 0.f;
    for (int i = lane; i < T_STEPS * C_CH; i += 32) {
        float v = row[i];
        a0 = fmaf(v, __ldg(&W2[i * 2 + 0]), a0);
        a1 = fmaf(v, __ldg(&W2[i * 2 + 1]), a1);
    }
#pragma unroll
    for (int o = 16; o; o >>= 1) {
        a0 += __shfl_xor_sync(0xffffffffu, a0, o);
        a1 += __shfl_xor_sync(0xffffffffu, a1, o);
    }
    if (lane == 0) {
        float f0 = a0 + b2[0];
        float f1 = a1 + b2[1];
        float m = fmaxf(f0, f1);
        float lse = m + logf(expf(f0 - m) + expf(f1 - m));
        out[gw * 2 + 0] = f0 - lse;
        out[gw * 2 + 1] = f1 - lse;
    }
}

// ---------------- launch ----------------
extern "C" void kernel_launch(void* const* d_in, const int* in_sizes, int n_in,
                              void* d_out, int out_size) {
    int base = 2;
    if (n_in >= 11 && in_sizes[2] <= 1) base = 3;

    const float* fts     = (const float*)d_in[0];
    const int*   graph   = (const int*)d_in[1];
    const float* W_gat   = (const float*)d_in[base + 0];
    const float* att_src = (const float*)d_in[base + 1];
    const float* att_dst = (const float*)d_in[base + 2];
    const float* b_gat   = (const float*)d_in[base + 3];
    const float* W1      = (const float*)d_in[base + 4];
    const float* b1      = (const float*)d_in[base + 5];
    const float* W2      = (const float*)d_in[base + 6];
    const float* b2      = (const float*)d_in[base + 7];
    float* out = (float*)d_out;

    cudaFuncSetAttribute(gemm_mma, cudaFuncAttributeMaxDynamicSharedMemorySize, GEMM_SMEM_TOT);

    const int convGrid = (int)(((size_t)T_STEPS * N_NODES * 128 + 255) / 256);

    // gemm_mma kept as the 4th launch for the ncu window
    conv_B<<<(512 * 512 + 255) / 256, 256>>>(W_gat);
    conv_A<<<convGrid, 256>>>(fts);
    zero_degT<<<(T_STEPS * N_NODES + 255) / 256, 256>>>();
    gemm_mma<<<dim3(NT_TILES, MT_TILES, T_STEPS), 256, GEMM_SMEM_TOT>>>(0);
    degT_kernel<<<(T_STEPS * ETOT + 255) / 256, 256>>>(graph);
    scanT_kernel<<<T_STEPS, 1024>>>();
    scatterT_kernel<<<(T_STEPS * ETOT + 255) / 256, 256>>>(graph);
    att_kernel<<<dim3(N_NODES / 2, T_STEPS), 256>>>(att_src, att_dst);
    aggregate_kernel<<<dim3(N_NODES / 2, T_STEPS), 256>>>(b_gat);
    lin_kernel<<<dim3((N_NODES + 31) / 32, T_STEPS), 128>>>(W1, b1);
    final_kernel<<<(N_NODES * 32 + 255) / 256, 256>>>(W2, b2, out);
}

// round 9
// speedup vs baseline: 2.6501x; 1.1425x over previous
#include <cuda_runtime.h>
#include <cuda_bf16.h>
#include <math.h>
#include <stdint.h>

#define N_NODES 20000
#define T_STEPS 8
#define E_EDGES 320000
#define ETOT    (E_EDGES + N_NODES)
#define NFEAT   512
#define HC      512
#define H_HEADS 4
#define C_CH    128
#define SLOPEV  0.2f

#define MT_TILES 157
#define NT_TILES 4
#define BK 32

// ---------------- scratch (batched across T) ----------------
__device__ float g_hT[(size_t)T_STEPS * N_NODES * HC];          // 328 MB
__device__ float g_asrcT[T_STEPS * N_NODES * H_HEADS];
__device__ float g_adstT[T_STEPS * N_NODES * H_HEADS];
__device__ float g_zT[(size_t)T_STEPS * N_NODES * C_CH];        // 82 MB
__device__ float g_LP[(size_t)T_STEPS * N_NODES * C_CH];        // 82 MB
__device__ uint16_t g_B16h[512 * 512];   // [n][k]
__device__ uint16_t g_B16l[512 * 512];
__device__ uint16_t g_A16h[(size_t)T_STEPS * N_NODES * 512];    // 164 MB (bf16 of A)
__device__ float g_wT[(size_t)T_STEPS * ETOT * H_HEADS];        // 42 MB
// batched CSR
__device__ int g_degT[T_STEPS * N_NODES];
__device__ int g_rowptrT[T_STEPS * (N_NODES + 1)];
__device__ int g_fillT[T_STEPS * N_NODES];
__device__ int g_colT[(size_t)T_STEPS * ETOT];

__device__ __forceinline__ float leaky(float x) { return x >= 0.f ? x : SLOPEV * x; }

__device__ __forceinline__ uint32_t smem_u32(const void* p) {
    uint32_t a;
    asm("{ .reg .u64 t; cvta.to.shared.u64 t, %1; cvt.u32.u64 %0, t; }" : "=r"(a) : "l"(p));
    return a;
}
__device__ __forceinline__ void ldsm_x4(uint32_t& r0, uint32_t& r1, uint32_t& r2, uint32_t& r3,
                                        uint32_t addr) {
    asm volatile("ldmatrix.sync.aligned.m8n8.x4.shared.b16 {%0,%1,%2,%3}, [%4];"
                 : "=r"(r0), "=r"(r1), "=r"(r2), "=r"(r3) : "r"(addr));
}
__device__ __forceinline__ void mma16816(float* c, const uint32_t* a, const uint32_t* b) {
    asm volatile(
        "mma.sync.aligned.m16n8k16.row.col.f32.bf16.bf16.f32 "
        "{%0,%1,%2,%3}, {%4,%5,%6,%7}, {%8,%9}, {%0,%1,%2,%3};"
        : "+f"(c[0]), "+f"(c[1]), "+f"(c[2]), "+f"(c[3])
        : "r"(a[0]), "r"(a[1]), "r"(a[2]), "r"(a[3]), "r"(b[0]), "r"(b[1]));
}
__device__ __forceinline__ uint32_t pack_hi2(float v0, float v1) {
    __nv_bfloat162 p = __floats2bfloat162_rn(v0, v1);
    return *reinterpret_cast<uint32_t*>(&p);
}
__device__ __forceinline__ void cp16(uint32_t dst, const void* src) {
    asm volatile("cp.async.cg.shared.global [%0], [%1], 16;" :: "r"(dst), "l"(src));
}
#define CP_COMMIT() asm volatile("cp.async.commit_group;" ::: "memory")
#define CP_WAIT0()  asm volatile("cp.async.wait_group 0;" ::: "memory")

// ---------------- 0a) convert W -> bf16 hi/lo, [n][k] ----------------
__global__ void conv_B(const float* __restrict__ W) {
    int i = blockIdx.x * blockDim.x + threadIdx.x;
    if (i >= 512 * 512) return;
    int k = i >> 9, n = i & 511;
    float v = W[(size_t)k * 512 + n];
    __nv_bfloat16 h = __float2bfloat16(v);
    __nv_bfloat16 l = __float2bfloat16(v - __bfloat162float(h));
    g_B16h[(size_t)n * 512 + k] = *reinterpret_cast<uint16_t*>(&h);
    g_B16l[(size_t)n * 512 + k] = *reinterpret_cast<uint16_t*>(&l);
}

// ---------------- 0b) convert ALL fts -> bf16 (hi only) ----------------
__global__ __launch_bounds__(256) void conv_A(const float* __restrict__ A) {
    size_t i = (size_t)blockIdx.x * blockDim.x + threadIdx.x;   // float4 index
    if (i >= (size_t)T_STEPS * N_NODES * 128) return;
    float4 v = ((const float4*)A)[i];
    uint2 hi = make_uint2(pack_hi2(v.x, v.y), pack_hi2(v.z, v.w));
    ((uint2*)g_A16h)[i] = hi;
}

// ---------------- 1) GEMM batched over t: 2-term (A_bf16 * (Bh + Bl)) ----------------
#define BF_PITCH  40
#define STG       (128 * BF_PITCH * 2)   // 10240 B
#define OFF_A     0
#define OFF_BH    (2 * STG)
#define OFF_BL    (4 * STG)
#define GEMM_SMEM_TOT (6 * STG)          // 61440

__device__ __forceinline__ void load_stage(uint32_t sb, int tid, size_t aBase, int mt, int nt,
                                           int buf, int k0) {
#pragma unroll
    for (int c = 0; c < 2; c++) {
        int idx = tid + c * 256;
        int row = idx >> 2, ch = idx & 3;
        int node = mt * 128 + row;
        if (node > N_NODES - 1) node = N_NODES - 1;
        uint32_t doff = buf * STG + row * (BF_PITCH * 2) + ch * 16;
        const uint16_t* sa = g_A16h + aBase + (size_t)node * 512 + k0 + ch * 8;
        cp16(sb + OFF_A + doff, sa);
        const uint16_t* sbh = g_B16h + (size_t)(nt * 128 + row) * 512 + k0 + ch * 8;
        const uint16_t* sbl = g_B16l + (size_t)(nt * 128 + row) * 512 + k0 + ch * 8;
        cp16(sb + OFF_BH + doff, sbh);
        cp16(sb + OFF_BL + doff, sbl);
    }
}

__global__ __launch_bounds__(256, 2) void gemm_mma(int unused) {
    extern __shared__ __align__(16) unsigned char sm[];
    uint32_t sb = smem_u32(sm);
    const int tid = threadIdx.x, warp = tid >> 5, lane = tid & 31;
    const int mt = blockIdx.y, nt = blockIdx.x, t = blockIdx.z;
    const int warpM = warp & 1, warpN = warp >> 1;
    const size_t aBase = (size_t)t * N_NODES * 512;

    float acc[4][4][4];
#pragma unroll
    for (int i = 0; i < 4; i++)
#pragma unroll
        for (int j = 0; j < 4; j++)
#pragma unroll
            for (int q = 0; q < 4; q++) acc[i][j][q] = 0.f;

    const uint32_t aB = sb + OFF_A;
    const uint32_t bhB = sb + OFF_BH, blB = sb + OFF_BL;
    const int aLdRow = warpM * 64 + (lane & 7) + ((lane >> 3) & 1) * 8;
    const int aLdK   = (lane >> 4) * 8;
    const int bLdRow = warpN * 32 + (lane & 7) + ((lane >> 4) & 1) * 8;
    const int bLdK   = ((lane >> 3) & 1) * 8;

    load_stage(sb, tid, aBase, mt, nt, 0, 0);
    CP_COMMIT();

    for (int it = 0; it < 16; it++) {
        const int cur = it & 1;
        CP_WAIT0();
        __syncthreads();
        if (it + 1 < 16) {
            load_stage(sb, tid, aBase, mt, nt, cur ^ 1, (it + 1) * BK);
            CP_COMMIT();
        }

#pragma unroll
        for (int kk = 0; kk < 32; kk += 16) {
            uint32_t bh[2][4], bl[2][4];
#pragma unroll
            for (int nfp = 0; nfp < 2; nfp++) {
                uint32_t off = (uint32_t)(cur * STG + (bLdRow + nfp * 16) * (BF_PITCH * 2)
                                          + (kk + bLdK) * 2);
                ldsm_x4(bh[nfp][0], bh[nfp][1], bh[nfp][2], bh[nfp][3], bhB + off);
                ldsm_x4(bl[nfp][0], bl[nfp][1], bl[nfp][2], bl[nfp][3], blB + off);
            }
#pragma unroll
            for (int mf = 0; mf < 4; mf++) {
                uint32_t off = (uint32_t)(cur * STG + (aLdRow + mf * 16) * (BF_PITCH * 2)
                                          + (kk + aLdK) * 2);
                uint32_t ah[4];
                ldsm_x4(ah[0], ah[1], ah[2], ah[3], aB + off);
#pragma unroll
                for (int nf = 0; nf < 4; nf++) {
                    const uint32_t* bfrag_h = &bh[nf >> 1][(nf & 1) * 2];
                    const uint32_t* bfrag_l = &bl[nf >> 1][(nf & 1) * 2];
                    mma16816(acc[mf][nf], ah, bfrag_h);
                    mma16816(acc[mf][nf], ah, bfrag_l);
                }
            }
        }
        __syncthreads();
    }

    float* hOut = g_hT + (size_t)t * N_NODES * HC;
    const int r0 = lane >> 2, c0 = (lane & 3) * 2;
#pragma unroll
    for (int mf = 0; mf < 4; mf++) {
#pragma unroll
        for (int nf = 0; nf < 4; nf++) {
            int row = mt * 128 + warpM * 64 + mf * 16 + r0;
            int col = nt * 128 + warpN * 32 + nf * 8 + c0;
            if (row < N_NODES)
                *(float2*)(hOut + (size_t)row * 512 + col) = make_float2(acc[mf][nf][0], acc[mf][nf][1]);
            if (row + 8 < N_NODES)
                *(float2*)(hOut + (size_t)(row + 8) * 512 + col) = make_float2(acc[mf][nf][2], acc[mf][nf][3]);
        }
    }
}

// ---------------- 2) attention coefficients (batched over t) ----------------
__global__ __launch_bounds__(256) void att_kernel(const float* __restrict__ att_src,
                                                  const float* __restrict__ att_dst) {
    int warp = threadIdx.x >> 5;
    int lane = threadIdx.x & 31;
    int t = blockIdx.y;
    int n = blockIdx.x * 2 + (warp >> 2);
    int head = warp & 3;
    const float* h = g_hT + (size_t)t * N_NODES * HC;
    const float4 v  = ((const float4*)(h + (size_t)n * HC + head * C_CH))[lane];
    const float4 as = ((const float4*)(att_src + head * C_CH))[lane];
    const float4 ad = ((const float4*)(att_dst + head * C_CH))[lane];
    float s = v.x * as.x + v.y * as.y + v.z * as.z + v.w * as.w;
    float d = v.x * ad.x + v.y * ad.y + v.z * ad.z + v.w * ad.w;
#pragma unroll
    for (int o = 16; o; o >>= 1) {
        s += __shfl_xor_sync(0xffffffffu, s, o);
        d += __shfl_xor_sync(0xffffffffu, d, o);
    }
    if (lane == 0) {
        g_asrcT[(t * N_NODES + n) * H_HEADS + head] = s;
        g_adstT[(t * N_NODES + n) * H_HEADS + head] = d;
    }
}

// ---------------- 3) batched CSR build ----------------
__global__ void zero_degT() {
    int i = blockIdx.x * blockDim.x + threadIdx.x;
    if (i < T_STEPS * N_NODES) g_degT[i] = 0;
}

__global__ void degT_kernel(const int* __restrict__ graph) {
    int i = blockIdx.x * blockDim.x + threadIdx.x;
    if (i >= T_STEPS * ETOT) return;
    int t = i / ETOT, e = i - t * ETOT;
    int d = (e < E_EDGES) ? graph[(size_t)t * 2 * E_EDGES + E_EDGES + e] : (e - E_EDGES);
    atomicAdd(&g_degT[t * N_NODES + d], 1);
}

__global__ __launch_bounds__(1024) void scanT_kernel() {
    __shared__ int s[1024];
    int t = blockIdx.x;
    const int* deg = g_degT + t * N_NODES;
    int* rowptr = g_rowptrT + t * (N_NODES + 1);
    int* fill = g_fillT + t * N_NODES;
    int tid = threadIdx.x;
    const int PER = 20;
    int base = tid * PER;
    int vals[PER];
    int run = 0;
#pragma unroll
    for (int i = 0; i < PER; i++) {
        int idx = base + i;
        int v = (idx < N_NODES) ? deg[idx] : 0;
        vals[i] = run;
        run += v;
    }
    s[tid] = run;
    __syncthreads();
    for (int off = 1; off < 1024; off <<= 1) {
        int v = (tid >= off) ? s[tid - off] : 0;
        __syncthreads();
        s[tid] += v;
        __syncthreads();
    }
    int prev = (tid == 0) ? 0 : s[tid - 1];
#pragma unroll
    for (int i = 0; i < PER; i++) {
        int idx = base + i;
        if (idx < N_NODES) {
            int r = prev + vals[i];
            rowptr[idx] = r;
            fill[idx] = r;
        }
    }
    if (tid == 1023) rowptr[N_NODES] = s[1023];
}

__global__ void scatterT_kernel(const int* __restrict__ graph) {
    int i = blockIdx.x * blockDim.x + threadIdx.x;
    if (i >= T_STEPS * ETOT) return;
    int t = i / ETOT, e = i - t * ETOT;
    int sidx, d;
    if (e < E_EDGES) {
        sidx = graph[(size_t)t * 2 * E_EDGES + e];
        d    = graph[(size_t)t * 2 * E_EDGES + E_EDGES + e];
    } else {
        sidx = d = e - E_EDGES;
    }
    int pos = atomicAdd(&g_fillT[t * N_NODES + d], 1);
    g_colT[(size_t)t * ETOT + pos] = sidx;
}

// ---------------- 4) GAT aggregation (batched over t, x4 unrolled gather) ----------------
__global__ __launch_bounds__(256) void aggregate_kernel(const float* __restrict__ b_gat) {
    __shared__ __align__(16) float acc_sm[2][H_HEADS][C_CH];
    int warp = threadIdx.x >> 5;
    int lane = threadIdx.x & 31;
    int nodeLocal = warp >> 2;
    int head = warp & 3;
    int t = blockIdx.y;
    int n = blockIdx.x * 2 + nodeLocal;

    const int* rowptr = g_rowptrT + t * (N_NODES + 1);
    const int* col = g_colT + (size_t)t * ETOT;
    const float* asrc = g_asrcT + (size_t)t * N_NODES * H_HEADS;
    const float* h = g_hT + (size_t)t * N_NODES * HC;
    float* w_arr = g_wT + (size_t)t * ETOT * H_HEADS;

    int beg = rowptr[n];
    int end = rowptr[n + 1];
    float ad = g_adstT[(t * N_NODES + n) * H_HEADS + head];

    float sum = 0.f;
    for (int k = beg + lane; k < end; k += 32) {
        int s = col[k];
        float w = __expf(leaky(asrc[s * H_HEADS + head] + ad));
        w_arr[(size_t)k * H_HEADS + head] = w;
        sum += w;
    }
#pragma unroll
    for (int o = 16; o; o >>= 1) sum += __shfl_xor_sync(0xffffffffu, sum, o);
    float inv = 1.f / (sum + 1e-16f);
    __threadfence_block();
    __syncwarp();

    float4 acc = make_float4(0.f, 0.f, 0.f, 0.f);
    int k = beg;
    for (; k + 4 <= end; k += 4) {
        int s0 = col[k], s1 = col[k + 1], s2 = col[k + 2], s3 = col[k + 3];
        float a0 = w_arr[(size_t)k * H_HEADS + head] * inv;
        float a1 = w_arr[(size_t)(k + 1) * H_HEADS + head] * inv;
        float a2 = w_arr[(size_t)(k + 2) * H_HEADS + head] * inv;
        float a3 = w_arr[(size_t)(k + 3) * H_HEADS + head] * inv;
        const float4 v0 = ((const float4*)(h + (size_t)s0 * HC + head * C_CH))[lane];
        const float4 v1 = ((const float4*)(h + (size_t)s1 * HC + head * C_CH))[lane];
        const float4 v2 = ((const float4*)(h + (size_t)s2 * HC + head * C_CH))[lane];
        const float4 v3 = ((const float4*)(h + (size_t)s3 * HC + head * C_CH))[lane];
        acc.x = fmaf(a0, v0.x, fmaf(a1, v1.x, fmaf(a2, v2.x, fmaf(a3, v3.x, acc.x))));
        acc.y = fmaf(a0, v0.y, fmaf(a1, v1.y, fmaf(a2, v2.y, fmaf(a3, v3.y, acc.y))));
        acc.z = fmaf(a0, v0.z, fmaf(a1, v1.z, fmaf(a2, v2.z, fmaf(a3, v3.z, acc.z))));
        acc.w = fmaf(a0, v0.w, fmaf(a1, v1.w, fmaf(a2, v2.w, fmaf(a3, v3.w, acc.w))));
    }
    for (; k < end; k++) {
        int s0 = col[k];
        float a0 = w_arr[(size_t)k * H_HEADS + head] * inv;
        const float4 v0 = ((const float4*)(h + (size_t)s0 * HC + head * C_CH))[lane];
        acc.x = fmaf(a0, v0.x, acc.x);
        acc.y = fmaf(a0, v0.y, acc.y);
        acc.z = fmaf(a0, v0.z, acc.z);
        acc.w = fmaf(a0, v0.w, acc.w);
    }
    ((float4*)&acc_sm[nodeLocal][head][lane * 4])[0] = acc;
    __syncthreads();

    int idx = threadIdx.x;
    int nl = idx >> 7;
    int c  = idx & 127;
    int n2 = blockIdx.x * 2 + nl;
    float v = 0.25f * (acc_sm[nl][0][c] + acc_sm[nl][1][c] + acc_sm[nl][2][c] + acc_sm[nl][3][c])
              + b_gat[c];
    g_zT[((size_t)t * N_NODES + n2) * C_CH + c] = leaky(v);
}

// ---------------- 5) LP = leaky(z @ W1 + b1) (batched over t) ----------------
__global__ __launch_bounds__(128) void lin_kernel(const float* __restrict__ W1,
                                                  const float* __restrict__ b1) {
    __shared__ float zs[32 * 128];
    int j = threadIdx.x;
    int t = blockIdx.y;
    int n0 = blockIdx.x * 32;
    const float* z = g_zT + (size_t)t * N_NODES * C_CH;
#pragma unroll
    for (int r = 0; r < 32; r++) {
        int n = n0 + r;
        zs[r * 128 + j] = (n < N_NODES) ? z[(size_t)n * C_CH + j] : 0.f;
    }
    __syncthreads();
    float acc[32];
    float b = b1[j];
#pragma unroll
    for (int r = 0; r < 32; r++) acc[r] = b;
    for (int k = 0; k < 128; k++) {
        float w = __ldg(&W1[k * 128 + j]);
#pragma unroll
        for (int r = 0; r < 32; r++) acc[r] = fmaf(zs[r * 128 + k], w, acc[r]);
    }
#pragma unroll
    for (int r = 0; r < 32; r++) {
        int n = n0 + r;
        if (n < N_NODES)
            g_LP[(size_t)t * N_NODES * C_CH + (size_t)n * C_CH + j] = leaky(acc[r]);
    }
}

// ---------------- 6) final ----------------
__global__ __launch_bounds__(256) void final_kernel(const float* __restrict__ W2,
                                                    const float* __restrict__ b2,
                                                    float* __restrict__ out) {
    int gw = (blockIdx.x * blockDim.x + threadIdx.x) >> 5;
    int lane = threadIdx.x & 31;
    if (gw >= N_NODES) return;
    const float* row = g_LP + (size_t)gw * (T_STEPS * C_CH);
    float a0 = 0.f, a1 = 0.f;
    for (int i = lane; i < T_STEPS * C_CH; i += 32) {
        float v = row[i];
        a0 = fmaf(v, __ldg(&W2[i * 2 + 0]), a0);
        a1 = fmaf(v, __ldg(&W2[i * 2 + 1]), a1);
    }
#pragma unroll
    for (int o = 16; o; o >>= 1) {
        a0 += __shfl_xor_sync(0xffffffffu, a0, o);
        a1 += __shfl_xor_sync(0xffffffffu, a1, o);
    }
    if (lane == 0) {
        float f0 = a0 + b2[0];
        float f1 = a1 + b2[1];
        float m = fmaxf(f0, f1);
        float lse = m + logf(expf(f0 - m) + expf(f1 - m));
        out[gw * 2 + 0] = f0 - lse;
        out[gw * 2 + 1] = f1 - lse;
    }
}

// ---------------- launch ----------------
extern "C" void kernel_launch(void* const* d_in, const int* in_sizes, int n_in,
                              void* d_out, int out_size) {
    int base = 2;
    if (n_in >= 11 && in_sizes[2] <= 1) base = 3;

    const float* fts     = (const float*)d_in[0];
    const int*   graph   = (const int*)d_in[1];
    const float* W_gat   = (const float*)d_in[base + 0];
    const float* att_src = (const float*)d_in[base + 1];
    const float* att_dst = (const float*)d_in[base + 2];
    const float* b_gat   = (const float*)d_in[base + 3];
    const float* W1      = (const float*)d_in[base + 4];
    const float* b1      = (const float*)d_in[base + 5];
    const float* W2      = (const float*)d_in[base + 6];
    const float* b2      = (const float*)d_in[base + 7];
    float* out = (float*)d_out;

    cudaFuncSetAttribute(gemm_mma, cudaFuncAttributeMaxDynamicSharedMemorySize, GEMM_SMEM_TOT);

    const int convGrid = (int)(((size_t)T_STEPS * N_NODES * 128 + 255) / 256);

    // gemm_mma kept as the 4th launch for the ncu window
    conv_B<<<(512 * 512 + 255) / 256, 256>>>(W_gat);
    conv_A<<<convGrid, 256>>>(fts);
    zero_degT<<<(T_STEPS * N_NODES + 255) / 256, 256>>>();
    gemm_mma<<<dim3(NT_TILES, MT_TILES, T_STEPS), 256, GEMM_SMEM_TOT>>>(0);
    degT_kernel<<<(T_STEPS * ETOT + 255) / 256, 256>>>(graph);
    scanT_kernel<<<T_STEPS, 1024>>>();
    scatterT_kernel<<<(T_STEPS * ETOT + 255) / 256, 256>>>(graph);
    att_kernel<<<dim3(N_NODES / 2, T_STEPS), 256>>>(att_src, att_dst);
    aggregate_kernel<<<dim3(N_NODES / 2, T_STEPS), 256>>>(b_gat);
    lin_kernel<<<dim3((N_NODES + 31) / 32, T_STEPS), 128>>>(W1, b1);
    final_kernel<<<(N_NODES * 32 + 255) / 256, 256>>>(W2, b2, out);
}

// round 10
// speedup vs baseline: 2.6615x; 1.0043x over previous
#include <cuda_runtime.h>
#include <cuda_bf16.h>
#include <math.h>
#include <stdint.h>

#define N_NODES 20000
#define T_STEPS 8
#define E_EDGES 320000
#define ETOT    (E_EDGES + N_NODES)
#define NFEAT   512
#define HC      512
#define H_HEADS 4
#define C_CH    128
#define SLOPEV  0.2f

#define MT_TILES 157
#define NT_TILES 4
#define BK 32

// ---------------- scratch (batched across T) ----------------
__device__ float g_hT[(size_t)T_STEPS * N_NODES * HC];          // 328 MB
__device__ float g_asrcT[T_STEPS * N_NODES * H_HEADS];
__device__ float g_adstT[T_STEPS * N_NODES * H_HEADS];
__device__ float g_LP[(size_t)T_STEPS * N_NODES * C_CH];        // 82 MB
__device__ uint16_t g_B16h[512 * 512];   // [n][k]
__device__ uint16_t g_B16l[512 * 512];
__device__ uint16_t g_A16h[(size_t)T_STEPS * N_NODES * 512];    // 164 MB
__device__ float g_wT[(size_t)T_STEPS * ETOT * H_HEADS];        // 42 MB
// batched CSR
__device__ int g_degT[T_STEPS * N_NODES];
__device__ int g_rowptrT[T_STEPS * (N_NODES + 1)];
__device__ int g_fillT[T_STEPS * N_NODES];
__device__ int g_colT[(size_t)T_STEPS * ETOT];

__device__ __forceinline__ float leaky(float x) { return x >= 0.f ? x : SLOPEV * x; }

__device__ __forceinline__ uint32_t smem_u32(const void* p) {
    uint32_t a;
    asm("{ .reg .u64 t; cvta.to.shared.u64 t, %1; cvt.u32.u64 %0, t; }" : "=r"(a) : "l"(p));
    return a;
}
__device__ __forceinline__ void ldsm_x4(uint32_t& r0, uint32_t& r1, uint32_t& r2, uint32_t& r3,
                                        uint32_t addr) {
    asm volatile("ldmatrix.sync.aligned.m8n8.x4.shared.b16 {%0,%1,%2,%3}, [%4];"
                 : "=r"(r0), "=r"(r1), "=r"(r2), "=r"(r3) : "r"(addr));
}
__device__ __forceinline__ void mma16816(float* c, const uint32_t* a, const uint32_t* b) {
    asm volatile(
        "mma.sync.aligned.m16n8k16.row.col.f32.bf16.bf16.f32 "
        "{%0,%1,%2,%3}, {%4,%5,%6,%7}, {%8,%9}, {%0,%1,%2,%3};"
        : "+f"(c[0]), "+f"(c[1]), "+f"(c[2]), "+f"(c[3])
        : "r"(a[0]), "r"(a[1]), "r"(a[2]), "r"(a[3]), "r"(b[0]), "r"(b[1]));
}
__device__ __forceinline__ uint32_t pack_hi2(float v0, float v1) {
    __nv_bfloat162 p = __floats2bfloat162_rn(v0, v1);
    return *reinterpret_cast<uint32_t*>(&p);
}
__device__ __forceinline__ void cp16(uint32_t dst, const void* src) {
    asm volatile("cp.async.cg.shared.global [%0], [%1], 16;" :: "r"(dst), "l"(src));
}
#define CP_COMMIT() asm volatile("cp.async.commit_group;" ::: "memory")
#define CP_WAIT0()  asm volatile("cp.async.wait_group 0;" ::: "memory")

// ---------------- 0a) convert W -> bf16 hi/lo, [n][k] ----------------
__global__ void conv_B(const float* __restrict__ W) {
    int i = blockIdx.x * blockDim.x + threadIdx.x;
    if (i >= 512 * 512) return;
    int k = i >> 9, n = i & 511;
    float v = W[(size_t)k * 512 + n];
    __nv_bfloat16 h = __float2bfloat16(v);
    __nv_bfloat16 l = __float2bfloat16(v - __bfloat162float(h));
    g_B16h[(size_t)n * 512 + k] = *reinterpret_cast<uint16_t*>(&h);
    g_B16l[(size_t)n * 512 + k] = *reinterpret_cast<uint16_t*>(&l);
}

// ---------------- 0b) convert ALL fts -> bf16 (hi only) ----------------
__global__ __launch_bounds__(256) void conv_A(const float* __restrict__ A) {
    size_t i = (size_t)blockIdx.x * blockDim.x + threadIdx.x;
    if (i >= (size_t)T_STEPS * N_NODES * 128) return;
    float4 v = ((const float4*)A)[i];
    uint2 hi = make_uint2(pack_hi2(v.x, v.y), pack_hi2(v.z, v.w));
    ((uint2*)g_A16h)[i] = hi;
}

// ---------------- 1) GEMM batched over t, fused attention-coefficient epilogue ----------------
#define BF_PITCH  40
#define STG       (128 * BF_PITCH * 2)
#define OFF_A     0
#define OFF_BH    (2 * STG)
#define OFF_BL    (4 * STG)
#define GEMM_SMEM_TOT (6 * STG)

__device__ __forceinline__ void load_stage(uint32_t sb, int tid, size_t aBase, int mt, int nt,
                                           int buf, int k0) {
#pragma unroll
    for (int c = 0; c < 2; c++) {
        int idx = tid + c * 256;
        int row = idx >> 2, ch = idx & 3;
        int node = mt * 128 + row;
        if (node > N_NODES - 1) node = N_NODES - 1;
        uint32_t doff = buf * STG + row * (BF_PITCH * 2) + ch * 16;
        const uint16_t* sa = g_A16h + aBase + (size_t)node * 512 + k0 + ch * 8;
        cp16(sb + OFF_A + doff, sa);
        const uint16_t* sbh = g_B16h + (size_t)(nt * 128 + row) * 512 + k0 + ch * 8;
        const uint16_t* sbl = g_B16l + (size_t)(nt * 128 + row) * 512 + k0 + ch * 8;
        cp16(sb + OFF_BH + doff, sbh);
        cp16(sb + OFF_BL + doff, sbl);
    }
}

__global__ __launch_bounds__(256, 2) void gemm_mma(const float* __restrict__ att_src,
                                                   const float* __restrict__ att_dst) {
    extern __shared__ __align__(16) unsigned char sm[];
    uint32_t sb = smem_u32(sm);
    const int tid = threadIdx.x, warp = tid >> 5, lane = tid & 31;
    const int mt = blockIdx.y, nt = blockIdx.x, t = blockIdx.z;
    const int warpM = warp & 1, warpN = warp >> 1;
    const size_t aBase = (size_t)t * N_NODES * 512;

    float acc[4][4][4];
#pragma unroll
    for (int i = 0; i < 4; i++)
#pragma unroll
        for (int j = 0; j < 4; j++)
#pragma unroll
            for (int q = 0; q < 4; q++) acc[i][j][q] = 0.f;

    const uint32_t aB = sb + OFF_A;
    const uint32_t bhB = sb + OFF_BH, blB = sb + OFF_BL;
    const int aLdRow = warpM * 64 + (lane & 7) + ((lane >> 3) & 1) * 8;
    const int aLdK   = (lane >> 4) * 8;
    const int bLdRow = warpN * 32 + (lane & 7) + ((lane >> 4) & 1) * 8;
    const int bLdK   = ((lane >> 3) & 1) * 8;

    load_stage(sb, tid, aBase, mt, nt, 0, 0);
    CP_COMMIT();

    for (int it = 0; it < 16; it++) {
        const int cur = it & 1;
        CP_WAIT0();
        __syncthreads();
        if (it + 1 < 16) {
            load_stage(sb, tid, aBase, mt, nt, cur ^ 1, (it + 1) * BK);
            CP_COMMIT();
        }

#pragma unroll
        for (int kk = 0; kk < 32; kk += 16) {
            uint32_t bh[2][4], bl[2][4];
#pragma unroll
            for (int nfp = 0; nfp < 2; nfp++) {
                uint32_t off = (uint32_t)(cur * STG + (bLdRow + nfp * 16) * (BF_PITCH * 2)
                                          + (kk + bLdK) * 2);
                ldsm_x4(bh[nfp][0], bh[nfp][1], bh[nfp][2], bh[nfp][3], bhB + off);
                ldsm_x4(bl[nfp][0], bl[nfp][1], bl[nfp][2], bl[nfp][3], blB + off);
            }
#pragma unroll
            for (int mf = 0; mf < 4; mf++) {
                uint32_t off = (uint32_t)(cur * STG + (aLdRow + mf * 16) * (BF_PITCH * 2)
                                          + (kk + aLdK) * 2);
                uint32_t ah[4];
                ldsm_x4(ah[0], ah[1], ah[2], ah[3], aB + off);
#pragma unroll
                for (int nf = 0; nf < 4; nf++) {
                    const uint32_t* bfrag_h = &bh[nf >> 1][(nf & 1) * 2];
                    const uint32_t* bfrag_l = &bl[nf >> 1][(nf & 1) * 2];
                    mma16816(acc[mf][nf], ah, bfrag_h);
                    mma16816(acc[mf][nf], ah, bfrag_l);
                }
            }
        }
        __syncthreads();
    }

    // ---- write h ----
    float* hOut = g_hT + (size_t)t * N_NODES * HC;
    const int r0 = lane >> 2, c0 = (lane & 3) * 2;
#pragma unroll
    for (int mf = 0; mf < 4; mf++) {
#pragma unroll
        for (int nf = 0; nf < 4; nf++) {
            int row = mt * 128 + warpM * 64 + mf * 16 + r0;
            int col = nt * 128 + warpN * 32 + nf * 8 + c0;
            if (row < N_NODES)
                *(float2*)(hOut + (size_t)row * 512 + col) = make_float2(acc[mf][nf][0], acc[mf][nf][1]);
            if (row + 8 < N_NODES)
                *(float2*)(hOut + (size_t)(row + 8) * 512 + col) = make_float2(acc[mf][nf][2], acc[mf][nf][3]);
        }
    }

    // ---- fused attention coefficients: column tile nt == head nt ----
    // per-thread attention vector values for its columns
    float asv[4][2], adv[4][2];
#pragma unroll
    for (int nf = 0; nf < 4; nf++) {
#pragma unroll
        for (int e = 0; e < 2; e++) {
            int cidx = nt * 128 + warpN * 32 + nf * 8 + c0 + e;
            asv[nf][e] = __ldg(&att_src[cidx]);
            adv[nf][e] = __ldg(&att_dst[cidx]);
        }
    }
    float* attS = (float*)sm;            // [128][4]
    float* attD = (float*)sm + 512;      // [128][4]
#pragma unroll
    for (int mf = 0; mf < 4; mf++) {
#pragma unroll
        for (int half = 0; half < 2; half++) {
            float s = 0.f, d = 0.f;
#pragma unroll
            for (int nf = 0; nf < 4; nf++) {
                s = fmaf(acc[mf][nf][half * 2 + 0], asv[nf][0], s);
                s = fmaf(acc[mf][nf][half * 2 + 1], asv[nf][1], s);
                d = fmaf(acc[mf][nf][half * 2 + 0], adv[nf][0], d);
                d = fmaf(acc[mf][nf][half * 2 + 1], adv[nf][1], d);
            }
            s += __shfl_xor_sync(0xffffffffu, s, 1);
            s += __shfl_xor_sync(0xffffffffu, s, 2);
            d += __shfl_xor_sync(0xffffffffu, d, 1);
            d += __shfl_xor_sync(0xffffffffu, d, 2);
            if ((lane & 3) == 0) {
                int rowL = warpM * 64 + mf * 16 + half * 8 + r0;
                attS[rowL * 4 + warpN] = s;
                attD[rowL * 4 + warpN] = d;
            }
        }
    }
    __syncthreads();
    {
        int rowL = tid >> 1, which = tid & 1;
        int node = mt * 128 + rowL;
        if (node < N_NODES) {
            const float* base = which ? attD : attS;
            float v = base[rowL * 4 + 0] + base[rowL * 4 + 1] + base[rowL * 4 + 2] + base[rowL * 4 + 3];
            float* dst = which ? g_adstT : g_asrcT;
            dst[((size_t)t * N_NODES + node) * H_HEADS + nt] = v;
        }
    }
}

// ---------------- 3) batched CSR build ----------------
__global__ void zero_degT() {
    int i = blockIdx.x * blockDim.x + threadIdx.x;
    if (i < T_STEPS * N_NODES) g_degT[i] = 0;
}

__global__ void degT_kernel(const int* __restrict__ graph) {
    int i = blockIdx.x * blockDim.x + threadIdx.x;
    if (i >= T_STEPS * ETOT) return;
    int t = i / ETOT, e = i - t * ETOT;
    int d = (e < E_EDGES) ? graph[(size_t)t * 2 * E_EDGES + E_EDGES + e] : (e - E_EDGES);
    atomicAdd(&g_degT[t * N_NODES + d], 1);
}

__global__ __launch_bounds__(1024) void scanT_kernel() {
    __shared__ int s[1024];
    int t = blockIdx.x;
    const int* deg = g_degT + t * N_NODES;
    int* rowptr = g_rowptrT + t * (N_NODES + 1);
    int* fill = g_fillT + t * N_NODES;
    int tid = threadIdx.x;
    const int PER = 20;
    int base = tid * PER;
    int vals[PER];
    int run = 0;
#pragma unroll
    for (int i = 0; i < PER; i++) {
        int idx = base + i;
        int v = (idx < N_NODES) ? deg[idx] : 0;
        vals[i] = run;
        run += v;
    }
    s[tid] = run;
    __syncthreads();
    for (int off = 1; off < 1024; off <<= 1) {
        int v = (tid >= off) ? s[tid - off] : 0;
        __syncthreads();
        s[tid] += v;
        __syncthreads();
    }
    int prev = (tid == 0) ? 0 : s[tid - 1];
#pragma unroll
    for (int i = 0; i < PER; i++) {
        int idx = base + i;
        if (idx < N_NODES) {
            int r = prev + vals[i];
            rowptr[idx] = r;
            fill[idx] = r;
        }
    }
    if (tid == 1023) rowptr[N_NODES] = s[1023];
}

__global__ void scatterT_kernel(const int* __restrict__ graph) {
    int i = blockIdx.x * blockDim.x + threadIdx.x;
    if (i >= T_STEPS * ETOT) return;
    int t = i / ETOT, e = i - t * ETOT;
    int sidx, d;
    if (e < E_EDGES) {
        sidx = graph[(size_t)t * 2 * E_EDGES + e];
        d    = graph[(size_t)t * 2 * E_EDGES + E_EDGES + e];
    } else {
        sidx = d = e - E_EDGES;
    }
    int pos = atomicAdd(&g_fillT[t * N_NODES + d], 1);
    g_colT[(size_t)t * ETOT + pos] = sidx;
}

// ---------------- 4) GAT aggregation + fused z@W1 (batched over t) ----------------
__global__ __launch_bounds__(256) void aggregate_kernel(const float* __restrict__ b_gat,
                                                        const float* __restrict__ W1,
                                                        const float* __restrict__ b1) {
    __shared__ __align__(16) float acc_sm[2][H_HEADS][C_CH];
    __shared__ __align__(16) float z_sm[2][C_CH];
    int warp = threadIdx.x >> 5;
    int lane = threadIdx.x & 31;
    int nodeLocal = warp >> 2;
    int head = warp & 3;
    int t = blockIdx.y;
    int n = blockIdx.x * 2 + nodeLocal;

    const int* rowptr = g_rowptrT + t * (N_NODES + 1);
    const int* col = g_colT + (size_t)t * ETOT;
    const float* asrc = g_asrcT + (size_t)t * N_NODES * H_HEADS;
    const float* h = g_hT + (size_t)t * N_NODES * HC;
    float* w_arr = g_wT + (size_t)t * ETOT * H_HEADS;

    int beg = rowptr[n];
    int end = rowptr[n + 1];
    float ad = g_adstT[((size_t)t * N_NODES + n) * H_HEADS + head];

    float sum = 0.f;
    for (int k = beg + lane; k < end; k += 32) {
        int s = col[k];
        float w = __expf(leaky(asrc[s * H_HEADS + head] + ad));
        w_arr[(size_t)k * H_HEADS + head] = w;
        sum += w;
    }
#pragma unroll
    for (int o = 16; o; o >>= 1) sum += __shfl_xor_sync(0xffffffffu, sum, o);
    float inv = 1.f / (sum + 1e-16f);
    __threadfence_block();
    __syncwarp();

    float4 acc = make_float4(0.f, 0.f, 0.f, 0.f);
    int k = beg;
    for (; k + 4 <= end; k += 4) {
        int s0 = col[k], s1 = col[k + 1], s2 = col[k + 2], s3 = col[k + 3];
        float a0 = w_arr[(size_t)k * H_HEADS + head] * inv;
        float a1 = w_arr[(size_t)(k + 1) * H_HEADS + head] * inv;
        float a2 = w_arr[(size_t)(k + 2) * H_HEADS + head] * inv;
        float a3 = w_arr[(size_t)(k + 3) * H_HEADS + head] * inv;
        const float4 v0 = ((const float4*)(h + (size_t)s0 * HC + head * C_CH))[lane];
        const float4 v1 = ((const float4*)(h + (size_t)s1 * HC + head * C_CH))[lane];
        const float4 v2 = ((const float4*)(h + (size_t)s2 * HC + head * C_CH))[lane];
        const float4 v3 = ((const float4*)(h + (size_t)s3 * HC + head * C_CH))[lane];
        acc.x = fmaf(a0, v0.x, fmaf(a1, v1.x, fmaf(a2, v2.x, fmaf(a3, v3.x, acc.x))));
        acc.y = fmaf(a0, v0.y, fmaf(a1, v1.y, fmaf(a2, v2.y, fmaf(a3, v3.y, acc.y))));
        acc.z = fmaf(a0, v0.z, fmaf(a1, v1.z, fmaf(a2, v2.z, fmaf(a3, v3.z, acc.z))));
        acc.w = fmaf(a0, v0.w, fmaf(a1, v1.w, fmaf(a2, v2.w, fmaf(a3, v3.w, acc.w))));
    }
    for (; k < end; k++) {
        int s0 = col[k];
        float a0 = w_arr[(size_t)k * H_HEADS + head] * inv;
        const float4 v0 = ((const float4*)(h + (size_t)s0 * HC + head * C_CH))[lane];
        acc.x = fmaf(a0, v0.x, acc.x);
        acc.y = fmaf(a0, v0.y, acc.y);
        acc.z = fmaf(a0, v0.z, acc.z);
        acc.w = fmaf(a0, v0.w, acc.w);
    }
    ((float4*)&acc_sm[nodeLocal][head][lane * 4])[0] = acc;
    __syncthreads();

    // head mean + bias + leaky -> z (in smem)
    {
        int idx = threadIdx.x;
        int nl = idx >> 7;
        int c  = idx & 127;
        float v = 0.25f * (acc_sm[nl][0][c] + acc_sm[nl][1][c] + acc_sm[nl][2][c] + acc_sm[nl][3][c])
                  + b_gat[c];
        z_sm[nl][c] = leaky(v);
    }
    __syncthreads();

    // fused: LP = leaky(z @ W1 + b1)
    {
        int j  = threadIdx.x & 127;
        int nl = threadIdx.x >> 7;
        int node = blockIdx.x * 2 + nl;
        float a = b1[j];
        const float* z = z_sm[nl];
#pragma unroll 8
        for (int kk = 0; kk < 128; kk++)
            a = fmaf(z[kk], __ldg(&W1[kk * 128 + j]), a);
        g_LP[((size_t)t * N_NODES + node) * C_CH + j] = leaky(a);
    }
}

// ---------------- 6) final ----------------
__global__ __launch_bounds__(256) void final_kernel(const float* __restrict__ W2,
                                                    const float* __restrict__ b2,
                                                    float* __restrict__ out) {
    int gw = (blockIdx.x * blockDim.x + threadIdx.x) >> 5;
    int lane = threadIdx.x & 31;
    if (gw >= N_NODES) return;
    const float* row = g_LP + (size_t)gw * (T_STEPS * C_CH);
    float a0 = 0.f, a1 = 0.f;
    for (int i = lane; i < T_STEPS * C_CH; i += 32) {
        float v = row[i];
        a0 = fmaf(v, __ldg(&W2[i * 2 + 0]), a0);
        a1 = fmaf(v, __ldg(&W2[i * 2 + 1]), a1);
    }
#pragma unroll
    for (int o = 16; o; o >>= 1) {
        a0 += __shfl_xor_sync(0xffffffffu, a0, o);
        a1 += __shfl_xor_sync(0xffffffffu, a1, o);
    }
    if (lane == 0) {
        float f0 = a0 + b2[0];
        float f1 = a1 + b2[1];
        float m = fmaxf(f0, f1);
        float lse = m + logf(expf(f0 - m) + expf(f1 - m));
        out[gw * 2 + 0] = f0 - lse;
        out[gw * 2 + 1] = f1 - lse;
    }
}

// ---------------- launch ----------------
extern "C" void kernel_launch(void* const* d_in, const int* in_sizes, int n_in,
                              void* d_out, int out_size) {
    int base = 2;
    if (n_in >= 11 && in_sizes[2] <= 1) base = 3;

    const float* fts     = (const float*)d_in[0];
    const int*   graph   = (const int*)d_in[1];
    const float* W_gat   = (const float*)d_in[base + 0];
    const float* att_src = (const float*)d_in[base + 1];
    const float* att_dst = (const float*)d_in[base + 2];
    const float* b_gat   = (const float*)d_in[base + 3];
    const float* W1      = (const float*)d_in[base + 4];
    const float* b1      = (const float*)d_in[base + 5];
    const float* W2      = (const float*)d_in[base + 6];
    const float* b2      = (const float*)d_in[base + 7];
    float* out = (float*)d_out;

    cudaFuncSetAttribute(gemm_mma, cudaFuncAttributeMaxDynamicSharedMemorySize, GEMM_SMEM_TOT);

    const int convGrid = (int)(((size_t)T_STEPS * N_NODES * 128 + 255) / 256);

    // gemm_mma kept as the 4th launch for the ncu window
    conv_B<<<(512 * 512 + 255) / 256, 256>>>(W_gat);
    conv_A<<<convGrid, 256>>>(fts);
    zero_degT<<<(T_STEPS * N_NODES + 255) / 256, 256>>>();
    gemm_mma<<<dim3(NT_TILES, MT_TILES, T_STEPS), 256, GEMM_SMEM_TOT>>>(att_src, att_dst);
    degT_kernel<<<(T_STEPS * ETOT + 255) / 256, 256>>>(graph);
    scanT_kernel<<<T_STEPS, 1024>>>();
    scatterT_kernel<<<(T_STEPS * ETOT + 255) / 256, 256>>>(graph);
    aggregate_kernel<<<dim3(N_NODES / 2, T_STEPS), 256>>>(b_gat, W1, b1);
    final_kernel<<<(N_NODES * 32 + 255) / 256, 256>>>(W2, b2, out);
}

// round 11
// speedup vs baseline: 2.8036x; 1.0534x over previous
#include <cuda_runtime.h>
#include <cuda_bf16.h>
#include <math.h>
#include <stdint.h>

#define N_NODES 20000
#define T_STEPS 8
#define E_EDGES 320000
#define ETOT    (E_EDGES + N_NODES)
#define NFEAT   512
#define HC      512
#define H_HEADS 4
#define C_CH    128
#define SLOPEV  0.2f

#define MT_TILES 157
#define NT_TILES 4
#define BK 32

// ---------------- scratch (batched across T) ----------------
__device__ uint32_t g_h16T[(size_t)T_STEPS * N_NODES * 256];    // bf16x2 h, 164 MB
__device__ float g_asrcT[T_STEPS * N_NODES * H_HEADS];
__device__ float g_adstT[T_STEPS * N_NODES * H_HEADS];
__device__ float g_LP[(size_t)T_STEPS * N_NODES * C_CH];        // 82 MB
__device__ uint16_t g_B16h[512 * 512];   // [n][k]
__device__ uint16_t g_B16l[512 * 512];
__device__ uint16_t g_A16h[(size_t)T_STEPS * N_NODES * 512];    // 164 MB
__device__ float g_wT[(size_t)T_STEPS * ETOT * H_HEADS];        // 42 MB
// batched CSR
__device__ int g_degT[T_STEPS * N_NODES];
__device__ int g_rowptrT[T_STEPS * (N_NODES + 1)];
__device__ int g_fillT[T_STEPS * N_NODES];
__device__ int g_colT[(size_t)T_STEPS * ETOT];

__device__ __forceinline__ float leaky(float x) { return x >= 0.f ? x : SLOPEV * x; }

__device__ __forceinline__ uint32_t smem_u32(const void* p) {
    uint32_t a;
    asm("{ .reg .u64 t; cvta.to.shared.u64 t, %1; cvt.u32.u64 %0, t; }" : "=r"(a) : "l"(p));
    return a;
}
__device__ __forceinline__ void ldsm_x4(uint32_t& r0, uint32_t& r1, uint32_t& r2, uint32_t& r3,
                                        uint32_t addr) {
    asm volatile("ldmatrix.sync.aligned.m8n8.x4.shared.b16 {%0,%1,%2,%3}, [%4];"
                 : "=r"(r0), "=r"(r1), "=r"(r2), "=r"(r3) : "r"(addr));
}
__device__ __forceinline__ void mma16816(float* c, const uint32_t* a, const uint32_t* b) {
    asm volatile(
        "mma.sync.aligned.m16n8k16.row.col.f32.bf16.bf16.f32 "
        "{%0,%1,%2,%3}, {%4,%5,%6,%7}, {%8,%9}, {%0,%1,%2,%3};"
        : "+f"(c[0]), "+f"(c[1]), "+f"(c[2]), "+f"(c[3])
        : "r"(a[0]), "r"(a[1]), "r"(a[2]), "r"(a[3]), "r"(b[0]), "r"(b[1]));
}
__device__ __forceinline__ uint32_t pack_hi2(float v0, float v1) {
    __nv_bfloat162 p = __floats2bfloat162_rn(v0, v1);
    return *reinterpret_cast<uint32_t*>(&p);
}
__device__ __forceinline__ void cp16(uint32_t dst, const void* src) {
    asm volatile("cp.async.cg.shared.global [%0], [%1], 16;" :: "r"(dst), "l"(src));
}
#define CP_COMMIT() asm volatile("cp.async.commit_group;" ::: "memory")
#define CP_WAIT0()  asm volatile("cp.async.wait_group 0;" ::: "memory")

// ---------------- 0a) convert W -> bf16 hi/lo, [n][k] ----------------
__global__ void conv_B(const float* __restrict__ W) {
    int i = blockIdx.x * blockDim.x + threadIdx.x;
    if (i >= 512 * 512) return;
    int k = i >> 9, n = i & 511;
    float v = W[(size_t)k * 512 + n];
    __nv_bfloat16 h = __float2bfloat16(v);
    __nv_bfloat16 l = __float2bfloat16(v - __bfloat162float(h));
    g_B16h[(size_t)n * 512 + k] = *reinterpret_cast<uint16_t*>(&h);
    g_B16l[(size_t)n * 512 + k] = *reinterpret_cast<uint16_t*>(&l);
}

// ---------------- 0b) convert ALL fts -> bf16 (hi only) ----------------
__global__ __launch_bounds__(256) void conv_A(const float* __restrict__ A) {
    size_t i = (size_t)blockIdx.x * blockDim.x + threadIdx.x;
    if (i >= (size_t)T_STEPS * N_NODES * 128) return;
    float4 v = ((const float4*)A)[i];
    uint2 hi = make_uint2(pack_hi2(v.x, v.y), pack_hi2(v.z, v.w));
    ((uint2*)g_A16h)[i] = hi;
}

// ---------------- 1) GEMM batched over t, fused att epilogue, bf16 h output ----------------
#define BF_PITCH  40
#define STG       (128 * BF_PITCH * 2)
#define OFF_A     0
#define OFF_BH    (2 * STG)
#define OFF_BL    (4 * STG)
#define GEMM_SMEM_TOT (6 * STG)

__device__ __forceinline__ void load_stage(uint32_t sb, int tid, size_t aBase, int mt, int nt,
                                           int buf, int k0) {
#pragma unroll
    for (int c = 0; c < 2; c++) {
        int idx = tid + c * 256;
        int row = idx >> 2, ch = idx & 3;
        int node = mt * 128 + row;
        if (node > N_NODES - 1) node = N_NODES - 1;
        uint32_t doff = buf * STG + row * (BF_PITCH * 2) + ch * 16;
        const uint16_t* sa = g_A16h + aBase + (size_t)node * 512 + k0 + ch * 8;
        cp16(sb + OFF_A + doff, sa);
        const uint16_t* sbh = g_B16h + (size_t)(nt * 128 + row) * 512 + k0 + ch * 8;
        const uint16_t* sbl = g_B16l + (size_t)(nt * 128 + row) * 512 + k0 + ch * 8;
        cp16(sb + OFF_BH + doff, sbh);
        cp16(sb + OFF_BL + doff, sbl);
    }
}

__global__ __launch_bounds__(256, 2) void gemm_mma(const float* __restrict__ att_src,
                                                   const float* __restrict__ att_dst) {
    extern __shared__ __align__(16) unsigned char sm[];
    uint32_t sb = smem_u32(sm);
    const int tid = threadIdx.x, warp = tid >> 5, lane = tid & 31;
    const int mt = blockIdx.y, nt = blockIdx.x, t = blockIdx.z;
    const int warpM = warp & 1, warpN = warp >> 1;
    const size_t aBase = (size_t)t * N_NODES * 512;

    float acc[4][4][4];
#pragma unroll
    for (int i = 0; i < 4; i++)
#pragma unroll
        for (int j = 0; j < 4; j++)
#pragma unroll
            for (int q = 0; q < 4; q++) acc[i][j][q] = 0.f;

    const uint32_t aB = sb + OFF_A;
    const uint32_t bhB = sb + OFF_BH, blB = sb + OFF_BL;
    const int aLdRow = warpM * 64 + (lane & 7) + ((lane >> 3) & 1) * 8;
    const int aLdK   = (lane >> 4) * 8;
    const int bLdRow = warpN * 32 + (lane & 7) + ((lane >> 4) & 1) * 8;
    const int bLdK   = ((lane >> 3) & 1) * 8;

    load_stage(sb, tid, aBase, mt, nt, 0, 0);
    CP_COMMIT();

    for (int it = 0; it < 16; it++) {
        const int cur = it & 1;
        CP_WAIT0();
        __syncthreads();
        if (it + 1 < 16) {
            load_stage(sb, tid, aBase, mt, nt, cur ^ 1, (it + 1) * BK);
            CP_COMMIT();
        }

#pragma unroll
        for (int kk = 0; kk < 32; kk += 16) {
            uint32_t bh[2][4], bl[2][4];
#pragma unroll
            for (int nfp = 0; nfp < 2; nfp++) {
                uint32_t off = (uint32_t)(cur * STG + (bLdRow + nfp * 16) * (BF_PITCH * 2)
                                          + (kk + bLdK) * 2);
                ldsm_x4(bh[nfp][0], bh[nfp][1], bh[nfp][2], bh[nfp][3], bhB + off);
                ldsm_x4(bl[nfp][0], bl[nfp][1], bl[nfp][2], bl[nfp][3], blB + off);
            }
#pragma unroll
            for (int mf = 0; mf < 4; mf++) {
                uint32_t off = (uint32_t)(cur * STG + (aLdRow + mf * 16) * (BF_PITCH * 2)
                                          + (kk + aLdK) * 2);
                uint32_t ah[4];
                ldsm_x4(ah[0], ah[1], ah[2], ah[3], aB + off);
#pragma unroll
                for (int nf = 0; nf < 4; nf++) {
                    const uint32_t* bfrag_h = &bh[nf >> 1][(nf & 1) * 2];
                    const uint32_t* bfrag_l = &bl[nf >> 1][(nf & 1) * 2];
                    mma16816(acc[mf][nf], ah, bfrag_h);
                    mma16816(acc[mf][nf], ah, bfrag_l);
                }
            }
        }
        __syncthreads();
    }

    // ---- write h in bf16x2 (aggregation is the only consumer) ----
    uint32_t* hOut = g_h16T + (size_t)t * N_NODES * 256;
    const int r0 = lane >> 2, c0 = (lane & 3) * 2;
#pragma unroll
    for (int mf = 0; mf < 4; mf++) {
#pragma unroll
        for (int nf = 0; nf < 4; nf++) {
            int row = mt * 128 + warpM * 64 + mf * 16 + r0;
            int col = nt * 128 + warpN * 32 + nf * 8 + c0;   // even
            if (row < N_NODES)
                hOut[(size_t)row * 256 + (col >> 1)] = pack_hi2(acc[mf][nf][0], acc[mf][nf][1]);
            if (row + 8 < N_NODES)
                hOut[(size_t)(row + 8) * 256 + (col >> 1)] = pack_hi2(acc[mf][nf][2], acc[mf][nf][3]);
        }
    }

    // ---- fused attention coefficients: column tile nt == head nt (fp32 accs) ----
    float asv[4][2], adv[4][2];
#pragma unroll
    for (int nf = 0; nf < 4; nf++) {
#pragma unroll
        for (int e = 0; e < 2; e++) {
            int cidx = nt * 128 + warpN * 32 + nf * 8 + c0 + e;
            asv[nf][e] = __ldg(&att_src[cidx]);
            adv[nf][e] = __ldg(&att_dst[cidx]);
        }
    }
    float* attS = (float*)sm;            // [128][4]
    float* attD = (float*)sm + 512;      // [128][4]
#pragma unroll
    for (int mf = 0; mf < 4; mf++) {
#pragma unroll
        for (int half = 0; half < 2; half++) {
            float s = 0.f, d = 0.f;
#pragma unroll
            for (int nf = 0; nf < 4; nf++) {
                s = fmaf(acc[mf][nf][half * 2 + 0], asv[nf][0], s);
                s = fmaf(acc[mf][nf][half * 2 + 1], asv[nf][1], s);
                d = fmaf(acc[mf][nf][half * 2 + 0], adv[nf][0], d);
                d = fmaf(acc[mf][nf][half * 2 + 1], adv[nf][1], d);
            }
            s += __shfl_xor_sync(0xffffffffu, s, 1);
            s += __shfl_xor_sync(0xffffffffu, s, 2);
            d += __shfl_xor_sync(0xffffffffu, d, 1);
            d += __shfl_xor_sync(0xffffffffu, d, 2);
            if ((lane & 3) == 0) {
                int rowL = warpM * 64 + mf * 16 + half * 8 + r0;
                attS[rowL * 4 + warpN] = s;
                attD[rowL * 4 + warpN] = d;
            }
        }
    }
    __syncthreads();
    {
        int rowL = tid >> 1, which = tid & 1;
        int node = mt * 128 + rowL;
        if (node < N_NODES) {
            const float* base = which ? attD : attS;
            float v = base[rowL * 4 + 0] + base[rowL * 4 + 1] + base[rowL * 4 + 2] + base[rowL * 4 + 3];
            float* dst = which ? g_adstT : g_asrcT;
            dst[((size_t)t * N_NODES + node) * H_HEADS + nt] = v;
        }
    }
}

// ---------------- 3) batched CSR build ----------------
__global__ void zero_degT() {
    int i = blockIdx.x * blockDim.x + threadIdx.x;
    if (i < T_STEPS * N_NODES) g_degT[i] = 0;
}

__global__ void degT_kernel(const int* __restrict__ graph) {
    int i = blockIdx.x * blockDim.x + threadIdx.x;
    if (i >= T_STEPS * ETOT) return;
    int t = i / ETOT, e = i - t * ETOT;
    int d = (e < E_EDGES) ? graph[(size_t)t * 2 * E_EDGES + E_EDGES + e] : (e - E_EDGES);
    atomicAdd(&g_degT[t * N_NODES + d], 1);
}

__global__ __launch_bounds__(1024) void scanT_kernel() {
    __shared__ int s[1024];
    int t = blockIdx.x;
    const int* deg = g_degT + t * N_NODES;
    int* rowptr = g_rowptrT + t * (N_NODES + 1);
    int* fill = g_fillT + t * N_NODES;
    int tid = threadIdx.x;
    const int PER = 20;
    int base = tid * PER;
    int vals[PER];
    int run = 0;
#pragma unroll
    for (int i = 0; i < PER; i++) {
        int idx = base + i;
        int v = (idx < N_NODES) ? deg[idx] : 0;
        vals[i] = run;
        run += v;
    }
    s[tid] = run;
    __syncthreads();
    for (int off = 1; off < 1024; off <<= 1) {
        int v = (tid >= off) ? s[tid - off] : 0;
        __syncthreads();
        s[tid] += v;
        __syncthreads();
    }
    int prev = (tid == 0) ? 0 : s[tid - 1];
#pragma unroll
    for (int i = 0; i < PER; i++) {
        int idx = base + i;
        if (idx < N_NODES) {
            int r = prev + vals[i];
            rowptr[idx] = r;
            fill[idx] = r;
        }
    }
    if (tid == 1023) rowptr[N_NODES] = s[1023];
}

__global__ void scatterT_kernel(const int* __restrict__ graph) {
    int i = blockIdx.x * blockDim.x + threadIdx.x;
    if (i >= T_STEPS * ETOT) return;
    int t = i / ETOT, e = i - t * ETOT;
    int sidx, d;
    if (e < E_EDGES) {
        sidx = graph[(size_t)t * 2 * E_EDGES + e];
        d    = graph[(size_t)t * 2 * E_EDGES + E_EDGES + e];
    } else {
        sidx = d = e - E_EDGES;
    }
    int pos = atomicAdd(&g_fillT[t * N_NODES + d], 1);
    g_colT[(size_t)t * ETOT + pos] = sidx;
}

// ---------------- 4) GAT aggregation (bf16 gather) + fused z@W1 ----------------
__global__ __launch_bounds__(256) void aggregate_kernel(const float* __restrict__ b_gat,
                                                        const float* __restrict__ W1,
                                                        const float* __restrict__ b1) {
    __shared__ __align__(16) float acc_sm[2][H_HEADS][C_CH];
    __shared__ __align__(16) float z_sm[2][C_CH];
    int warp = threadIdx.x >> 5;
    int lane = threadIdx.x & 31;
    int nodeLocal = warp >> 2;
    int head = warp & 3;
    int t = blockIdx.y;
    int n = blockIdx.x * 2 + nodeLocal;

    const int* rowptr = g_rowptrT + t * (N_NODES + 1);
    const int* col = g_colT + (size_t)t * ETOT;
    const float* asrc = g_asrcT + (size_t)t * N_NODES * H_HEADS;
    const uint32_t* h16 = g_h16T + (size_t)t * N_NODES * 256;
    float* w_arr = g_wT + (size_t)t * ETOT * H_HEADS;

    int beg = rowptr[n];
    int end = rowptr[n + 1];
    float ad = g_adstT[((size_t)t * N_NODES + n) * H_HEADS + head];

    float sum = 0.f;
    for (int k = beg + lane; k < end; k += 32) {
        int s = col[k];
        float w = __expf(leaky(asrc[s * H_HEADS + head] + ad));
        w_arr[(size_t)k * H_HEADS + head] = w;
        sum += w;
    }
#pragma unroll
    for (int o = 16; o; o >>= 1) sum += __shfl_xor_sync(0xffffffffu, sum, o);
    float inv = 1.f / (sum + 1e-16f);
    __threadfence_block();
    __syncwarp();

    // gather: each lane covers 4 channels = uint2 of bf16x2
    const int hOff = head * 64 + lane * 2;   // uint32 offset within node row
    float4 acc = make_float4(0.f, 0.f, 0.f, 0.f);
    int k = beg;
    for (; k + 4 <= end; k += 4) {
        int s0 = col[k], s1 = col[k + 1], s2 = col[k + 2], s3 = col[k + 3];
        float a0 = w_arr[(size_t)k * H_HEADS + head] * inv;
        float a1 = w_arr[(size_t)(k + 1) * H_HEADS + head] * inv;
        float a2 = w_arr[(size_t)(k + 2) * H_HEADS + head] * inv;
        float a3 = w_arr[(size_t)(k + 3) * H_HEADS + head] * inv;
        uint2 u0 = *(const uint2*)(h16 + (size_t)s0 * 256 + hOff);
        uint2 u1 = *(const uint2*)(h16 + (size_t)s1 * 256 + hOff);
        uint2 u2 = *(const uint2*)(h16 + (size_t)s2 * 256 + hOff);
        uint2 u3 = *(const uint2*)(h16 + (size_t)s3 * 256 + hOff);
        float2 l0 = __bfloat1622float2(*(__nv_bfloat162*)&u0.x);
        float2 h0 = __bfloat1622float2(*(__nv_bfloat162*)&u0.y);
        float2 l1 = __bfloat1622float2(*(__nv_bfloat162*)&u1.x);
        float2 h1 = __bfloat1622float2(*(__nv_bfloat162*)&u1.y);
        float2 l2 = __bfloat1622float2(*(__nv_bfloat162*)&u2.x);
        float2 h2 = __bfloat1622float2(*(__nv_bfloat162*)&u2.y);
        float2 l3 = __bfloat1622float2(*(__nv_bfloat162*)&u3.x);
        float2 h3 = __bfloat1622float2(*(__nv_bfloat162*)&u3.y);
        acc.x = fmaf(a0, l0.x, fmaf(a1, l1.x, fmaf(a2, l2.x, fmaf(a3, l3.x, acc.x))));
        acc.y = fmaf(a0, l0.y, fmaf(a1, l1.y, fmaf(a2, l2.y, fmaf(a3, l3.y, acc.y))));
        acc.z = fmaf(a0, h0.x, fmaf(a1, h1.x, fmaf(a2, h2.x, fmaf(a3, h3.x, acc.z))));
        acc.w = fmaf(a0, h0.y, fmaf(a1, h1.y, fmaf(a2, h2.y, fmaf(a3, h3.y, acc.w))));
    }
    for (; k < end; k++) {
        int s0 = col[k];
        float a0 = w_arr[(size_t)k * H_HEADS + head] * inv;
        uint2 u0 = *(const uint2*)(h16 + (size_t)s0 * 256 + hOff);
        float2 l0 = __bfloat1622float2(*(__nv_bfloat162*)&u0.x);
        float2 h0 = __bfloat1622float2(*(__nv_bfloat162*)&u0.y);
        acc.x = fmaf(a0, l0.x, acc.x);
        acc.y = fmaf(a0, l0.y, acc.y);
        acc.z = fmaf(a0, h0.x, acc.z);
        acc.w = fmaf(a0, h0.y, acc.w);
    }
    ((float4*)&acc_sm[nodeLocal][head][lane * 4])[0] = acc;
    __syncthreads();

    // head mean + bias + leaky -> z (in smem)
    {
        int idx = threadIdx.x;
        int nl = idx >> 7;
        int c  = idx & 127;
        float v = 0.25f * (acc_sm[nl][0][c] + acc_sm[nl][1][c] + acc_sm[nl][2][c] + acc_sm[nl][3][c])
                  + b_gat[c];
        z_sm[nl][c] = leaky(v);
    }
    __syncthreads();

    // fused: LP = leaky(z @ W1 + b1)
    {
        int j  = threadIdx.x & 127;
        int nl = threadIdx.x >> 7;
        int node = blockIdx.x * 2 + nl;
        float a = b1[j];
        const float* z = z_sm[nl];
#pragma unroll 8
        for (int kk = 0; kk < 128; kk++)
            a = fmaf(z[kk], __ldg(&W1[kk * 128 + j]), a);
        g_LP[((size_t)t * N_NODES + node) * C_CH + j] = leaky(a);
    }
}

// ---------------- 6) final ----------------
__global__ __launch_bounds__(256) void final_kernel(const float* __restrict__ W2,
                                                    const float* __restrict__ b2,
                                                    float* __restrict__ out) {
    int gw = (blockIdx.x * blockDim.x + threadIdx.x) >> 5;
    int lane = threadIdx.x & 31;
    if (gw >= N_NODES) return;
    const float* row = g_LP + (size_t)gw * (T_STEPS * C_CH);
    float a0 = 0.f, a1 = 0.f;
    for (int i = lane; i < T_STEPS * C_CH; i += 32) {
        float v = row[i];
        a0 = fmaf(v, __ldg(&W2[i * 2 + 0]), a0);
        a1 = fmaf(v, __ldg(&W2[i * 2 + 1]), a1);
    }
#pragma unroll
    for (int o = 16; o; o >>= 1) {
        a0 += __shfl_xor_sync(0xffffffffu, a0, o);
        a1 += __shfl_xor_sync(0xffffffffu, a1, o);
    }
    if (lane == 0) {
        float f0 = a0 + b2[0];
        float f1 = a1 + b2[1];
        float m = fmaxf(f0, f1);
        float lse = m + logf(expf(f0 - m) + expf(f1 - m));
        out[gw * 2 + 0] = f0 - lse;
        out[gw * 2 + 1] = f1 - lse;
    }
}

// ---------------- launch ----------------
extern "C" void kernel_launch(void* const* d_in, const int* in_sizes, int n_in,
                              void* d_out, int out_size) {
    int base = 2;
    if (n_in >= 11 && in_sizes[2] <= 1) base = 3;

    const float* fts     = (const float*)d_in[0];
    const int*   graph   = (const int*)d_in[1];
    const float* W_gat   = (const float*)d_in[base + 0];
    const float* att_src = (const float*)d_in[base + 1];
    const float* att_dst = (const float*)d_in[base + 2];
    const float* b_gat   = (const float*)d_in[base + 3];
    const float* W1      = (const float*)d_in[base + 4];
    const float* b1      = (const float*)d_in[base + 5];
    const float* W2      = (const float*)d_in[base + 6];
    const float* b2      = (const float*)d_in[base + 7];
    float* out = (float*)d_out;

    cudaFuncSetAttribute(gemm_mma, cudaFuncAttributeMaxDynamicSharedMemorySize, GEMM_SMEM_TOT);

    const int convGrid = (int)(((size_t)T_STEPS * N_NODES * 128 + 255) / 256);

    // gemm_mma kept as the 4th launch for the ncu window
    conv_B<<<(512 * 512 + 255) / 256, 256>>>(W_gat);
    conv_A<<<convGrid, 256>>>(fts);
    zero_degT<<<(T_STEPS * N_NODES + 255) / 256, 256>>>();
    gemm_mma<<<dim3(NT_TILES, MT_TILES, T_STEPS), 256, GEMM_SMEM_TOT>>>(att_src, att_dst);
    degT_kernel<<<(T_STEPS * ETOT + 255) / 256, 256>>>(graph);
    scanT_kernel<<<T_STEPS, 1024>>>();
    scatterT_kernel<<<(T_STEPS * ETOT + 255) / 256, 256>>>(graph);
    aggregate_kernel<<<dim3(N_NODES / 2, T_STEPS), 256>>>(b_gat, W1, b1);
    final_kernel<<<(N_NODES * 32 + 255) / 256, 256>>>(W2, b2, out);
}

// round 12
// speedup vs baseline: 2.8459x; 1.0151x over previous
#include <cuda_runtime.h>
#include <cuda_bf16.h>
#include <math.h>
#include <stdint.h>

#define N_NODES 20000
#define T_STEPS 8
#define E_EDGES 320000
#define ETOT    (E_EDGES + N_NODES)
#define NFEAT   512
#define HC      512
#define H_HEADS 4
#define C_CH    128
#define SLOPEV  0.2f

#define MT_TILES 157
#define NT_TILES 4
#define BK 32

// ---------------- scratch (batched across T) ----------------
__device__ uint32_t g_h16T[(size_t)T_STEPS * N_NODES * 256];    // bf16x2 h, 164 MB
__device__ float g_asrcT[T_STEPS * N_NODES * H_HEADS];
__device__ float g_adstT[T_STEPS * N_NODES * H_HEADS];
__device__ float g_LP[(size_t)T_STEPS * N_NODES * C_CH];        // 82 MB
__device__ uint16_t g_B16h[512 * 512];   // [n][k]
__device__ uint16_t g_B16l[512 * 512];
__device__ uint16_t g_A16h[(size_t)T_STEPS * N_NODES * 512];    // 164 MB
// batched CSR
__device__ int g_degT[T_STEPS * N_NODES];
__device__ int g_rowptrT[T_STEPS * (N_NODES + 1)];
__device__ int g_fillT[T_STEPS * N_NODES];
__device__ int g_colT[(size_t)T_STEPS * ETOT];

__device__ __forceinline__ float leaky(float x) { return x >= 0.f ? x : SLOPEV * x; }

__device__ __forceinline__ uint32_t smem_u32(const void* p) {
    uint32_t a;
    asm("{ .reg .u64 t; cvta.to.shared.u64 t, %1; cvt.u32.u64 %0, t; }" : "=r"(a) : "l"(p));
    return a;
}
__device__ __forceinline__ void ldsm_x4(uint32_t& r0, uint32_t& r1, uint32_t& r2, uint32_t& r3,
                                        uint32_t addr) {
    asm volatile("ldmatrix.sync.aligned.m8n8.x4.shared.b16 {%0,%1,%2,%3}, [%4];"
                 : "=r"(r0), "=r"(r1), "=r"(r2), "=r"(r3) : "r"(addr));
}
__device__ __forceinline__ void mma16816(float* c, const uint32_t* a, const uint32_t* b) {
    asm volatile(
        "mma.sync.aligned.m16n8k16.row.col.f32.bf16.bf16.f32 "
        "{%0,%1,%2,%3}, {%4,%5,%6,%7}, {%8,%9}, {%0,%1,%2,%3};"
        : "+f"(c[0]), "+f"(c[1]), "+f"(c[2]), "+f"(c[3])
        : "r"(a[0]), "r"(a[1]), "r"(a[2]), "r"(a[3]), "r"(b[0]), "r"(b[1]));
}
__device__ __forceinline__ uint32_t pack_hi2(float v0, float v1) {
    __nv_bfloat162 p = __floats2bfloat162_rn(v0, v1);
    return *reinterpret_cast<uint32_t*>(&p);
}
__device__ __forceinline__ void cp16(uint32_t dst, const void* src) {
    asm volatile("cp.async.cg.shared.global [%0], [%1], 16;" :: "r"(dst), "l"(src));
}
#define CP_COMMIT() asm volatile("cp.async.commit_group;" ::: "memory")
#define CP_WAIT0()  asm volatile("cp.async.wait_group 0;" ::: "memory")

// ---------------- 0a) convert W -> bf16 hi/lo, [n][k] ----------------
__global__ void conv_B(const float* __restrict__ W) {
    int i = blockIdx.x * blockDim.x + threadIdx.x;
    if (i >= 512 * 512) return;
    int k = i >> 9, n = i & 511;
    float v = W[(size_t)k * 512 + n];
    __nv_bfloat16 h = __float2bfloat16(v);
    __nv_bfloat16 l = __float2bfloat16(v - __bfloat162float(h));
    g_B16h[(size_t)n * 512 + k] = *reinterpret_cast<uint16_t*>(&h);
    g_B16l[(size_t)n * 512 + k] = *reinterpret_cast<uint16_t*>(&l);
}

// ---------------- 0b) convert ALL fts -> bf16 (hi only) ----------------
__global__ __launch_bounds__(256) void conv_A(const float* __restrict__ A) {
    size_t i = (size_t)blockIdx.x * blockDim.x + threadIdx.x;
    if (i >= (size_t)T_STEPS * N_NODES * 128) return;
    float4 v = ((const float4*)A)[i];
    uint2 hi = make_uint2(pack_hi2(v.x, v.y), pack_hi2(v.z, v.w));
    ((uint2*)g_A16h)[i] = hi;
}

// ---------------- 1) GEMM batched over t, fused att epilogue, bf16 h output ----------------
#define BF_PITCH  40
#define STG       (128 * BF_PITCH * 2)
#define OFF_A     0
#define OFF_BH    (2 * STG)
#define OFF_BL    (4 * STG)
#define GEMM_SMEM_TOT (6 * STG)

__device__ __forceinline__ void load_stage(uint32_t sb, int tid, size_t aBase, int mt, int nt,
                                           int buf, int k0) {
#pragma unroll
    for (int c = 0; c < 2; c++) {
        int idx = tid + c * 256;
        int row = idx >> 2, ch = idx & 3;
        int node = mt * 128 + row;
        if (node > N_NODES - 1) node = N_NODES - 1;
        uint32_t doff = buf * STG + row * (BF_PITCH * 2) + ch * 16;
        const uint16_t* sa = g_A16h + aBase + (size_t)node * 512 + k0 + ch * 8;
        cp16(sb + OFF_A + doff, sa);
        const uint16_t* sbh = g_B16h + (size_t)(nt * 128 + row) * 512 + k0 + ch * 8;
        const uint16_t* sbl = g_B16l + (size_t)(nt * 128 + row) * 512 + k0 + ch * 8;
        cp16(sb + OFF_BH + doff, sbh);
        cp16(sb + OFF_BL + doff, sbl);
    }
}

__global__ __launch_bounds__(256, 2) void gemm_mma(const float* __restrict__ att_src,
                                                   const float* __restrict__ att_dst) {
    extern __shared__ __align__(16) unsigned char sm[];
    uint32_t sb = smem_u32(sm);
    const int tid = threadIdx.x, warp = tid >> 5, lane = tid & 31;
    const int mt = blockIdx.y, nt = blockIdx.x, t = blockIdx.z;
    const int warpM = warp & 1, warpN = warp >> 1;
    const size_t aBase = (size_t)t * N_NODES * 512;

    float acc[4][4][4];
#pragma unroll
    for (int i = 0; i < 4; i++)
#pragma unroll
        for (int j = 0; j < 4; j++)
#pragma unroll
            for (int q = 0; q < 4; q++) acc[i][j][q] = 0.f;

    const uint32_t aB = sb + OFF_A;
    const uint32_t bhB = sb + OFF_BH, blB = sb + OFF_BL;
    const int aLdRow = warpM * 64 + (lane & 7) + ((lane >> 3) & 1) * 8;
    const int aLdK   = (lane >> 4) * 8;
    const int bLdRow = warpN * 32 + (lane & 7) + ((lane >> 4) & 1) * 8;
    const int bLdK   = ((lane >> 3) & 1) * 8;

    load_stage(sb, tid, aBase, mt, nt, 0, 0);
    CP_COMMIT();

    for (int it = 0; it < 16; it++) {
        const int cur = it & 1;
        CP_WAIT0();
        __syncthreads();
        if (it + 1 < 16) {
            load_stage(sb, tid, aBase, mt, nt, cur ^ 1, (it + 1) * BK);
            CP_COMMIT();
        }

#pragma unroll
        for (int kk = 0; kk < 32; kk += 16) {
            uint32_t bh[2][4], bl[2][4];
#pragma unroll
            for (int nfp = 0; nfp < 2; nfp++) {
                uint32_t off = (uint32_t)(cur * STG + (bLdRow + nfp * 16) * (BF_PITCH * 2)
                                          + (kk + bLdK) * 2);
                ldsm_x4(bh[nfp][0], bh[nfp][1], bh[nfp][2], bh[nfp][3], bhB + off);
                ldsm_x4(bl[nfp][0], bl[nfp][1], bl[nfp][2], bl[nfp][3], blB + off);
            }
#pragma unroll
            for (int mf = 0; mf < 4; mf++) {
                uint32_t off = (uint32_t)(cur * STG + (aLdRow + mf * 16) * (BF_PITCH * 2)
                                          + (kk + aLdK) * 2);
                uint32_t ah[4];
                ldsm_x4(ah[0], ah[1], ah[2], ah[3], aB + off);
#pragma unroll
                for (int nf = 0; nf < 4; nf++) {
                    const uint32_t* bfrag_h = &bh[nf >> 1][(nf & 1) * 2];
                    const uint32_t* bfrag_l = &bl[nf >> 1][(nf & 1) * 2];
                    mma16816(acc[mf][nf], ah, bfrag_h);
                    mma16816(acc[mf][nf], ah, bfrag_l);
                }
            }
        }
        __syncthreads();
    }

    // ---- write h in bf16x2 ----
    uint32_t* hOut = g_h16T + (size_t)t * N_NODES * 256;
    const int r0 = lane >> 2, c0 = (lane & 3) * 2;
#pragma unroll
    for (int mf = 0; mf < 4; mf++) {
#pragma unroll
        for (int nf = 0; nf < 4; nf++) {
            int row = mt * 128 + warpM * 64 + mf * 16 + r0;
            int col = nt * 128 + warpN * 32 + nf * 8 + c0;
            if (row < N_NODES)
                hOut[(size_t)row * 256 + (col >> 1)] = pack_hi2(acc[mf][nf][0], acc[mf][nf][1]);
            if (row + 8 < N_NODES)
                hOut[(size_t)(row + 8) * 256 + (col >> 1)] = pack_hi2(acc[mf][nf][2], acc[mf][nf][3]);
        }
    }

    // ---- fused attention coefficients ----
    float asv[4][2], adv[4][2];
#pragma unroll
    for (int nf = 0; nf < 4; nf++) {
#pragma unroll
        for (int e = 0; e < 2; e++) {
            int cidx = nt * 128 + warpN * 32 + nf * 8 + c0 + e;
            asv[nf][e] = __ldg(&att_src[cidx]);
            adv[nf][e] = __ldg(&att_dst[cidx]);
        }
    }
    float* attS = (float*)sm;            // [128][4]
    float* attD = (float*)sm + 512;      // [128][4]
#pragma unroll
    for (int mf = 0; mf < 4; mf++) {
#pragma unroll
        for (int half = 0; half < 2; half++) {
            float s = 0.f, d = 0.f;
#pragma unroll
            for (int nf = 0; nf < 4; nf++) {
                s = fmaf(acc[mf][nf][half * 2 + 0], asv[nf][0], s);
                s = fmaf(acc[mf][nf][half * 2 + 1], asv[nf][1], s);
                d = fmaf(acc[mf][nf][half * 2 + 0], adv[nf][0], d);
                d = fmaf(acc[mf][nf][half * 2 + 1], adv[nf][1], d);
            }
            s += __shfl_xor_sync(0xffffffffu, s, 1);
            s += __shfl_xor_sync(0xffffffffu, s, 2);
            d += __shfl_xor_sync(0xffffffffu, d, 1);
            d += __shfl_xor_sync(0xffffffffu, d, 2);
            if ((lane & 3) == 0) {
                int rowL = warpM * 64 + mf * 16 + half * 8 + r0;
                attS[rowL * 4 + warpN] = s;
                attD[rowL * 4 + warpN] = d;
            }
        }
    }
    __syncthreads();
    {
        int rowL = tid >> 1, which = tid & 1;
        int node = mt * 128 + rowL;
        if (node < N_NODES) {
            const float* base = which ? attD : attS;
            float v = base[rowL * 4 + 0] + base[rowL * 4 + 1] + base[rowL * 4 + 2] + base[rowL * 4 + 3];
            float* dst = which ? g_adstT : g_asrcT;
            dst[((size_t)t * N_NODES + node) * H_HEADS + nt] = v;
        }
    }
}

// ---------------- 3) batched CSR build ----------------
__global__ void zero_degT() {
    int i = blockIdx.x * blockDim.x + threadIdx.x;
    if (i < T_STEPS * N_NODES) g_degT[i] = 0;
}

__global__ void degT_kernel(const int* __restrict__ graph) {
    int i = blockIdx.x * blockDim.x + threadIdx.x;
    if (i >= T_STEPS * ETOT) return;
    int t = i / ETOT, e = i - t * ETOT;
    int d = (e < E_EDGES) ? graph[(size_t)t * 2 * E_EDGES + E_EDGES + e] : (e - E_EDGES);
    atomicAdd(&g_degT[t * N_NODES + d], 1);
}

__global__ __launch_bounds__(1024) void scanT_kernel() {
    __shared__ int s[1024];
    int t = blockIdx.x;
    const int* deg = g_degT + t * N_NODES;
    int* rowptr = g_rowptrT + t * (N_NODES + 1);
    int* fill = g_fillT + t * N_NODES;
    int tid = threadIdx.x;
    const int PER = 20;
    int base = tid * PER;
    int vals[PER];
    int run = 0;
#pragma unroll
    for (int i = 0; i < PER; i++) {
        int idx = base + i;
        int v = (idx < N_NODES) ? deg[idx] : 0;
        vals[i] = run;
        run += v;
    }
    s[tid] = run;
    __syncthreads();
    for (int off = 1; off < 1024; off <<= 1) {
        int v = (tid >= off) ? s[tid - off] : 0;
        __syncthreads();
        s[tid] += v;
        __syncthreads();
    }
    int prev = (tid == 0) ? 0 : s[tid - 1];
#pragma unroll
    for (int i = 0; i < PER; i++) {
        int idx = base + i;
        if (idx < N_NODES) {
            int r = prev + vals[i];
            rowptr[idx] = r;
            fill[idx] = r;
        }
    }
    if (tid == 1023) rowptr[N_NODES] = s[1023];
}

__global__ void scatterT_kernel(const int* __restrict__ graph) {
    int i = blockIdx.x * blockDim.x + threadIdx.x;
    if (i >= T_STEPS * ETOT) return;
    int t = i / ETOT, e = i - t * ETOT;
    int sidx, d;
    if (e < E_EDGES) {
        sidx = graph[(size_t)t * 2 * E_EDGES + e];
        d    = graph[(size_t)t * 2 * E_EDGES + E_EDGES + e];
    } else {
        sidx = d = e - E_EDGES;
    }
    int pos = atomicAdd(&g_fillT[t * N_NODES + d], 1);
    g_colT[(size_t)t * ETOT + pos] = sidx;
}

// ---------------- 4) single-pass GAT aggregation (bf16 gather) + fused z@W1 ----------------
__global__ __launch_bounds__(256) void aggregate_kernel(const float* __restrict__ b_gat,
                                                        const float* __restrict__ W1,
                                                        const float* __restrict__ b1) {
    __shared__ __align__(16) float acc_sm[2][H_HEADS][C_CH];
    __shared__ __align__(16) float z_sm[2][C_CH];
    int warp = threadIdx.x >> 5;
    int lane = threadIdx.x & 31;
    int nodeLocal = warp >> 2;
    int head = warp & 3;
    int t = blockIdx.y;
    int n = blockIdx.x * 2 + nodeLocal;

    const int* rowptr = g_rowptrT + t * (N_NODES + 1);
    const int* col = g_colT + (size_t)t * ETOT;
    const float* asrc = g_asrcT + (size_t)t * N_NODES * H_HEADS;
    const uint32_t* h16 = g_h16T + (size_t)t * N_NODES * 256;

    int beg = rowptr[n];
    int end = rowptr[n + 1];
    float ad = g_adstT[((size_t)t * N_NODES + n) * H_HEADS + head];

    // single pass: acc = sum w_k * h_k ; sum = sum w_k (identical in all lanes)
    const int hOff = head * 64 + lane * 2;
    float4 acc = make_float4(0.f, 0.f, 0.f, 0.f);
    float sum = 0.f;
    int k = beg;
    for (; k + 4 <= end; k += 4) {
        int s0 = col[k], s1 = col[k + 1], s2 = col[k + 2], s3 = col[k + 3];
        float w0 = __expf(leaky(asrc[s0 * H_HEADS + head] + ad));
        float w1 = __expf(leaky(asrc[s1 * H_HEADS + head] + ad));
        float w2 = __expf(leaky(asrc[s2 * H_HEADS + head] + ad));
        float w3 = __expf(leaky(asrc[s3 * H_HEADS + head] + ad));
        uint2 u0 = *(const uint2*)(h16 + (size_t)s0 * 256 + hOff);
        uint2 u1 = *(const uint2*)(h16 + (size_t)s1 * 256 + hOff);
        uint2 u2 = *(const uint2*)(h16 + (size_t)s2 * 256 + hOff);
        uint2 u3 = *(const uint2*)(h16 + (size_t)s3 * 256 + hOff);
        sum += (w0 + w1) + (w2 + w3);
        float2 l0 = __bfloat1622float2(*(__nv_bfloat162*)&u0.x);
        float2 h0 = __bfloat1622float2(*(__nv_bfloat162*)&u0.y);
        float2 l1 = __bfloat1622float2(*(__nv_bfloat162*)&u1.x);
        float2 h1 = __bfloat1622float2(*(__nv_bfloat162*)&u1.y);
        float2 l2 = __bfloat1622float2(*(__nv_bfloat162*)&u2.x);
        float2 h2 = __bfloat1622float2(*(__nv_bfloat162*)&u2.y);
        float2 l3 = __bfloat1622float2(*(__nv_bfloat162*)&u3.x);
        float2 h3 = __bfloat1622float2(*(__nv_bfloat162*)&u3.y);
        acc.x = fmaf(w0, l0.x, fmaf(w1, l1.x, fmaf(w2, l2.x, fmaf(w3, l3.x, acc.x))));
        acc.y = fmaf(w0, l0.y, fmaf(w1, l1.y, fmaf(w2, l2.y, fmaf(w3, l3.y, acc.y))));
        acc.z = fmaf(w0, h0.x, fmaf(w1, h1.x, fmaf(w2, h2.x, fmaf(w3, h3.x, acc.z))));
        acc.w = fmaf(w0, h0.y, fmaf(w1, h1.y, fmaf(w2, h2.y, fmaf(w3, h3.y, acc.w))));
    }
    for (; k < end; k++) {
        int s0 = col[k];
        float w0 = __expf(leaky(asrc[s0 * H_HEADS + head] + ad));
        uint2 u0 = *(const uint2*)(h16 + (size_t)s0 * 256 + hOff);
        float2 l0 = __bfloat1622float2(*(__nv_bfloat162*)&u0.x);
        float2 h0 = __bfloat1622float2(*(__nv_bfloat162*)&u0.y);
        sum += w0;
        acc.x = fmaf(w0, l0.x, acc.x);
        acc.y = fmaf(w0, l0.y, acc.y);
        acc.z = fmaf(w0, h0.x, acc.z);
        acc.w = fmaf(w0, h0.y, acc.w);
    }
    float inv = 1.f / (sum + 1e-16f);
    acc.x *= inv; acc.y *= inv; acc.z *= inv; acc.w *= inv;

    ((float4*)&acc_sm[nodeLocal][head][lane * 4])[0] = acc;
    __syncthreads();

    // head mean + bias + leaky -> z (in smem)
    {
        int idx = threadIdx.x;
        int nl = idx >> 7;
        int c  = idx & 127;
        float v = 0.25f * (acc_sm[nl][0][c] + acc_sm[nl][1][c] + acc_sm[nl][2][c] + acc_sm[nl][3][c])
                  + b_gat[c];
        z_sm[nl][c] = leaky(v);
    }
    __syncthreads();

    // fused: LP = leaky(z @ W1 + b1)
    {
        int j  = threadIdx.x & 127;
        int nl = threadIdx.x >> 7;
        int node = blockIdx.x * 2 + nl;
        float a = b1[j];
        const float* z = z_sm[nl];
#pragma unroll 8
        for (int kk = 0; kk < 128; kk++)
            a = fmaf(z[kk], __ldg(&W1[kk * 128 + j]), a);
        g_LP[((size_t)t * N_NODES + node) * C_CH + j] = leaky(a);
    }
}

// ---------------- 6) final ----------------
__global__ __launch_bounds__(256) void final_kernel(const float* __restrict__ W2,
                                                    const float* __restrict__ b2,
                                                    float* __restrict__ out) {
    int gw = (blockIdx.x * blockDim.x + threadIdx.x) >> 5;
    int lane = threadIdx.x & 31;
    if (gw >= N_NODES) return;
    const float* row = g_LP + (size_t)gw * (T_STEPS * C_CH);
    float a0 = 0.f, a1 = 0.f;
    for (int i = lane; i < T_STEPS * C_CH; i += 32) {
        float v = row[i];
        a0 = fmaf(v, __ldg(&W2[i * 2 + 0]), a0);
        a1 = fmaf(v, __ldg(&W2[i * 2 + 1]), a1);
    }
#pragma unroll
    for (int o = 16; o; o >>= 1) {
        a0 += __shfl_xor_sync(0xffffffffu, a0, o);
        a1 += __shfl_xor_sync(0xffffffffu, a1, o);
    }
    if (lane == 0) {
        float f0 = a0 + b2[0];
        float f1 = a1 + b2[1];
        float m = fmaxf(f0, f1);
        float lse = m + logf(expf(f0 - m) + expf(f1 - m));
        out[gw * 2 + 0] = f0 - lse;
        out[gw * 2 + 1] = f1 - lse;
    }
}

// ---------------- launch ----------------
extern "C" void kernel_launch(void* const* d_in, const int* in_sizes, int n_in,
                              void* d_out, int out_size) {
    int base = 2;
    if (n_in >= 11 && in_sizes[2] <= 1) base = 3;

    const float* fts     = (const float*)d_in[0];
    const int*   graph   = (const int*)d_in[1];
    const float* W_gat   = (const float*)d_in[base + 0];
    const float* att_src = (const float*)d_in[base + 1];
    const float* att_dst = (const float*)d_in[base + 2];
    const float* b_gat   = (const float*)d_in[base + 3];
    const float* W1      = (const float*)d_in[base + 4];
    const float* b1      = (const float*)d_in[base + 5];
    const float* W2      = (const float*)d_in[base + 6];
    const float* b2      = (const float*)d_in[base + 7];
    float* out = (float*)d_out;

    cudaFuncSetAttribute(gemm_mma, cudaFuncAttributeMaxDynamicSharedMemorySize, GEMM_SMEM_TOT);

    const int convGrid = (int)(((size_t)T_STEPS * N_NODES * 128 + 255) / 256);

    // gemm_mma kept as the 4th launch for the ncu window
    conv_B<<<(512 * 512 + 255) / 256, 256>>>(W_gat);
    conv_A<<<convGrid, 256>>>(fts);
    zero_degT<<<(T_STEPS * N_NODES + 255) / 256, 256>>>();
    gemm_mma<<<dim3(NT_TILES, MT_TILES, T_STEPS), 256, GEMM_SMEM_TOT>>>(att_src, att_dst);
    degT_kernel<<<(T_STEPS * ETOT + 255) / 256, 256>>>(graph);
    scanT_kernel<<<T_STEPS, 1024>>>();
    scatterT_kernel<<<(T_STEPS * ETOT + 255) / 256, 256>>>(graph);
    aggregate_kernel<<<dim3(N_NODES / 2, T_STEPS), 256>>>(b_gat, W1, b1);
    final_kernel<<<(N_NODES * 32 + 255) / 256, 256>>>(W2, b2, out);
}

// round 13
// speedup vs baseline: 3.3867x; 1.1900x over previous
#include <cuda_runtime.h>
#include <cuda_bf16.h>
#include <math.h>
#include <stdint.h>

#define N_NODES 20000
#define T_STEPS 8
#define E_EDGES 320000
#define ETOT    (E_EDGES + N_NODES)
#define NFEAT   512
#define HC      512
#define H_HEADS 4
#define C_CH    128
#define SLOPEV  0.2f

#define MT_TILES 157
#define NT_TILES 4
#define BK 32

// ---------------- scratch (batched across T) ----------------
__device__ uint32_t g_h16T[(size_t)T_STEPS * N_NODES * 256];    // bf16x2 h, 164 MB
__device__ float g_asrcT[T_STEPS * N_NODES * H_HEADS];
__device__ float g_adstT[T_STEPS * N_NODES * H_HEADS];
__device__ float g_LP[(size_t)T_STEPS * N_NODES * C_CH];        // 82 MB
__device__ uint16_t g_B16h[512 * 512];   // [n][k]
__device__ uint16_t g_B16l[512 * 512];
__device__ uint16_t g_A16h[(size_t)T_STEPS * N_NODES * 512];    // 164 MB
// batched CSR
__device__ int g_degT[T_STEPS * N_NODES];
__device__ int g_rowptrT[T_STEPS * (N_NODES + 1)];
__device__ int g_fillT[T_STEPS * N_NODES];
__device__ int g_colT[(size_t)T_STEPS * ETOT];

__device__ __forceinline__ float leaky(float x) { return x >= 0.f ? x : SLOPEV * x; }

__device__ __forceinline__ uint32_t smem_u32(const void* p) {
    uint32_t a;
    asm("{ .reg .u64 t; cvta.to.shared.u64 t, %1; cvt.u32.u64 %0, t; }" : "=r"(a) : "l"(p));
    return a;
}
__device__ __forceinline__ void ldsm_x4(uint32_t& r0, uint32_t& r1, uint32_t& r2, uint32_t& r3,
                                        uint32_t addr) {
    asm volatile("ldmatrix.sync.aligned.m8n8.x4.shared.b16 {%0,%1,%2,%3}, [%4];"
                 : "=r"(r0), "=r"(r1), "=r"(r2), "=r"(r3) : "r"(addr));
}
__device__ __forceinline__ void mma16816(float* c, const uint32_t* a, const uint32_t* b) {
    asm volatile(
        "mma.sync.aligned.m16n8k16.row.col.f32.bf16.bf16.f32 "
        "{%0,%1,%2,%3}, {%4,%5,%6,%7}, {%8,%9}, {%0,%1,%2,%3};"
        : "+f"(c[0]), "+f"(c[1]), "+f"(c[2]), "+f"(c[3])
        : "r"(a[0]), "r"(a[1]), "r"(a[2]), "r"(a[3]), "r"(b[0]), "r"(b[1]));
}
__device__ __forceinline__ uint32_t pack_hi2(float v0, float v1) {
    __nv_bfloat162 p = __floats2bfloat162_rn(v0, v1);
    return *reinterpret_cast<uint32_t*>(&p);
}
__device__ __forceinline__ void cp16(uint32_t dst, const void* src) {
    asm volatile("cp.async.cg.shared.global [%0], [%1], 16;" :: "r"(dst), "l"(src));
}
#define CP_COMMIT() asm volatile("cp.async.commit_group;" ::: "memory")
#define CP_WAIT0()  asm volatile("cp.async.wait_group 0;" ::: "memory")

// ---------------- 0a) convert W -> bf16 hi/lo, [n][k] ----------------
__global__ void conv_B(const float* __restrict__ W) {
    int i = blockIdx.x * blockDim.x + threadIdx.x;
    if (i >= 512 * 512) return;
    int k = i >> 9, n = i & 511;
    float v = W[(size_t)k * 512 + n];
    __nv_bfloat16 h = __float2bfloat16(v);
    __nv_bfloat16 l = __float2bfloat16(v - __bfloat162float(h));
    g_B16h[(size_t)n * 512 + k] = *reinterpret_cast<uint16_t*>(&h);
    g_B16l[(size_t)n * 512 + k] = *reinterpret_cast<uint16_t*>(&l);
}

// ---------------- 0b) convert ALL fts -> bf16 (hi only) ----------------
__global__ __launch_bounds__(256) void conv_A(const float* __restrict__ A) {
    size_t i = (size_t)blockIdx.x * blockDim.x + threadIdx.x;
    if (i >= (size_t)T_STEPS * N_NODES * 128) return;
    float4 v = ((const float4*)A)[i];
    uint2 hi = make_uint2(pack_hi2(v.x, v.y), pack_hi2(v.z, v.w));
    ((uint2*)g_A16h)[i] = hi;
}

// ---------------- 1) GEMM batched over t, fused att epilogue, bf16 h output ----------------
#define BF_PITCH  40
#define STG       (128 * BF_PITCH * 2)
#define OFF_A     0
#define OFF_BH    (2 * STG)
#define OFF_BL    (4 * STG)
#define GEMM_SMEM_TOT (6 * STG)

__device__ __forceinline__ void load_stage(uint32_t sb, int tid, size_t aBase, int mt, int nt,
                                           int buf, int k0) {
#pragma unroll
    for (int c = 0; c < 2; c++) {
        int idx = tid + c * 256;
        int row = idx >> 2, ch = idx & 3;
        int node = mt * 128 + row;
        if (node > N_NODES - 1) node = N_NODES - 1;
        uint32_t doff = buf * STG + row * (BF_PITCH * 2) + ch * 16;
        const uint16_t* sa = g_A16h + aBase + (size_t)node * 512 + k0 + ch * 8;
        cp16(sb + OFF_A + doff, sa);
        const uint16_t* sbh = g_B16h + (size_t)(nt * 128 + row) * 512 + k0 + ch * 8;
        const uint16_t* sbl = g_B16l + (size_t)(nt * 128 + row) * 512 + k0 + ch * 8;
        cp16(sb + OFF_BH + doff, sbh);
        cp16(sb + OFF_BL + doff, sbl);
    }
}

__global__ __launch_bounds__(256, 2) void gemm_mma(const float* __restrict__ att_src,
                                                   const float* __restrict__ att_dst) {
    extern __shared__ __align__(16) unsigned char sm[];
    uint32_t sb = smem_u32(sm);
    const int tid = threadIdx.x, warp = tid >> 5, lane = tid & 31;
    const int mt = blockIdx.y, nt = blockIdx.x, t = blockIdx.z;
    const int warpM = warp & 1, warpN = warp >> 1;
    const size_t aBase = (size_t)t * N_NODES * 512;

    float acc[4][4][4];
#pragma unroll
    for (int i = 0; i < 4; i++)
#pragma unroll
        for (int j = 0; j < 4; j++)
#pragma unroll
            for (int q = 0; q < 4; q++) acc[i][j][q] = 0.f;

    const uint32_t aB = sb + OFF_A;
    const uint32_t bhB = sb + OFF_BH, blB = sb + OFF_BL;
    const int aLdRow = warpM * 64 + (lane & 7) + ((lane >> 3) & 1) * 8;
    const int aLdK   = (lane >> 4) * 8;
    const int bLdRow = warpN * 32 + (lane & 7) + ((lane >> 4) & 1) * 8;
    const int bLdK   = ((lane >> 3) & 1) * 8;

    load_stage(sb, tid, aBase, mt, nt, 0, 0);
    CP_COMMIT();

    for (int it = 0; it < 16; it++) {
        const int cur = it & 1;
        CP_WAIT0();
        __syncthreads();
        if (it + 1 < 16) {
            load_stage(sb, tid, aBase, mt, nt, cur ^ 1, (it + 1) * BK);
            CP_COMMIT();
        }

#pragma unroll
        for (int kk = 0; kk < 32; kk += 16) {
            uint32_t bh[2][4], bl[2][4];
#pragma unroll
            for (int nfp = 0; nfp < 2; nfp++) {
                uint32_t off = (uint32_t)(cur * STG + (bLdRow + nfp * 16) * (BF_PITCH * 2)
                                          + (kk + bLdK) * 2);
                ldsm_x4(bh[nfp][0], bh[nfp][1], bh[nfp][2], bh[nfp][3], bhB + off);
                ldsm_x4(bl[nfp][0], bl[nfp][1], bl[nfp][2], bl[nfp][3], blB + off);
            }
#pragma unroll
            for (int mf = 0; mf < 4; mf++) {
                uint32_t off = (uint32_t)(cur * STG + (aLdRow + mf * 16) * (BF_PITCH * 2)
                                          + (kk + aLdK) * 2);
                uint32_t ah[4];
                ldsm_x4(ah[0], ah[1], ah[2], ah[3], aB + off);
#pragma unroll
                for (int nf = 0; nf < 4; nf++) {
                    const uint32_t* bfrag_h = &bh[nf >> 1][(nf & 1) * 2];
                    const uint32_t* bfrag_l = &bl[nf >> 1][(nf & 1) * 2];
                    mma16816(acc[mf][nf], ah, bfrag_h);
                    mma16816(acc[mf][nf], ah, bfrag_l);
                }
            }
        }
        __syncthreads();
    }

    // ---- write h in bf16x2 ----
    uint32_t* hOut = g_h16T + (size_t)t * N_NODES * 256;
    const int r0 = lane >> 2, c0 = (lane & 3) * 2;
#pragma unroll
    for (int mf = 0; mf < 4; mf++) {
#pragma unroll
        for (int nf = 0; nf < 4; nf++) {
            int row = mt * 128 + warpM * 64 + mf * 16 + r0;
            int col = nt * 128 + warpN * 32 + nf * 8 + c0;
            if (row < N_NODES)
                hOut[(size_t)row * 256 + (col >> 1)] = pack_hi2(acc[mf][nf][0], acc[mf][nf][1]);
            if (row + 8 < N_NODES)
                hOut[(size_t)(row + 8) * 256 + (col >> 1)] = pack_hi2(acc[mf][nf][2], acc[mf][nf][3]);
        }
    }

    // ---- fused attention coefficients ----
    float asv[4][2], adv[4][2];
#pragma unroll
    for (int nf = 0; nf < 4; nf++) {
#pragma unroll
        for (int e = 0; e < 2; e++) {
            int cidx = nt * 128 + warpN * 32 + nf * 8 + c0 + e;
            asv[nf][e] = __ldg(&att_src[cidx]);
            adv[nf][e] = __ldg(&att_dst[cidx]);
        }
    }
    float* attS = (float*)sm;            // [128][4]
    float* attD = (float*)sm + 512;      // [128][4]
#pragma unroll
    for (int mf = 0; mf < 4; mf++) {
#pragma unroll
        for (int half = 0; half < 2; half++) {
            float s = 0.f, d = 0.f;
#pragma unroll
            for (int nf = 0; nf < 4; nf++) {
                s = fmaf(acc[mf][nf][half * 2 + 0], asv[nf][0], s);
                s = fmaf(acc[mf][nf][half * 2 + 1], asv[nf][1], s);
                d = fmaf(acc[mf][nf][half * 2 + 0], adv[nf][0], d);
                d = fmaf(acc[mf][nf][half * 2 + 1], adv[nf][1], d);
            }
            s += __shfl_xor_sync(0xffffffffu, s, 1);
            s += __shfl_xor_sync(0xffffffffu, s, 2);
            d += __shfl_xor_sync(0xffffffffu, d, 1);
            d += __shfl_xor_sync(0xffffffffu, d, 2);
            if ((lane & 3) == 0) {
                int rowL = warpM * 64 + mf * 16 + half * 8 + r0;
                attS[rowL * 4 + warpN] = s;
                attD[rowL * 4 + warpN] = d;
            }
        }
    }
    __syncthreads();
    {
        int rowL = tid >> 1, which = tid & 1;
        int node = mt * 128 + rowL;
        if (node < N_NODES) {
            const float* base = which ? attD : attS;
            float v = base[rowL * 4 + 0] + base[rowL * 4 + 1] + base[rowL * 4 + 2] + base[rowL * 4 + 3];
            float* dst = which ? g_adstT : g_asrcT;
            dst[((size_t)t * N_NODES + node) * H_HEADS + nt] = v;
        }
    }
}

// ---------------- 3) batched CSR build ----------------
__global__ void zero_degT() {
    int i = blockIdx.x * blockDim.x + threadIdx.x;
    if (i < T_STEPS * N_NODES) g_degT[i] = 0;
}

__global__ void degT_kernel(const int* __restrict__ graph) {
    int i = blockIdx.x * blockDim.x + threadIdx.x;
    if (i >= T_STEPS * ETOT) return;
    int t = i / ETOT, e = i - t * ETOT;
    int d = (e < E_EDGES) ? graph[(size_t)t * 2 * E_EDGES + E_EDGES + e] : (e - E_EDGES);
    atomicAdd(&g_degT[t * N_NODES + d], 1);
}

__global__ __launch_bounds__(1024) void scanT_kernel() {
    __shared__ int s[1024];
    int t = blockIdx.x;
    const int* deg = g_degT + t * N_NODES;
    int* rowptr = g_rowptrT + t * (N_NODES + 1);
    int* fill = g_fillT + t * N_NODES;
    int tid = threadIdx.x;
    const int PER = 20;
    int base = tid * PER;
    int vals[PER];
    int run = 0;
#pragma unroll
    for (int i = 0; i < PER; i++) {
        int idx = base + i;
        int v = (idx < N_NODES) ? deg[idx] : 0;
        vals[i] = run;
        run += v;
    }
    s[tid] = run;
    __syncthreads();
    for (int off = 1; off < 1024; off <<= 1) {
        int v = (tid >= off) ? s[tid - off] : 0;
        __syncthreads();
        s[tid] += v;
        __syncthreads();
    }
    int prev = (tid == 0) ? 0 : s[tid - 1];
#pragma unroll
    for (int i = 0; i < PER; i++) {
        int idx = base + i;
        if (idx < N_NODES) {
            int r = prev + vals[i];
            rowptr[idx] = r;
            fill[idx] = r;
        }
    }
    if (tid == 1023) rowptr[N_NODES] = s[1023];
}

__global__ void scatterT_kernel(const int* __restrict__ graph) {
    int i = blockIdx.x * blockDim.x + threadIdx.x;
    if (i >= T_STEPS * ETOT) return;
    int t = i / ETOT, e = i - t * ETOT;
    int sidx, d;
    if (e < E_EDGES) {
        sidx = graph[(size_t)t * 2 * E_EDGES + e];
        d    = graph[(size_t)t * 2 * E_EDGES + E_EDGES + e];
    } else {
        sidx = d = e - E_EDGES;
    }
    int pos = atomicAdd(&g_fillT[t * N_NODES + d], 1);
    g_colT[(size_t)t * ETOT + pos] = sidx;
}

// ---------------- 4) aggregation: 8 nodes/block, warp per node (all 4 heads) + fused z@W1 --
__global__ __launch_bounds__(256) void aggregate_kernel(const float* __restrict__ b_gat,
                                                        const float* __restrict__ W1,
                                                        const float* __restrict__ b1) {
    __shared__ __align__(16) float z_sm[8][C_CH];
    int warp = threadIdx.x >> 5;
    int lane = threadIdx.x & 31;
    int t = blockIdx.y;
    int n = blockIdx.x * 8 + warp;

    const int* rowptr = g_rowptrT + t * (N_NODES + 1);
    const int* col = g_colT + (size_t)t * ETOT;
    const float* asrc = g_asrcT + (size_t)t * N_NODES * H_HEADS;
    const uint32_t* h16 = g_h16T + (size_t)t * N_NODES * 256;

    int beg = rowptr[n];
    int end = rowptr[n + 1];
    const float4 ad = *(const float4*)&g_adstT[((size_t)t * N_NODES + n) * H_HEADS];

    // acc[hh] covers channels [lane*4, lane*4+4) of head hh; sum[hh] lane-uniform
    float4 acc0 = make_float4(0.f, 0.f, 0.f, 0.f), acc1 = acc0, acc2 = acc0, acc3 = acc0;
    float s0 = 0.f, s1 = 0.f, s2 = 0.f, s3 = 0.f;
    const int lOff = lane * 2;

    int k = beg;
    for (; k + 2 <= end; k += 2) {
        int sa = col[k], sb2 = col[k + 1];
        const float4 ea = *(const float4*)&asrc[sa * H_HEADS];
        const float4 eb = *(const float4*)&asrc[sb2 * H_HEADS];
        float wa0 = __expf(leaky(ea.x + ad.x)), wa1 = __expf(leaky(ea.y + ad.y));
        float wa2 = __expf(leaky(ea.z + ad.z)), wa3 = __expf(leaky(ea.w + ad.w));
        float wb0 = __expf(leaky(eb.x + ad.x)), wb1 = __expf(leaky(eb.y + ad.y));
        float wb2 = __expf(leaky(eb.z + ad.z)), wb3 = __expf(leaky(eb.w + ad.w));
        const uint32_t* ha = h16 + (size_t)sa * 256 + lOff;
        const uint32_t* hb = h16 + (size_t)sb2 * 256 + lOff;
        uint2 ua0 = *(const uint2*)(ha);
        uint2 ua1 = *(const uint2*)(ha + 64);
        uint2 ua2 = *(const uint2*)(ha + 128);
        uint2 ua3 = *(const uint2*)(ha + 192);
        uint2 ub0 = *(const uint2*)(hb);
        uint2 ub1 = *(const uint2*)(hb + 64);
        uint2 ub2 = *(const uint2*)(hb + 128);
        uint2 ub3 = *(const uint2*)(hb + 192);
        s0 += wa0 + wb0; s1 += wa1 + wb1; s2 += wa2 + wb2; s3 += wa3 + wb3;
#define ACCH(ACC, W_A, W_B, UA, UB)                                              \
        {                                                                        \
            float2 la = __bfloat1622float2(*(__nv_bfloat162*)&UA.x);             \
            float2 ha2 = __bfloat1622float2(*(__nv_bfloat162*)&UA.y);            \
            float2 lb = __bfloat1622float2(*(__nv_bfloat162*)&UB.x);             \
            float2 hb2 = __bfloat1622float2(*(__nv_bfloat162*)&UB.y);            \
            ACC.x = fmaf(W_A, la.x, fmaf(W_B, lb.x, ACC.x));                     \
            ACC.y = fmaf(W_A, la.y, fmaf(W_B, lb.y, ACC.y));                     \
            ACC.z = fmaf(W_A, ha2.x, fmaf(W_B, hb2.x, ACC.z));                   \
            ACC.w = fmaf(W_A, ha2.y, fmaf(W_B, hb2.y, ACC.w));                   \
        }
        ACCH(acc0, wa0, wb0, ua0, ub0)
        ACCH(acc1, wa1, wb1, ua1, ub1)
        ACCH(acc2, wa2, wb2, ua2, ub2)
        ACCH(acc3, wa3, wb3, ua3, ub3)
    }
    if (k < end) {
        int sa = col[k];
        const float4 ea = *(const float4*)&asrc[sa * H_HEADS];
        float wa0 = __expf(leaky(ea.x + ad.x)), wa1 = __expf(leaky(ea.y + ad.y));
        float wa2 = __expf(leaky(ea.z + ad.z)), wa3 = __expf(leaky(ea.w + ad.w));
        const uint32_t* ha = h16 + (size_t)sa * 256 + lOff;
        uint2 ua0 = *(const uint2*)(ha);
        uint2 ua1 = *(const uint2*)(ha + 64);
        uint2 ua2 = *(const uint2*)(ha + 128);
        uint2 ua3 = *(const uint2*)(ha + 192);
        s0 += wa0; s1 += wa1; s2 += wa2; s3 += wa3;
#define ACC1(ACC, W_A, UA)                                                       \
        {                                                                        \
            float2 la = __bfloat1622float2(*(__nv_bfloat162*)&UA.x);             \
            float2 ha2 = __bfloat1622float2(*(__nv_bfloat162*)&UA.y);            \
            ACC.x = fmaf(W_A, la.x, ACC.x);                                      \
            ACC.y = fmaf(W_A, la.y, ACC.y);                                      \
            ACC.z = fmaf(W_A, ha2.x, ACC.z);                                     \
            ACC.w = fmaf(W_A, ha2.y, ACC.w);                                     \
        }
        ACC1(acc0, wa0, ua0)
        ACC1(acc1, wa1, ua1)
        ACC1(acc2, wa2, ua2)
        ACC1(acc3, wa3, ua3)
    }
    float i0 = 1.f / (s0 + 1e-16f), i1 = 1.f / (s1 + 1e-16f);
    float i2 = 1.f / (s2 + 1e-16f), i3 = 1.f / (s3 + 1e-16f);

    // head mean + bias + leaky -> z_sm[warp][lane*4 ..]
    {
        const float4 bg = *(const float4*)&b_gat[lane * 4];
        float4 z;
        z.x = leaky(0.25f * (acc0.x * i0 + acc1.x * i1 + acc2.x * i2 + acc3.x * i3) + bg.x);
        z.y = leaky(0.25f * (acc0.y * i0 + acc1.y * i1 + acc2.y * i2 + acc3.y * i3) + bg.y);
        z.z = leaky(0.25f * (acc0.z * i0 + acc1.z * i1 + acc2.z * i2 + acc3.z * i3) + bg.z);
        z.w = leaky(0.25f * (acc0.w * i0 + acc1.w * i1 + acc2.w * i2 + acc3.w * i3) + bg.w);
        *(float4*)&z_sm[warp][lane * 4] = z;
    }
    __syncthreads();

    // fused: LP = leaky(z @ W1 + b1) for 8 nodes; thread (half, j) handles 4 nodes
    {
        int j    = threadIdx.x & 127;
        int half = threadIdx.x >> 7;
        float a0 = b1[j], a1 = a0, a2 = a0, a3 = a0;
        const float* z0 = z_sm[half * 4 + 0];
        const float* z1 = z_sm[half * 4 + 1];
        const float* z2 = z_sm[half * 4 + 2];
        const float* z3 = z_sm[half * 4 + 3];
#pragma unroll 8
        for (int kk = 0; kk < 128; kk++) {
            float wv = __ldg(&W1[kk * 128 + j]);
            a0 = fmaf(z0[kk], wv, a0);
            a1 = fmaf(z1[kk], wv, a1);
            a2 = fmaf(z2[kk], wv, a2);
            a3 = fmaf(z3[kk], wv, a3);
        }
        size_t outBase = ((size_t)t * N_NODES + blockIdx.x * 8 + half * 4) * C_CH + j;
        g_LP[outBase + 0 * C_CH] = leaky(a0);
        g_LP[outBase + 1 * C_CH] = leaky(a1);
        g_LP[outBase + 2 * C_CH] = leaky(a2);
        g_LP[outBase + 3 * C_CH] = leaky(a3);
    }
}

// ---------------- 6) final ----------------
__global__ __launch_bounds__(256) void final_kernel(const float* __restrict__ W2,
                                                    const float* __restrict__ b2,
                                                    float* __restrict__ out) {
    int gw = (blockIdx.x * blockDim.x + threadIdx.x) >> 5;
    int lane = threadIdx.x & 31;
    if (gw >= N_NODES) return;
    const float* row = g_LP + (size_t)gw * (T_STEPS * C_CH);
    float a0 = 0.f, a1 = 0.f;
    for (int i = lane; i < T_STEPS * C_CH; i += 32) {
        float v = row[i];
        a0 = fmaf(v, __ldg(&W2[i * 2 + 0]), a0);
        a1 = fmaf(v, __ldg(&W2[i * 2 + 1]), a1);
    }
#pragma unroll
    for (int o = 16; o; o >>= 1) {
        a0 += __shfl_xor_sync(0xffffffffu, a0, o);
        a1 += __shfl_xor_sync(0xffffffffu, a1, o);
    }
    if (lane == 0) {
        float f0 = a0 + b2[0];
        float f1 = a1 + b2[1];
        float m = fmaxf(f0, f1);
        float lse = m + logf(expf(f0 - m) + expf(f1 - m));
        out[gw * 2 + 0] = f0 - lse;
        out[gw * 2 + 1] = f1 - lse;
    }
}

// ---------------- launch ----------------
extern "C" void kernel_launch(void* const* d_in, const int* in_sizes, int n_in,
                              void* d_out, int out_size) {
    int base = 2;
    if (n_in >= 11 && in_sizes[2] <= 1) base = 3;

    const float* fts     = (const float*)d_in[0];
    const int*   graph   = (const int*)d_in[1];
    const float* W_gat   = (const float*)d_in[base + 0];
    const float* att_src = (const float*)d_in[base + 1];
    const float* att_dst = (const float*)d_in[base + 2];
    const float* b_gat   = (const float*)d_in[base + 3];
    const float* W1      = (const float*)d_in[base + 4];
    const float* b1      = (const float*)d_in[base + 5];
    const float* W2      = (const float*)d_in[base + 6];
    const float* b2      = (const float*)d_in[base + 7];
    float* out = (float*)d_out;

    cudaFuncSetAttribute(gemm_mma, cudaFuncAttributeMaxDynamicSharedMemorySize, GEMM_SMEM_TOT);

    const int convGrid = (int)(((size_t)T_STEPS * N_NODES * 128 + 255) / 256);

    // gemm_mma kept as the 4th launch for the ncu window
    conv_B<<<(512 * 512 + 255) / 256, 256>>>(W_gat);
    conv_A<<<convGrid, 256>>>(fts);
    zero_degT<<<(T_STEPS * N_NODES + 255) / 256, 256>>>();
    gemm_mma<<<dim3(NT_TILES, MT_TILES, T_STEPS), 256, GEMM_SMEM_TOT>>>(att_src, att_dst);
    degT_kernel<<<(T_STEPS * ETOT + 255) / 256, 256>>>(graph);
    scanT_kernel<<<T_STEPS, 1024>>>();
    scatterT_kernel<<<(T_STEPS * ETOT + 255) / 256, 256>>>(graph);
    aggregate_kernel<<<dim3(N_NODES / 8, T_STEPS), 256>>>(b_gat, W1, b1);
    final_kernel<<<(N_NODES * 32 + 255) / 256, 256>>>(W2, b2, out);
}